// round 13
// baseline (speedup 1.0000x reference)
#include <cuda_runtime.h>
#include <cuda_bf16.h>
#include <math.h>
#include <stdint.h>

// ---------------------------------------------------------------------------
// GriffinBlock: HMMA bf16x3 GEMMs (256x128 CTA, 512 thr) + HMMA flash attn
// B=4, T=2048, DIM=1024, HID=1536, GH=2048, K=4, HD=128, QH=8, W=1024
// ---------------------------------------------------------------------------

#define Bdim 4
#define Tdim 2048
#define DIM 1024
#define HID 1536
#define GH  2048
#define KCONV 4
#define HD  128
#define QH  8
#define WINSZ 1024
#define MROWS (Bdim*Tdim)   // 8192
#define LOG2E 1.4426950408889634f
#define QSCALE 0.088388347648318447f
#define ROT_C (9.210340371976184f / 128.0f)

// ---------------- static scratch ----------------
__device__ float g_big[33554432];      // 8192*4096
__device__ float g_mid[25165824];      // 8192*3072 (hawk gi; act/attn bf16 scratch)
__device__ float g_small[12582912];    // 8192*1536
__device__ __nv_bfloat16 g_Ahi[16777216];  // 8192*2048 max
__device__ __nv_bfloat16 g_Alo[16777216];
__device__ __nv_bfloat16 g_Whi[24379392];  // all weights, bf16 hi
__device__ __nv_bfloat16 g_Wlo[24379392];  // all weights, bf16 lo
__device__ float g_chA[98304];
__device__ float g_chS[98304];
__device__ float g_sIn[98304];

// weight slice offsets in float4 units (x4 for elements)
#define W_WIN  0u
#define W_WG   786432u
#define W_WOUT 1966080u
#define W_G1G  2359296u
#define W_G1S  3407872u
#define W_G2G  3932160u
#define W_G2S  4980736u
#define W_Q    5505024u
#define W_KV   5767168u
#define W_O2   5832704u
#define W_TOT  6094848u

__device__ __forceinline__ float gelu_exact(float x) {
    return 0.5f * x * (1.0f + erff(x * 0.70710678118654752f));
}
__device__ __forceinline__ float sigmoidf_(float x) {
    return 1.0f / (1.0f + expf(-x));
}
__device__ __forceinline__ void split_bf16(float v, __nv_bfloat16& h, __nv_bfloat16& l) {
    h = __float2bfloat16(v);
    l = __float2bfloat16(v - __bfloat162float(h));
}

__device__ __forceinline__ uint32_t smem_u32(const void* p) {
    uint32_t a;
    asm("{ .reg .u64 t; cvta.to.shared.u64 t, %1; cvt.u32.u64 %0, t; }" : "=r"(a) : "l"(p));
    return a;
}
__device__ __forceinline__ void cp16(uint32_t dst, const void* src) {
    asm volatile("cp.async.ca.shared.global [%0], [%1], 16;" :: "r"(dst), "l"(src));
}

#define LDSM4(r0, r1, r2, r3, addr) \
    asm volatile("ldmatrix.sync.aligned.m8n8.x4.shared.b16 {%0,%1,%2,%3}, [%4];" \
        : "=r"(r0), "=r"(r1), "=r"(r2), "=r"(r3) : "r"(addr))

#define MMA_BF16(d, a, b) \
    asm volatile("mma.sync.aligned.m16n8k16.row.col.f32.bf16.bf16.f32 " \
        "{%0,%1,%2,%3}, {%4,%5,%6,%7}, {%8,%9}, {%0,%1,%2,%3};" \
        : "+f"((d)[0]), "+f"((d)[1]), "+f"((d)[2]), "+f"((d)[3]) \
        : "r"((a)[0]), "r"((a)[1]), "r"((a)[2]), "r"((a)[3]), \
          "r"((b)[0]), "r"((b)[1]))

// ---------------------------------------------------------------------------
// bf16x3 HMMA GEMM: CTA 256x128, 512 threads (16 warps: 8 M-rows x 2 N-cols
// of 32x64 warp tiles), CTK=64, 2-stage cp.async, 1 CTA/SM, 4 warps/SMSP.
// EPI: 0 = plain fp32 C (+bias/res), 1 = gelu-gate pair -> bf16 hi/lo,
//      2 = q rotary+scale -> bf16, 3 = kv rotary / v-transpose -> bf16
// ---------------------------------------------------------------------------
#define CTM 256
#define CTN 128
#define CTK 64
#define APITCH 72
#define OFF_SALO_B 36864u
#define OFF_SBHI_B 73728u
#define OFF_SBLO_B 92160u
#define STAGE_BYTES 110592u
#define GEMM_SMEM_BYTES (2u*STAGE_BYTES)  // 221184

template<int EPI, bool HAS_BIAS, bool HAS_RES>
__global__ void __launch_bounds__(512, 1)
bgemm_kernel(const __nv_bfloat16* __restrict__ Ahi, const __nv_bfloat16* __restrict__ Alo,
             const __nv_bfloat16* __restrict__ Whi, const __nv_bfloat16* __restrict__ Wlo,
             const float* __restrict__ bias, const float* __restrict__ res,
             float* __restrict__ C, int N, int K,
             __nv_bfloat16* __restrict__ e0, __nv_bfloat16* __restrict__ e1,
             __nv_bfloat16* __restrict__ e2, __nv_bfloat16* __restrict__ e3) {
    extern __shared__ char smc[];
    const uint32_t sb = smem_u32(smc);
    const int tid = threadIdx.x;
    const int lane = tid & 31;
    const int wid = tid >> 5;
    const int wy = wid & 7;            // 8 warp-rows of 32
    const int wx = wid >> 3;           // 2 warp-cols of 64
    const int m0 = blockIdx.y * CTM;
    const int n0 = blockIdx.x * CTN;

    const int arow = wy*32 + (lane & 15);
    const int acol = (lane >> 4) * 8;
    const uint32_t aoff = (uint32_t)(arow*APITCH + acol) * 2u;
    const int g  = lane >> 3;
    const int rr = lane & 7;
    const int brow = wx*64 + rr + ((g >> 1) << 3);
    const int bcol = (g & 1) * 8;
    const uint32_t boff = (uint32_t)(brow*APITCH + bcol) * 2u;

    float acc[2][8][4];
    #pragma unroll
    for (int i = 0; i < 2; i++)
        #pragma unroll
        for (int j = 0; j < 8; j++)
            #pragma unroll
            for (int v = 0; v < 4; v++) acc[i][j][v] = 0.f;

    const int NC = K / CTK;

    // stage loader: A 256 rows + B 128 rows, 8 chunks of 16B each, 512 thr
    #define LOAD_STAGE(stg, kb) do { \
        uint32_t sbase_ = sb + (stg)*STAGE_BYTES; \
        _Pragma("unroll") \
        for (int it_ = 0; it_ < 4; it_++) { \
            int u_ = tid + it_*512; \
            int r_ = u_ >> 3; \
            int c_ = u_ & 7; \
            uint32_t d_ = sbase_ + (uint32_t)r_*144u + (uint32_t)c_*16u; \
            size_t ga_ = (size_t)(m0 + r_) * K + (kb) + c_*8; \
            cp16(d_,              Ahi + ga_); \
            cp16(d_ + OFF_SALO_B, Alo + ga_); \
        } \
        _Pragma("unroll") \
        for (int it_ = 0; it_ < 2; it_++) { \
            int u_ = tid + it_*512; \
            int r_ = u_ >> 3; \
            int c_ = u_ & 7; \
            uint32_t d_ = sbase_ + OFF_SBHI_B + (uint32_t)r_*144u + (uint32_t)c_*16u; \
            size_t gb_ = (size_t)(n0 + r_) * K + (kb) + c_*8; \
            cp16(d_,                           Whi + gb_); \
            cp16(d_ + (OFF_SBLO_B - OFF_SBHI_B), Wlo + gb_); \
        } \
        asm volatile("cp.async.commit_group;"); \
    } while (0)

    LOAD_STAGE(0, 0);

    for (int ch = 0; ch < NC; ch++) {
        const int stg = ch & 1;
        if (ch + 1 < NC) {
            LOAD_STAGE(stg ^ 1, (ch + 1) * CTK);
            asm volatile("cp.async.wait_group 1;");
        } else {
            asm volatile("cp.async.wait_group 0;");
        }
        __syncthreads();

        const uint32_t sbase = sb + stg * STAGE_BYTES;
        #pragma unroll
        for (int k16 = 0; k16 < 4; k16++) {
            uint32_t ah[2][4], al[2][4];
            #pragma unroll
            for (int mt = 0; mt < 2; mt++) {
                uint32_t ad = sbase + aoff + (uint32_t)mt*(16*APITCH*2) + (uint32_t)k16*32u;
                LDSM4(ah[mt][0], ah[mt][1], ah[mt][2], ah[mt][3], ad);
                LDSM4(al[mt][0], al[mt][1], al[mt][2], al[mt][3], ad + OFF_SALO_B);
            }
            #pragma unroll
            for (int jp = 0; jp < 4; jp++) {
                uint32_t bd = sbase + OFF_SBHI_B + boff + (uint32_t)jp*(16*APITCH*2) + (uint32_t)k16*32u;
                uint32_t bh0,bh1,bh2,bh3, bl0,bl1,bl2,bl3;
                LDSM4(bh0,bh1,bh2,bh3, bd);
                LDSM4(bl0,bl1,bl2,bl3, bd + (OFF_SBLO_B - OFF_SBHI_B));
                uint32_t ba[2] = {bh0,bh1}, bb[2] = {bh2,bh3};
                uint32_t la[2] = {bl0,bl1}, lb[2] = {bl2,bl3};
                #pragma unroll
                for (int mt = 0; mt < 2; mt++) {
                    MMA_BF16(acc[mt][2*jp],   ah[mt], ba);
                    MMA_BF16(acc[mt][2*jp],   ah[mt], la);
                    MMA_BF16(acc[mt][2*jp],   al[mt], ba);
                    MMA_BF16(acc[mt][2*jp+1], ah[mt], bb);
                    MMA_BF16(acc[mt][2*jp+1], ah[mt], lb);
                    MMA_BF16(acc[mt][2*jp+1], al[mt], bb);
                }
            }
        }
        __syncthreads();
    }
    #undef LOAD_STAGE

    // ---- epilogues ----
    const int rbase = m0 + wy*32 + (lane >> 2);
    const int cbase = wx*64 + (lane & 3)*2;   // tile-local, even
    #pragma unroll
    for (int mt = 0; mt < 2; mt++) {
        #pragma unroll
        for (int half = 0; half < 2; half++) {
            const int row = rbase + mt*16 + half*8;
            #pragma unroll
            for (int j = 0; j < 8; j++) {
                const int coll = cbase + j*8;     // local col (even)
                const int col  = n0 + coll;       // global col
                float v0 = acc[mt][j][half*2 + 0];
                float v1 = acc[mt][j][half*2 + 1];
                if (EPI == 0) {
                    if (HAS_BIAS) { v0 += bias[col]; v1 += bias[col + 1]; }
                    if (HAS_RES) {
                        const float2 rv = *(const float2*)(res + (size_t)row * N + col);
                        v0 += rv.x; v1 += rv.y;
                    }
                    float2 o; o.x = v0; o.y = v1;
                    *(float2*)(C + (size_t)row * N + col) = o;
                } else if (EPI == 1) {
                    float y = gelu_exact(v0) * v1;
                    __nv_bfloat16 hh, ll; split_bf16(y, hh, ll);
                    size_t o = (size_t)row * GH + (col >> 1);
                    e0[o] = hh; e1[o] = ll;
                } else if (EPI == 2) {
                    int d = col & (HD - 1);
                    int hh_ = col >> 7;
                    int t = row & (Tdim - 1);
                    int b = row >> 11;
                    float inv = expf(-(float)d * ROT_C);
                    float sn, cs; sincosf((float)t * inv, &sn, &cs);
                    float y0 = (v0*cs - v1*sn) * QSCALE;
                    float y1 = (v1*cs + v0*sn) * QSCALE;
                    __nv_bfloat16 h0,l0,h1,l1;
                    split_bf16(y0,h0,l0); split_bf16(y1,h1,l1);
                    size_t o = (((size_t)(b*QH + hh_)) * Tdim + t) * HD + d;
                    *(__nv_bfloat162*)(e0 + o) = __nv_bfloat162(h0,h1);
                    *(__nv_bfloat162*)(e1 + o) = __nv_bfloat162(l0,l1);
                } else {
                    int t = row & (Tdim - 1);
                    int b = row >> 11;
                    if (col < HD) {
                        int d = col;
                        float inv = expf(-(float)d * ROT_C);
                        float sn, cs; sincosf((float)t * inv, &sn, &cs);
                        float y0 = v0*cs - v1*sn;
                        float y1 = v1*cs + v0*sn;
                        __nv_bfloat16 h0,l0,h1,l1;
                        split_bf16(y0,h0,l0); split_bf16(y1,h1,l1);
                        size_t o = (size_t)row * HD + d;
                        *(__nv_bfloat162*)(e0 + o) = __nv_bfloat162(h0,h1);
                        *(__nv_bfloat162*)(e1 + o) = __nv_bfloat162(l0,l1);
                    } else {
                        int d = col - HD;
                        __nv_bfloat16 h0,l0,h1,l1;
                        split_bf16(v0,h0,l0); split_bf16(v1,h1,l1);
                        size_t o0 = ((size_t)(b*HD + d)) * Tdim + t;
                        size_t o1 = ((size_t)(b*HD + d + 1)) * Tdim + t;
                        e2[o0] = h0; e3[o0] = l0;
                        e2[o1] = h1; e3[o1] = l1;
                    }
                }
            }
        }
    }
}

// ---------------------------------------------------------------------------
// ONE-SHOT weight conversion (unchanged)
// ---------------------------------------------------------------------------
__device__ __forceinline__ void conv_store(__nv_bfloat16* hi, __nv_bfloat16* lo,
                                           uint32_t dst4, float4 v) {
    __nv_bfloat16 h0, h1, h2, h3, l0, l1, l2, l3;
    split_bf16(v.x, h0, l0); split_bf16(v.y, h1, l1);
    split_bf16(v.z, h2, l2); split_bf16(v.w, h3, l3);
    __nv_bfloat162* hp = (__nv_bfloat162*)hi;
    __nv_bfloat162* lp = (__nv_bfloat162*)lo;
    hp[2*(size_t)dst4]   = __nv_bfloat162(h0, h1);
    hp[2*(size_t)dst4+1] = __nv_bfloat162(h2, h3);
    lp[2*(size_t)dst4]   = __nv_bfloat162(l0, l1);
    lp[2*(size_t)dst4+1] = __nv_bfloat162(l2, l3);
}

__global__ void convw_all_kernel(
    const float* __restrict__ win, const float* __restrict__ wg,
    const float* __restrict__ wout, const float* __restrict__ g1g,
    const float* __restrict__ g1s, const float* __restrict__ g2g,
    const float* __restrict__ g2s, const float* __restrict__ wq,
    const float* __restrict__ wkv, const float* __restrict__ wo2,
    __nv_bfloat16* __restrict__ hi, __nv_bfloat16* __restrict__ lo) {
    uint32_t i = blockIdx.x * blockDim.x + threadIdx.x;
    if (i >= W_TOT) return;
    const float* src;
    uint32_t base, local;
    bool ilv = false;
    if      (i < W_WG)   { src = win;  base = W_WIN;  }
    else if (i < W_WOUT) { src = wg;   base = W_WG;   }
    else if (i < W_G1G)  { src = wout; base = W_WOUT; }
    else if (i < W_G1S)  { src = g1g;  base = W_G1G;  ilv = true; }
    else if (i < W_G2G)  { src = g1s;  base = W_G1S;  }
    else if (i < W_G2S)  { src = g2g;  base = W_G2G;  ilv = true; }
    else if (i < W_Q)    { src = g2s;  base = W_G2S;  }
    else if (i < W_KV)   { src = wq;   base = W_Q;    }
    else if (i < W_O2)   { src = wkv;  base = W_KV;   }
    else                 { src = wo2;  base = W_O2;   }
    local = i - base;
    float4 v = ((const float4*)src)[local];
    uint32_t dlocal = local;
    if (ilv) {
        uint32_t r  = local >> 8;
        uint32_t c4 = local & 255u;
        uint32_t rp = (r < GH) ? (2u*r) : (2u*(r - GH) + 1u);
        dlocal = rp*256u + c4;
    }
    conv_store(hi, lo, base + dlocal, v);
}

// ---------------------------------------------------------------------------
// RMSNorm -> bf16 hi/lo
// ---------------------------------------------------------------------------
__global__ void rmsnorm_bf16_kernel(const float* __restrict__ x,
                                    const float* __restrict__ gamma,
                                    __nv_bfloat16* __restrict__ hi,
                                    __nv_bfloat16* __restrict__ lo) {
    int row = blockIdx.x;
    int tid = threadIdx.x;
    float4 v = ((const float4*)(x + (size_t)row * DIM))[tid];
    float ss = v.x*v.x + v.y*v.y + v.z*v.z + v.w*v.w;
    #pragma unroll
    for (int o = 16; o; o >>= 1) ss += __shfl_xor_sync(0xffffffffu, ss, o);
    __shared__ float red[8];
    __shared__ float stot;
    if ((tid & 31) == 0) red[tid >> 5] = ss;
    __syncthreads();
    if (tid == 0) {
        float s = 0.f;
        #pragma unroll
        for (int i = 0; i < 8; i++) s += red[i];
        stot = s;
    }
    __syncthreads();
    float scale = 32.0f * rsqrtf(stot);
    float4 g = ((const float4*)gamma)[tid];
    float o0 = v.x*scale*g.x, o1 = v.y*scale*g.y, o2 = v.z*scale*g.z, o3 = v.w*scale*g.w;
    __nv_bfloat16 h0,h1,h2,h3,l0,l1,l2,l3;
    split_bf16(o0,h0,l0); split_bf16(o1,h1,l1); split_bf16(o2,h2,l2); split_bf16(o3,h3,l3);
    __nv_bfloat162* hp = (__nv_bfloat162*)(hi + (size_t)row * DIM);
    __nv_bfloat162* lp = (__nv_bfloat162*)(lo + (size_t)row * DIM);
    hp[2*tid]   = __nv_bfloat162(h0,h1);
    hp[2*tid+1] = __nv_bfloat162(h2,h3);
    lp[2*tid]   = __nv_bfloat162(l0,l1);
    lp[2*tid+1] = __nv_bfloat162(l2,l3);
}

// ---------------------------------------------------------------------------
// hawk depthwise causal conv (K=4), sliding-window (unchanged)
// ---------------------------------------------------------------------------
#define TCH 32
__global__ void __launch_bounds__(384)
conv_kernel(const float* __restrict__ gh,
            const float* __restrict__ cw,
            const float* __restrict__ cb,
            float* __restrict__ hconv,
            __nv_bfloat16* __restrict__ hi,
            __nv_bfloat16* __restrict__ lo) {
    __shared__ float scw[HID*KCONV];
    const int tb = blockIdx.x;
    const int b  = blockIdx.y;
    const int c4 = threadIdx.x;
    const int c  = c4 * 4;
    for (int i = threadIdx.x; i < (HID*KCONV)/4; i += 384)
        ((float4*)scw)[i] = ((const float4*)cw)[i];
    __syncthreads();
    float w[4][4];
    #pragma unroll
    for (int i = 0; i < 4; i++)
        #pragma unroll
        for (int k = 0; k < 4; k++) w[i][k] = scw[(c+i)*KCONV + k];
    const float4 bias = ((const float4*)cb)[c4];
    const int t0 = tb * TCH;
    float4 win[4];
    #pragma unroll
    for (int k = 0; k < 3; k++) {
        int tt = t0 - 3 + k;
        win[k] = make_float4(0.f, 0.f, 0.f, 0.f);
        if (tt >= 0)
            win[k] = *(const float4*)(gh + (size_t)(b*Tdim + tt)*(2*HID) + HID + c);
    }
    for (int dt = 0; dt < TCH; dt++) {
        const int t = t0 + dt;
        win[3] = *(const float4*)(gh + (size_t)(b*Tdim + t)*(2*HID) + HID + c);
        float4 acc = bias;
        #pragma unroll
        for (int k = 0; k < 4; k++) {
            acc.x = fmaf(w[0][k], win[k].x, acc.x);
            acc.y = fmaf(w[1][k], win[k].y, acc.y);
            acc.z = fmaf(w[2][k], win[k].z, acc.z);
            acc.w = fmaf(w[3][k], win[k].w, acc.w);
        }
        const size_t bt = (size_t)(b*Tdim + t);
        *(float4*)(hconv + bt * HID + c) = acc;
        __nv_bfloat16 h0,h1,h2,h3,l0,l1,l2,l3;
        split_bf16(acc.x,h0,l0); split_bf16(acc.y,h1,l1);
        split_bf16(acc.z,h2,l2); split_bf16(acc.w,h3,l3);
        __nv_bfloat162* hp = (__nv_bfloat162*)(hi + bt * HID + c);
        __nv_bfloat162* lp = (__nv_bfloat162*)(lo + bt * HID + c);
        hp[0] = __nv_bfloat162(h0,h1);
        hp[1] = __nv_bfloat162(h2,h3);
        lp[0] = __nv_bfloat162(l0,l1);
        lp[1] = __nv_bfloat162(l2,l3);
        win[0] = win[1]; win[1] = win[2]; win[2] = win[3];
    }
}

// ---------------------------------------------------------------------------
// chunked parallel scan (unchanged)
// ---------------------------------------------------------------------------
#define SCH 128
#define NCH 16
__global__ void scanAG_kernel(float* __restrict__ gi,
                              const float* __restrict__ hconv,
                              const float* __restrict__ fb,
                              float* __restrict__ chA, float* __restrict__ chS) {
    int idx = blockIdx.x * blockDim.x + threadIdx.x;
    if (idx >= Bdim * NCH * HID) return;
    int c = idx % HID;
    int r = idx / HID;
    int ch = r & (NCH - 1);
    int b  = r >> 4;
    const float m8sp = -8.0f * log1pf(expf(fb[c]));
    size_t base = ((size_t)b * Tdim + ch * SCH) * (2*HID) + c;
    size_t hb   = ((size_t)b * Tdim + ch * SCH) * HID + c;
    float ap = 1.f, s = 0.f;
    for (int t = 0; t < SCH; t++) {
        size_t o = base + (size_t)t * (2*HID);
        float f  = gi[o];
        float ip = gi[o + HID];
        float h  = hconv[hb + (size_t)t * HID];
        float alpha = expf(m8sp * sigmoidf_(f));
        float beta  = sqrtf(1.0f - alpha*alpha + 1e-6f);
        float xs = beta * sigmoidf_(ip) * h;
        gi[o]       = alpha;
        gi[o + HID] = xs;
        s = fmaf(alpha, s, xs);
        ap *= alpha;
    }
    chA[idx] = ap;
    chS[idx] = s;
}
__global__ void scanB_kernel(const float* __restrict__ chA, const float* __restrict__ chS,
                             float* __restrict__ sIn) {
    int idx = blockIdx.x * blockDim.x + threadIdx.x;
    if (idx >= Bdim * HID) return;
    int c = idx % HID;
    int b = idx / HID;
    float s = 0.f;
    #pragma unroll
    for (int ch = 0; ch < NCH; ch++) {
        size_t o = ((size_t)(b * NCH + ch)) * HID + c;
        sIn[o] = s;
        s = fmaf(chA[o], s, chS[o]);
    }
}
__global__ void scanC_kernel(const float* __restrict__ gi, const float* __restrict__ gh,
                             const float* __restrict__ sIn,
                             __nv_bfloat16* __restrict__ hi, __nv_bfloat16* __restrict__ lo) {
    int idx = blockIdx.x * blockDim.x + threadIdx.x;
    if (idx >= Bdim * NCH * HID) return;
    int c = idx % HID;
    int r = idx / HID;
    int ch = r & (NCH - 1);
    int b  = r >> 4;
    float st = sIn[idx];
    size_t base = ((size_t)b * Tdim + ch * SCH) * (2*HID) + c;
    size_t ob   = ((size_t)b * Tdim + ch * SCH) * HID + c;
    for (int t = 0; t < SCH; t++) {
        size_t o = base + (size_t)t * (2*HID);
        float a = gi[o];
        float x = gi[o + HID];
        float g = gh[o];
        st = fmaf(a, st, x);
        float y = gelu_exact(g) * st;
        __nv_bfloat16 h, l; split_bf16(y, h, l);
        hi[ob + (size_t)t * HID] = h;
        lo[ob + (size_t)t * HID] = l;
    }
}

// ---------------------------------------------------------------------------
// HMMA flash attention (unchanged from R12): bf16x3 QK^T, PV hi-only P
// ---------------------------------------------------------------------------
#define AQ 128
#define AQH_OFF 0u
#define AQL_OFF 34816u
#define AST_OFF 69632u
#define AKH 0u
#define AKL 17408u
#define AVH 34816u
#define AVL 53248u
#define ASTAGE 71680u
#define ATT_SMEM (69632u + 2u*71680u)   // 212992

__global__ void __launch_bounds__(256, 1)
attn_hmma_kernel(const __nv_bfloat16* __restrict__ qhi, const __nv_bfloat16* __restrict__ qlo,
                 const __nv_bfloat16* __restrict__ khi, const __nv_bfloat16* __restrict__ klo,
                 const __nv_bfloat16* __restrict__ vthi, const __nv_bfloat16* __restrict__ vtlo,
                 __nv_bfloat16* __restrict__ ohi, __nv_bfloat16* __restrict__ olo) {
    extern __shared__ char smc[];
    const uint32_t sb = smem_u32(smc);
    const int tid  = threadIdx.x;
    const int lane = tid & 31;
    const int w    = tid >> 5;
    const int b  = blockIdx.z;
    const int h  = blockIdx.y;
    const int q0 = blockIdx.x * AQ;

    {
        const __nv_bfloat16* qh_ = qhi + ((size_t)(b*QH + h) * Tdim + q0) * HD;
        const __nv_bfloat16* ql_ = qlo + ((size_t)(b*QH + h) * Tdim + q0) * HD;
        #pragma unroll
        for (int it = 0; it < 8; it++) {
            int u = tid + it*256;
            int r = u >> 4, c = u & 15;
            uint32_t d = sb + AQH_OFF + (uint32_t)r*272u + (uint32_t)c*16u;
            cp16(d,           qh_ + (size_t)r*HD + c*8);
            cp16(d + AQL_OFF, ql_ + (size_t)r*HD + c*8);
        }
        asm volatile("cp.async.commit_group;");
    }

    const int ks0 = (q0 >= WINSZ) ? (q0 - WINSZ) : 0;
    const int nt  = (q0 + AQ - ks0) >> 6;

    #define LOAD_KV(stg, ks) do { \
        uint32_t sbase_ = sb + AST_OFF + (uint32_t)(stg)*ASTAGE; \
        const __nv_bfloat16* kh_ = khi + ((size_t)b*Tdim + (ks))*HD; \
        const __nv_bfloat16* kl_ = klo + ((size_t)b*Tdim + (ks))*HD; \
        const __nv_bfloat16* vh_ = vthi + (size_t)b*HD*Tdim + (ks); \
        const __nv_bfloat16* vl_ = vtlo + (size_t)b*HD*Tdim + (ks); \
        _Pragma("unroll") \
        for (int it_ = 0; it_ < 4; it_++) { \
            int u_ = tid + it_*256; \
            int r_ = u_ >> 4, c_ = u_ & 15; \
            uint32_t d_ = sbase_ + AKH + (uint32_t)r_*272u + (uint32_t)c_*16u; \
            cp16(d_,             kh_ + (size_t)r_*HD + c_*8); \
            cp16(d_ + (AKL-AKH), kl_ + (size_t)r_*HD + c_*8); \
            int r2_ = u_ >> 3, c2_ = u_ & 7; \
            uint32_t d2_ = sbase_ + AVH + (uint32_t)r2_*144u + (uint32_t)c2_*16u; \
            cp16(d2_,            vh_ + (size_t)r2_*Tdim + c2_*8); \
            cp16(d2_ + (AVL-AVH), vl_ + (size_t)r2_*Tdim + c2_*8); \
        } \
        asm volatile("cp.async.commit_group;"); \
    } while (0)

    LOAD_KV(0, ks0);
    asm volatile("cp.async.wait_group 1;");
    __syncthreads();

    uint32_t qfh[8][4], qfl[8][4];
    {
        const int arow = w*16 + (lane & 15);
        const int acol = (lane >> 4) * 8;
        uint32_t abase = sb + AQH_OFF + (uint32_t)(arow*136 + acol)*2u;
        #pragma unroll
        for (int k = 0; k < 8; k++) {
            LDSM4(qfh[k][0],qfh[k][1],qfh[k][2],qfh[k][3], abase + (uint32_t)k*32u);
            LDSM4(qfl[k][0],qfl[k][1],qfl[k][2],qfl[k][3], abase + AQL_OFF + (uint32_t)k*32u);
        }
    }

    float o_[16][4];
    #pragma unroll
    for (int j = 0; j < 16; j++)
        #pragma unroll
        for (int v = 0; v < 4; v++) o_[j][v] = 0.f;
    float m0 = -1e30f, m1 = -1e30f, l0 = 0.f, l1 = 0.f;

    const int t0 = q0 + w*16 + (lane >> 2);
    const int t1 = t0 + 8;
    const int cb2 = (lane & 3)*2;
    const int gB  = lane >> 3;
    const int rrB = lane & 7;
    const int browB = rrB + ((gB >> 1) << 3);
    const int bcolB = (gB & 1) * 8;

    for (int i = 0; i < nt; i++) {
        const int stg = i & 1;
        if (i + 1 < nt) {
            LOAD_KV(stg ^ 1, ks0 + (i+1)*64);
            asm volatile("cp.async.wait_group 1;");
        } else {
            asm volatile("cp.async.wait_group 0;");
        }
        __syncthreads();
        const uint32_t kb_ = sb + AST_OFF + (uint32_t)stg*ASTAGE;
        const int ks = ks0 + i*64;

        float s_[8][4];
        #pragma unroll
        for (int j = 0; j < 8; j++)
            #pragma unroll
            for (int v = 0; v < 4; v++) s_[j][v] = 0.f;
        #pragma unroll
        for (int jp = 0; jp < 4; jp++) {
            #pragma unroll
            for (int k = 0; k < 8; k++) {
                uint32_t ad = kb_ + AKH + (uint32_t)((browB + jp*16)*136 + bcolB + k*16)*2u;
                uint32_t bh0,bh1,bh2,bh3, bl0,bl1,bl2,bl3;
                LDSM4(bh0,bh1,bh2,bh3, ad);
                LDSM4(bl0,bl1,bl2,bl3, ad + (AKL-AKH));
                uint32_t ba[2] = {bh0,bh1}, bb[2] = {bh2,bh3};
                uint32_t la[2] = {bl0,bl1}, lb[2] = {bl2,bl3};
                MMA_BF16(s_[2*jp],   qfh[k], ba);
                MMA_BF16(s_[2*jp],   qfl[k], ba);
                MMA_BF16(s_[2*jp],   qfh[k], la);
                MMA_BF16(s_[2*jp+1], qfh[k], bb);
                MMA_BF16(s_[2*jp+1], qfl[k], bb);
                MMA_BF16(s_[2*jp+1], qfh[k], lb);
            }
        }

        float mx0 = -1e30f, mx1 = -1e30f;
        #pragma unroll
        for (int jf = 0; jf < 8; jf++) {
            #pragma unroll
            for (int cc = 0; cc < 2; cc++) {
                int g = ks + jf*8 + cb2 + cc;
                if (!(g <= t0 && g >= t0 - WINSZ)) s_[jf][cc]   = -1e30f;
                if (!(g <= t1 && g >= t1 - WINSZ)) s_[jf][2+cc] = -1e30f;
            }
            mx0 = fmaxf(mx0, fmaxf(s_[jf][0], s_[jf][1]));
            mx1 = fmaxf(mx1, fmaxf(s_[jf][2], s_[jf][3]));
        }
        mx0 = fmaxf(mx0, __shfl_xor_sync(0xffffffffu, mx0, 1));
        mx0 = fmaxf(mx0, __shfl_xor_sync(0xffffffffu, mx0, 2));
        mx1 = fmaxf(mx1, __shfl_xor_sync(0xffffffffu, mx1, 1));
        mx1 = fmaxf(mx1, __shfl_xor_sync(0xffffffffu, mx1, 2));
        float m0n = fmaxf(m0, mx0), m1n = fmaxf(m1, mx1);
        float c0 = exp2f((m0 - m0n)*LOG2E), c1 = exp2f((m1 - m1n)*LOG2E);

        float rs0 = 0.f, rs1 = 0.f;
        uint32_t pfh[4][4];
        #pragma unroll
        for (int kf = 0; kf < 4; kf++) {
            #pragma unroll
            for (int jj = 0; jj < 2; jj++) {
                const int jf = 2*kf + jj;
                float p0 = (s_[jf][0] > -1e29f) ? exp2f((s_[jf][0] - m0n)*LOG2E) : 0.f;
                float p1 = (s_[jf][1] > -1e29f) ? exp2f((s_[jf][1] - m0n)*LOG2E) : 0.f;
                float p2 = (s_[jf][2] > -1e29f) ? exp2f((s_[jf][2] - m1n)*LOG2E) : 0.f;
                float p3 = (s_[jf][3] > -1e29f) ? exp2f((s_[jf][3] - m1n)*LOG2E) : 0.f;
                rs0 += p0 + p1;
                rs1 += p2 + p3;
                __nv_bfloat162 hA(__float2bfloat16(p0), __float2bfloat16(p1));
                __nv_bfloat162 hB(__float2bfloat16(p2), __float2bfloat16(p3));
                pfh[kf][0 + 2*jj] = *(uint32_t*)&hA;
                pfh[kf][1 + 2*jj] = *(uint32_t*)&hB;
            }
        }
        rs0 += __shfl_xor_sync(0xffffffffu, rs0, 1);
        rs0 += __shfl_xor_sync(0xffffffffu, rs0, 2);
        rs1 += __shfl_xor_sync(0xffffffffu, rs1, 1);
        rs1 += __shfl_xor_sync(0xffffffffu, rs1, 2);
        l0 = l0*c0 + rs0;
        l1 = l1*c1 + rs1;
        m0 = m0n; m1 = m1n;
        #pragma unroll
        for (int j = 0; j < 16; j++) {
            o_[j][0] *= c0; o_[j][1] *= c0;
            o_[j][2] *= c1; o_[j][3] *= c1;
        }

        // O += P V  (P bf16, V split hi+lo)
        #pragma unroll
        for (int jp = 0; jp < 8; jp++) {
            #pragma unroll
            for (int kf = 0; kf < 4; kf++) {
                uint32_t ad = kb_ + AVH + (uint32_t)((browB + jp*16)*72 + bcolB + kf*16)*2u;
                uint32_t vh0,vh1,vh2,vh3, vl0,vl1,vl2,vl3;
                LDSM4(vh0,vh1,vh2,vh3, ad);
                LDSM4(vl0,vl1,vl2,vl3, ad + (AVL-AVH));
                uint32_t va[2] = {vh0,vh1}, vb[2] = {vh2,vh3};
                uint32_t wa[2] = {vl0,vl1}, wb[2] = {vl2,vl3};
                MMA_BF16(o_[2*jp],   pfh[kf], va);
                MMA_BF16(o_[2*jp],   pfh[kf], wa);
                MMA_BF16(o_[2*jp+1], pfh[kf], vb);
                MMA_BF16(o_[2*jp+1], pfh[kf], wb);
            }
        }
        __syncthreads();
    }
    #undef LOAD_KV

    const float inv0 = 1.0f / l0;
    const float inv1 = 1.0f / l1;
    const size_t ob0 = ((size_t)(b*Tdim) + t0) * (QH*HD) + h*HD;
    const size_t ob1 = ((size_t)(b*Tdim) + t1) * (QH*HD) + h*HD;
    #pragma unroll
    for (int jn = 0; jn < 16; jn++) {
        int d = jn*8 + cb2;
        float y0 = o_[jn][0]*inv0, y1 = o_[jn][1]*inv0;
        float y2 = o_[jn][2]*inv1, y3 = o_[jn][3]*inv1;
        __nv_bfloat16 h0,lo0,h1,lo1,h2,lo2,h3,lo3;
        split_bf16(y0,h0,lo0); split_bf16(y1,h1,lo1);
        split_bf16(y2,h2,lo2); split_bf16(y3,h3,lo3);
        *(__nv_bfloat162*)(ohi + ob0 + d) = __nv_bfloat162(h0,h1);
        *(__nv_bfloat162*)(olo + ob0 + d) = __nv_bfloat162(lo0,lo1);
        *(__nv_bfloat162*)(ohi + ob1 + d) = __nv_bfloat162(h2,h3);
        *(__nv_bfloat162*)(olo + ob1 + d) = __nv_bfloat162(lo2,lo3);
    }
}

// ---------------------------------------------------------------------------
// launch helper (grid passed explicitly)
// ---------------------------------------------------------------------------
#define LAUNCH_G(g, EPI, BIAS, RES, ...) \
    bgemm_kernel<EPI, BIAS, RES><<<(g), 512, GEMM_SMEM_BYTES>>>(__VA_ARGS__)

extern "C" void kernel_launch(void* const* d_in, const int* in_sizes, int n_in,
                              void* d_out, int out_size) {
    const float* x         = (const float*)d_in[0];
    const float* gn_hawk   = (const float*)d_in[1];
    const float* gn_hgmlp  = (const float*)d_in[2];
    const float* gn_smqa   = (const float*)d_in[3];
    const float* gn_sgmlp  = (const float*)d_in[4];
    const float* hawk_Win  = (const float*)d_in[5];
    const float* hawk_cw   = (const float*)d_in[6];
    const float* hawk_cb   = (const float*)d_in[7];
    const float* hawk_Wg   = (const float*)d_in[8];
    const float* hawk_bg   = (const float*)d_in[9];
    const float* hawk_fb   = (const float*)d_in[10];
    const float* hawk_Wout = (const float*)d_in[11];
    const float* g1_Wgrow  = (const float*)d_in[12];
    const float* g1_Wshr   = (const float*)d_in[13];
    const float* g2_Wgrow  = (const float*)d_in[14];
    const float* g2_Wshr   = (const float*)d_in[15];
    const float* smqa_Wq   = (const float*)d_in[16];
    const float* smqa_Wkv  = (const float*)d_in[17];
    const float* smqa_Wout = (const float*)d_in[18];
    float* out = (float*)d_out;

    float *big, *mid, *small, *chA, *chS, *sIn;
    __nv_bfloat16 *Ahi, *Alo, *Whi, *Wlo;
    cudaGetSymbolAddress((void**)&big,   g_big);
    cudaGetSymbolAddress((void**)&mid,   g_mid);
    cudaGetSymbolAddress((void**)&small, g_small);
    cudaGetSymbolAddress((void**)&Ahi,   g_Ahi);
    cudaGetSymbolAddress((void**)&Alo,   g_Alo);
    cudaGetSymbolAddress((void**)&Whi,   g_Whi);
    cudaGetSymbolAddress((void**)&Wlo,   g_Wlo);
    cudaGetSymbolAddress((void**)&chA,   g_chA);
    cudaGetSymbolAddress((void**)&chS,   g_chS);
    cudaGetSymbolAddress((void**)&sIn,   g_sIn);

    cudaFuncSetAttribute((const void*)attn_hmma_kernel,
                         cudaFuncAttributeMaxDynamicSharedMemorySize, (int)ATT_SMEM);
    cudaFuncSetAttribute((const void*)bgemm_kernel<0,false,false>,
                         cudaFuncAttributeMaxDynamicSharedMemorySize, GEMM_SMEM_BYTES);
    cudaFuncSetAttribute((const void*)bgemm_kernel<0,true,false>,
                         cudaFuncAttributeMaxDynamicSharedMemorySize, GEMM_SMEM_BYTES);
    cudaFuncSetAttribute((const void*)bgemm_kernel<0,false,true>,
                         cudaFuncAttributeMaxDynamicSharedMemorySize, GEMM_SMEM_BYTES);
    cudaFuncSetAttribute((const void*)bgemm_kernel<1,false,false>,
                         cudaFuncAttributeMaxDynamicSharedMemorySize, GEMM_SMEM_BYTES);
    cudaFuncSetAttribute((const void*)bgemm_kernel<2,false,false>,
                         cudaFuncAttributeMaxDynamicSharedMemorySize, GEMM_SMEM_BYTES);
    cudaFuncSetAttribute((const void*)bgemm_kernel<3,false,false>,
                         cudaFuncAttributeMaxDynamicSharedMemorySize, GEMM_SMEM_BYTES);

    const int EW = 256;
    __nv_bfloat16* nb = nullptr;

    // weight slices
    __nv_bfloat16* WinH  = Whi + (size_t)W_WIN*4;   __nv_bfloat16* WinL  = Wlo + (size_t)W_WIN*4;
    __nv_bfloat16* WgH   = Whi + (size_t)W_WG*4;    __nv_bfloat16* WgL   = Wlo + (size_t)W_WG*4;
    __nv_bfloat16* WoutH = Whi + (size_t)W_WOUT*4;  __nv_bfloat16* WoutL = Wlo + (size_t)W_WOUT*4;
    __nv_bfloat16* G1gH  = Whi + (size_t)W_G1G*4;   __nv_bfloat16* G1gL  = Wlo + (size_t)W_G1G*4;
    __nv_bfloat16* G1sH  = Whi + (size_t)W_G1S*4;   __nv_bfloat16* G1sL  = Wlo + (size_t)W_G1S*4;
    __nv_bfloat16* G2gH  = Whi + (size_t)W_G2G*4;   __nv_bfloat16* G2gL  = Wlo + (size_t)W_G2G*4;
    __nv_bfloat16* G2sH  = Whi + (size_t)W_G2S*4;   __nv_bfloat16* G2sL  = Wlo + (size_t)W_G2S*4;
    __nv_bfloat16* WqH   = Whi + (size_t)W_Q*4;     __nv_bfloat16* WqL   = Wlo + (size_t)W_Q*4;
    __nv_bfloat16* WkvH  = Whi + (size_t)W_KV*4;    __nv_bfloat16* WkvL  = Wlo + (size_t)W_KV*4;
    __nv_bfloat16* Wo2H  = Whi + (size_t)W_O2*4;    __nv_bfloat16* Wo2L  = Wlo + (size_t)W_O2*4;

    // grids (CTM=256, CTN=128)
    const dim3 gridWin((2*HID)/CTN, MROWS/CTM);   // 24 x 32
    const dim3 gridDim_(DIM/CTN, MROWS/CTM);      // 8 x 32
    const dim3 gridGrow((2*GH)/CTN, MROWS/CTM);   // 32 x 32
    const dim3 gridQ((QH*HD)/CTN, MROWS/CTM);     // 8 x 32
    const dim3 gridKV((2*HD)/CTN, MROWS/CTM);     // 2 x 32

    // attn bf16 buffers inside g_mid
    __nv_bfloat16* qhi  = (__nv_bfloat16*)mid;
    __nv_bfloat16* qlo  = (__nv_bfloat16*)(mid + 4194304);
    __nv_bfloat16* khi  = (__nv_bfloat16*)(mid + 8388608);
    __nv_bfloat16* klo  = (__nv_bfloat16*)(mid + 8912896);
    __nv_bfloat16* vthi = (__nv_bfloat16*)(mid + 9437184);
    __nv_bfloat16* vtlo = (__nv_bfloat16*)(mid + 9961472);
    __nv_bfloat16* acth = (__nv_bfloat16*)mid;
    __nv_bfloat16* actl = (__nv_bfloat16*)(mid + 8388608);

    // ---------------- one-shot: convert all weights ----------------
    convw_all_kernel<<<(W_TOT + EW - 1)/EW, EW>>>(
        hawk_Win, hawk_Wg, hawk_Wout, g1_Wgrow, g1_Wshr,
        g2_Wgrow, g2_Wshr, smqa_Wq, smqa_Wkv, smqa_Wout, Whi, Wlo);

    // ---------------- stage 1: hawk ----------------
    rmsnorm_bf16_kernel<<<MROWS, 256>>>(x, gn_hawk, Ahi, Alo);
    LAUNCH_G(gridWin, 0,false,false, Ahi,Alo,WinH,WinL, nullptr,nullptr, big, 2*HID, DIM, nb,nb,nb,nb);
    conv_kernel<<<dim3(Tdim/TCH, Bdim), 384>>>(big, hawk_cw, hawk_cb, small, Ahi, Alo);
    LAUNCH_G(gridWin, 0,true,false, Ahi,Alo,WgH,WgL, hawk_bg,nullptr, mid, 2*HID, HID, nb,nb,nb,nb);
    scanAG_kernel<<<(Bdim*NCH*HID + EW - 1)/EW, EW>>>(mid, small, hawk_fb, chA, chS);
    scanB_kernel<<<(Bdim*HID + EW - 1)/EW, EW>>>(chA, chS, sIn);
    scanC_kernel<<<(Bdim*NCH*HID + EW - 1)/EW, EW>>>(mid, big, sIn, Ahi, Alo);
    LAUNCH_G(gridDim_, 0,false,true, Ahi,Alo,WoutH,WoutL, nullptr,x, out, DIM, HID, nb,nb,nb,nb);

    // ---------------- stage 2: gated MLP 1 ----------------
    rmsnorm_bf16_kernel<<<MROWS, 256>>>(out, gn_hgmlp, Ahi, Alo);
    LAUNCH_G(gridGrow, 1,false,false, Ahi,Alo,G1gH,G1gL, nullptr,nullptr, nullptr, 2*GH, DIM,
             acth, actl, nb, nb);
    LAUNCH_G(gridDim_, 0,false,true, acth,actl,G1sH,G1sL, nullptr,out, out, DIM, GH, nb,nb,nb,nb);

    // ---------------- stage 3: sliding-window MQA ----------------
    rmsnorm_bf16_kernel<<<MROWS, 256>>>(out, gn_smqa, Ahi, Alo);
    LAUNCH_G(gridQ, 2,false,false, Ahi,Alo,WqH,WqL, nullptr,nullptr, nullptr, QH*HD, DIM,
             qhi, qlo, nb, nb);
    LAUNCH_G(gridKV, 3,false,false, Ahi,Alo,WkvH,WkvL, nullptr,nullptr, nullptr, 2*HD, DIM,
             khi, klo, vthi, vtlo);
    attn_hmma_kernel<<<dim3(Tdim/AQ, QH, Bdim), 256, ATT_SMEM>>>(
        qhi, qlo, khi, klo, vthi, vtlo, Ahi, Alo);
    LAUNCH_G(gridDim_, 0,false,true, Ahi,Alo,Wo2H,Wo2L, nullptr,out, out, DIM, DIM, nb,nb,nb,nb);

    // ---------------- stage 4: gated MLP 2 ----------------
    rmsnorm_bf16_kernel<<<MROWS, 256>>>(out, gn_sgmlp, Ahi, Alo);
    LAUNCH_G(gridGrow, 1,false,false, Ahi,Alo,G2gH,G2gL, nullptr,nullptr, nullptr, 2*GH, DIM,
             acth, actl, nb, nb);
    LAUNCH_G(gridDim_, 0,false,true, acth,actl,G2sH,G2sL, nullptr,out, out, DIM, GH, nb,nb,nb,nb);
}

// round 14
// speedup vs baseline: 1.0912x; 1.0912x over previous
#include <cuda_runtime.h>
#include <cuda_bf16.h>
#include <math.h>
#include <stdint.h>

// ---------------------------------------------------------------------------
// GriffinBlock: HMMA bf16x3 GEMMs (R12 config) + merged QKV epilogue GEMM
// B=4, T=2048, DIM=1024, HID=1536, GH=2048, K=4, HD=128, QH=8, W=1024
// ---------------------------------------------------------------------------

#define Bdim 4
#define Tdim 2048
#define DIM 1024
#define HID 1536
#define GH  2048
#define KCONV 4
#define HD  128
#define QH  8
#define WINSZ 1024
#define MROWS (Bdim*Tdim)   // 8192
#define LOG2E 1.4426950408889634f
#define QSCALE 0.088388347648318447f
#define ROT_C (9.210340371976184f / 128.0f)

// ---------------- static scratch ----------------
__device__ float g_big[33554432];      // 8192*4096
__device__ float g_mid[25165824];      // 8192*3072 (hawk gi; act/attn bf16 scratch)
__device__ float g_small[12582912];    // 8192*1536
__device__ __nv_bfloat16 g_Ahi[16777216];  // 8192*2048 max
__device__ __nv_bfloat16 g_Alo[16777216];
__device__ __nv_bfloat16 g_Whi[24379392];  // all weights, bf16 hi
__device__ __nv_bfloat16 g_Wlo[24379392];  // all weights, bf16 lo
__device__ float g_chA[98304];
__device__ float g_chS[98304];
__device__ float g_sIn[98304];

// weight slice offsets in float4 units (x4 for elements)
#define W_WIN  0u
#define W_WG   786432u
#define W_WOUT 1966080u
#define W_G1G  2359296u
#define W_G1S  3407872u
#define W_G2G  3932160u
#define W_G2S  4980736u
#define W_Q    5505024u
#define W_KV   5767168u
#define W_O2   5832704u
#define W_TOT  6094848u

__device__ __forceinline__ float gelu_exact(float x) {
    return 0.5f * x * (1.0f + erff(x * 0.70710678118654752f));
}
__device__ __forceinline__ float sigmoidf_(float x) {
    return 1.0f / (1.0f + expf(-x));
}
__device__ __forceinline__ void split_bf16(float v, __nv_bfloat16& h, __nv_bfloat16& l) {
    h = __float2bfloat16(v);
    l = __float2bfloat16(v - __bfloat162float(h));
}

__device__ __forceinline__ uint32_t smem_u32(const void* p) {
    uint32_t a;
    asm("{ .reg .u64 t; cvta.to.shared.u64 t, %1; cvt.u32.u64 %0, t; }" : "=r"(a) : "l"(p));
    return a;
}
__device__ __forceinline__ void cp16(uint32_t dst, const void* src) {
    asm volatile("cp.async.ca.shared.global [%0], [%1], 16;" :: "r"(dst), "l"(src));
}

#define LDSM4(r0, r1, r2, r3, addr) \
    asm volatile("ldmatrix.sync.aligned.m8n8.x4.shared.b16 {%0,%1,%2,%3}, [%4];" \
        : "=r"(r0), "=r"(r1), "=r"(r2), "=r"(r3) : "r"(addr))

#define MMA_BF16(d, a, b) \
    asm volatile("mma.sync.aligned.m16n8k16.row.col.f32.bf16.bf16.f32 " \
        "{%0,%1,%2,%3}, {%4,%5,%6,%7}, {%8,%9}, {%0,%1,%2,%3};" \
        : "+f"((d)[0]), "+f"((d)[1]), "+f"((d)[2]), "+f"((d)[3]) \
        : "r"((a)[0]), "r"((a)[1]), "r"((a)[2]), "r"((a)[3]), \
          "r"((b)[0]), "r"((b)[1]))

// ---------------------------------------------------------------------------
// bf16x3 HMMA GEMM (R12 config): CTA 128x128, warp 32x64, CTK=64, 2-stage.
// EPI: 0 = plain fp32 C (+bias/res), 1 = gelu-gate pair -> bf16 hi/lo,
//      4 = merged QKV: col<1024 q rotary; 1024..1151 k rotary; >=1152 v transp
// ---------------------------------------------------------------------------
#define CTM 128
#define CTN 128
#define CTK 64
#define APITCH 72
#define OFF_SALO_B 18432u
#define OFF_SBHI_B 36864u
#define OFF_SBLO_B 55296u
#define STAGE_BYTES 73728u
#define GEMM_SMEM_BYTES (2u*STAGE_BYTES)  // 147456

template<int EPI, bool HAS_BIAS, bool HAS_RES>
__global__ void __launch_bounds__(256, 1)
bgemm_kernel(const __nv_bfloat16* __restrict__ Ahi, const __nv_bfloat16* __restrict__ Alo,
             const __nv_bfloat16* __restrict__ Whi, const __nv_bfloat16* __restrict__ Wlo,
             const float* __restrict__ bias, const float* __restrict__ res,
             float* __restrict__ C, int N, int K,
             __nv_bfloat16* __restrict__ e0, __nv_bfloat16* __restrict__ e1,
             __nv_bfloat16* __restrict__ e2, __nv_bfloat16* __restrict__ e3,
             __nv_bfloat16* __restrict__ e4, __nv_bfloat16* __restrict__ e5) {
    extern __shared__ char smc[];
    const uint32_t sb = smem_u32(smc);
    const int tid = threadIdx.x;
    const int lane = tid & 31;
    const int wid = tid >> 5;
    const int wy = wid & 3;
    const int wx = wid >> 2;
    const int m0 = blockIdx.y * CTM;
    const int n0 = blockIdx.x * CTN;

    const int arow = wy*32 + (lane & 15);
    const int acol = (lane >> 4) * 8;
    const uint32_t aoff = (uint32_t)(arow*APITCH + acol) * 2u;
    const int g  = lane >> 3;
    const int rr = lane & 7;
    const int brow = wx*64 + rr + ((g >> 1) << 3);
    const int bcol = (g & 1) * 8;
    const uint32_t boff = (uint32_t)(brow*APITCH + bcol) * 2u;

    float acc[2][8][4];
    #pragma unroll
    for (int i = 0; i < 2; i++)
        #pragma unroll
        for (int j = 0; j < 8; j++)
            #pragma unroll
            for (int v = 0; v < 4; v++) acc[i][j][v] = 0.f;

    const int NC = K / CTK;

    #define LOAD_STAGE(stg, kb) do { \
        uint32_t sbase_ = sb + (stg)*STAGE_BYTES; \
        _Pragma("unroll") \
        for (int it_ = 0; it_ < 4; it_++) { \
            int u_ = tid + it_*256; \
            int r_ = u_ >> 3; \
            int c_ = u_ & 7; \
            uint32_t d_ = sbase_ + (uint32_t)r_*144u + (uint32_t)c_*16u; \
            size_t ga_ = (size_t)(m0 + r_) * K + (kb) + c_*8; \
            size_t gb_ = (size_t)(n0 + r_) * K + (kb) + c_*8; \
            cp16(d_,              Ahi + ga_); \
            cp16(d_ + OFF_SALO_B, Alo + ga_); \
            cp16(d_ + OFF_SBHI_B, Whi + gb_); \
            cp16(d_ + OFF_SBLO_B, Wlo + gb_); \
        } \
        asm volatile("cp.async.commit_group;"); \
    } while (0)

    LOAD_STAGE(0, 0);

    for (int ch = 0; ch < NC; ch++) {
        const int stg = ch & 1;
        if (ch + 1 < NC) {
            LOAD_STAGE(stg ^ 1, (ch + 1) * CTK);
            asm volatile("cp.async.wait_group 1;");
        } else {
            asm volatile("cp.async.wait_group 0;");
        }
        __syncthreads();

        const uint32_t sbase = sb + stg * STAGE_BYTES;
        #pragma unroll
        for (int k16 = 0; k16 < 4; k16++) {
            uint32_t ah[2][4], al[2][4], bh[8][2], bl[8][2];
            #pragma unroll
            for (int mt = 0; mt < 2; mt++) {
                uint32_t ad = sbase + aoff + (uint32_t)mt*(16*APITCH*2) + (uint32_t)k16*32u;
                LDSM4(ah[mt][0], ah[mt][1], ah[mt][2], ah[mt][3], ad);
                LDSM4(al[mt][0], al[mt][1], al[mt][2], al[mt][3], ad + OFF_SALO_B);
            }
            #pragma unroll
            for (int jp = 0; jp < 4; jp++) {
                uint32_t bd = sbase + boff + (uint32_t)jp*(16*APITCH*2) + (uint32_t)k16*32u;
                LDSM4(bh[2*jp][0], bh[2*jp][1], bh[2*jp+1][0], bh[2*jp+1][1], bd + OFF_SBHI_B);
                LDSM4(bl[2*jp][0], bl[2*jp][1], bl[2*jp+1][0], bl[2*jp+1][1], bd + OFF_SBLO_B);
            }
            #pragma unroll
            for (int mt = 0; mt < 2; mt++)
                #pragma unroll
                for (int j = 0; j < 8; j++) {
                    MMA_BF16(acc[mt][j], ah[mt], bh[j]);
                    MMA_BF16(acc[mt][j], ah[mt], bl[j]);
                    MMA_BF16(acc[mt][j], al[mt], bh[j]);
                }
        }
        __syncthreads();
    }
    #undef LOAD_STAGE

    // ---- epilogues ----
    const int rbase = m0 + wy*32 + (lane >> 2);
    const int cbase = wx*64 + (lane & 3)*2;   // tile-local, even
    #pragma unroll
    for (int mt = 0; mt < 2; mt++) {
        #pragma unroll
        for (int half = 0; half < 2; half++) {
            const int row = rbase + mt*16 + half*8;
            #pragma unroll
            for (int j = 0; j < 8; j++) {
                const int coll = cbase + j*8;     // local col (even)
                const int col  = n0 + coll;       // global col
                float v0 = acc[mt][j][half*2 + 0];
                float v1 = acc[mt][j][half*2 + 1];
                if (EPI == 0) {
                    if (HAS_BIAS) { v0 += bias[col]; v1 += bias[col + 1]; }
                    if (HAS_RES) {
                        const float2 rv = *(const float2*)(res + (size_t)row * N + col);
                        v0 += rv.x; v1 += rv.y;
                    }
                    float2 o; o.x = v0; o.y = v1;
                    *(float2*)(C + (size_t)row * N + col) = o;
                } else if (EPI == 1) {
                    float y = gelu_exact(v0) * v1;
                    __nv_bfloat16 hh, ll; split_bf16(y, hh, ll);
                    size_t o = (size_t)row * GH + (col >> 1);
                    e0[o] = hh; e1[o] = ll;
                } else {
                    // EPI == 4: merged QKV
                    int t = row & (Tdim - 1);
                    int b = row >> 11;
                    if (col < QH*HD) {
                        // q rotary + scale -> [(b*QH+h)*T + t]*HD + d
                        int d = col & (HD - 1);
                        int hh_ = col >> 7;
                        float inv = expf(-(float)d * ROT_C);
                        float sn, cs; sincosf((float)t * inv, &sn, &cs);
                        float y0 = (v0*cs - v1*sn) * QSCALE;
                        float y1 = (v1*cs + v0*sn) * QSCALE;
                        __nv_bfloat16 h0,l0,h1,l1;
                        split_bf16(y0,h0,l0); split_bf16(y1,h1,l1);
                        size_t o = (((size_t)(b*QH + hh_)) * Tdim + t) * HD + d;
                        *(__nv_bfloat162*)(e0 + o) = __nv_bfloat162(h0,h1);
                        *(__nv_bfloat162*)(e1 + o) = __nv_bfloat162(l0,l1);
                    } else if (col < QH*HD + HD) {
                        // k rotary -> [b*T + t]*HD + d
                        int d = col - QH*HD;
                        float inv = expf(-(float)d * ROT_C);
                        float sn, cs; sincosf((float)t * inv, &sn, &cs);
                        float y0 = v0*cs - v1*sn;
                        float y1 = v1*cs + v0*sn;
                        __nv_bfloat16 h0,l0,h1,l1;
                        split_bf16(y0,h0,l0); split_bf16(y1,h1,l1);
                        size_t o = (size_t)row * HD + d;
                        *(__nv_bfloat162*)(e2 + o) = __nv_bfloat162(h0,h1);
                        *(__nv_bfloat162*)(e3 + o) = __nv_bfloat162(l0,l1);
                    } else {
                        // v transpose -> [(b*HD + d)*T + t]
                        int d = col - QH*HD - HD;
                        __nv_bfloat16 h0,l0,h1,l1;
                        split_bf16(v0,h0,l0); split_bf16(v1,h1,l1);
                        size_t o0 = ((size_t)(b*HD + d)) * Tdim + t;
                        size_t o1 = ((size_t)(b*HD + d + 1)) * Tdim + t;
                        e4[o0] = h0; e5[o0] = l0;
                        e4[o1] = h1; e5[o1] = l1;
                    }
                }
            }
        }
    }
}

// ---------------------------------------------------------------------------
// ONE-SHOT weight conversion (unchanged)
// ---------------------------------------------------------------------------
__device__ __forceinline__ void conv_store(__nv_bfloat16* hi, __nv_bfloat16* lo,
                                           uint32_t dst4, float4 v) {
    __nv_bfloat16 h0, h1, h2, h3, l0, l1, l2, l3;
    split_bf16(v.x, h0, l0); split_bf16(v.y, h1, l1);
    split_bf16(v.z, h2, l2); split_bf16(v.w, h3, l3);
    __nv_bfloat162* hp = (__nv_bfloat162*)hi;
    __nv_bfloat162* lp = (__nv_bfloat162*)lo;
    hp[2*(size_t)dst4]   = __nv_bfloat162(h0, h1);
    hp[2*(size_t)dst4+1] = __nv_bfloat162(h2, h3);
    lp[2*(size_t)dst4]   = __nv_bfloat162(l0, l1);
    lp[2*(size_t)dst4+1] = __nv_bfloat162(l2, l3);
}

__global__ void convw_all_kernel(
    const float* __restrict__ win, const float* __restrict__ wg,
    const float* __restrict__ wout, const float* __restrict__ g1g,
    const float* __restrict__ g1s, const float* __restrict__ g2g,
    const float* __restrict__ g2s, const float* __restrict__ wq,
    const float* __restrict__ wkv, const float* __restrict__ wo2,
    __nv_bfloat16* __restrict__ hi, __nv_bfloat16* __restrict__ lo) {
    uint32_t i = blockIdx.x * blockDim.x + threadIdx.x;
    if (i >= W_TOT) return;
    const float* src;
    uint32_t base, local;
    bool ilv = false;
    if      (i < W_WG)   { src = win;  base = W_WIN;  }
    else if (i < W_WOUT) { src = wg;   base = W_WG;   }
    else if (i < W_G1G)  { src = wout; base = W_WOUT; }
    else if (i < W_G1S)  { src = g1g;  base = W_G1G;  ilv = true; }
    else if (i < W_G2G)  { src = g1s;  base = W_G1S;  }
    else if (i < W_G2S)  { src = g2g;  base = W_G2G;  ilv = true; }
    else if (i < W_Q)    { src = g2s;  base = W_G2S;  }
    else if (i < W_KV)   { src = wq;   base = W_Q;    }
    else if (i < W_O2)   { src = wkv;  base = W_KV;   }
    else                 { src = wo2;  base = W_O2;   }
    local = i - base;
    float4 v = ((const float4*)src)[local];
    uint32_t dlocal = local;
    if (ilv) {
        uint32_t r  = local >> 8;
        uint32_t c4 = local & 255u;
        uint32_t rp = (r < GH) ? (2u*r) : (2u*(r - GH) + 1u);
        dlocal = rp*256u + c4;
    }
    conv_store(hi, lo, base + dlocal, v);
}

// ---------------------------------------------------------------------------
// RMSNorm -> bf16 hi/lo
// ---------------------------------------------------------------------------
__global__ void rmsnorm_bf16_kernel(const float* __restrict__ x,
                                    const float* __restrict__ gamma,
                                    __nv_bfloat16* __restrict__ hi,
                                    __nv_bfloat16* __restrict__ lo) {
    int row = blockIdx.x;
    int tid = threadIdx.x;
    float4 v = ((const float4*)(x + (size_t)row * DIM))[tid];
    float ss = v.x*v.x + v.y*v.y + v.z*v.z + v.w*v.w;
    #pragma unroll
    for (int o = 16; o; o >>= 1) ss += __shfl_xor_sync(0xffffffffu, ss, o);
    __shared__ float red[8];
    __shared__ float stot;
    if ((tid & 31) == 0) red[tid >> 5] = ss;
    __syncthreads();
    if (tid == 0) {
        float s = 0.f;
        #pragma unroll
        for (int i = 0; i < 8; i++) s += red[i];
        stot = s;
    }
    __syncthreads();
    float scale = 32.0f * rsqrtf(stot);
    float4 g = ((const float4*)gamma)[tid];
    float o0 = v.x*scale*g.x, o1 = v.y*scale*g.y, o2 = v.z*scale*g.z, o3 = v.w*scale*g.w;
    __nv_bfloat16 h0,h1,h2,h3,l0,l1,l2,l3;
    split_bf16(o0,h0,l0); split_bf16(o1,h1,l1); split_bf16(o2,h2,l2); split_bf16(o3,h3,l3);
    __nv_bfloat162* hp = (__nv_bfloat162*)(hi + (size_t)row * DIM);
    __nv_bfloat162* lp = (__nv_bfloat162*)(lo + (size_t)row * DIM);
    hp[2*tid]   = __nv_bfloat162(h0,h1);
    hp[2*tid+1] = __nv_bfloat162(h2,h3);
    lp[2*tid]   = __nv_bfloat162(l0,l1);
    lp[2*tid+1] = __nv_bfloat162(l2,l3);
}

// ---------------------------------------------------------------------------
// hawk depthwise causal conv (K=4), sliding-window (unchanged)
// ---------------------------------------------------------------------------
#define TCH 32
__global__ void __launch_bounds__(384)
conv_kernel(const float* __restrict__ gh,
            const float* __restrict__ cw,
            const float* __restrict__ cb,
            float* __restrict__ hconv,
            __nv_bfloat16* __restrict__ hi,
            __nv_bfloat16* __restrict__ lo) {
    __shared__ float scw[HID*KCONV];
    const int tb = blockIdx.x;
    const int b  = blockIdx.y;
    const int c4 = threadIdx.x;
    const int c  = c4 * 4;
    for (int i = threadIdx.x; i < (HID*KCONV)/4; i += 384)
        ((float4*)scw)[i] = ((const float4*)cw)[i];
    __syncthreads();
    float w[4][4];
    #pragma unroll
    for (int i = 0; i < 4; i++)
        #pragma unroll
        for (int k = 0; k < 4; k++) w[i][k] = scw[(c+i)*KCONV + k];
    const float4 bias = ((const float4*)cb)[c4];
    const int t0 = tb * TCH;
    float4 win[4];
    #pragma unroll
    for (int k = 0; k < 3; k++) {
        int tt = t0 - 3 + k;
        win[k] = make_float4(0.f, 0.f, 0.f, 0.f);
        if (tt >= 0)
            win[k] = *(const float4*)(gh + (size_t)(b*Tdim + tt)*(2*HID) + HID + c);
    }
    for (int dt = 0; dt < TCH; dt++) {
        const int t = t0 + dt;
        win[3] = *(const float4*)(gh + (size_t)(b*Tdim + t)*(2*HID) + HID + c);
        float4 acc = bias;
        #pragma unroll
        for (int k = 0; k < 4; k++) {
            acc.x = fmaf(w[0][k], win[k].x, acc.x);
            acc.y = fmaf(w[1][k], win[k].y, acc.y);
            acc.z = fmaf(w[2][k], win[k].z, acc.z);
            acc.w = fmaf(w[3][k], win[k].w, acc.w);
        }
        const size_t bt = (size_t)(b*Tdim + t);
        *(float4*)(hconv + bt * HID + c) = acc;
        __nv_bfloat16 h0,h1,h2,h3,l0,l1,l2,l3;
        split_bf16(acc.x,h0,l0); split_bf16(acc.y,h1,l1);
        split_bf16(acc.z,h2,l2); split_bf16(acc.w,h3,l3);
        __nv_bfloat162* hp = (__nv_bfloat162*)(hi + bt * HID + c);
        __nv_bfloat162* lp = (__nv_bfloat162*)(lo + bt * HID + c);
        hp[0] = __nv_bfloat162(h0,h1);
        hp[1] = __nv_bfloat162(h2,h3);
        lp[0] = __nv_bfloat162(l0,l1);
        lp[1] = __nv_bfloat162(l2,l3);
        win[0] = win[1]; win[1] = win[2]; win[2] = win[3];
    }
}

// ---------------------------------------------------------------------------
// chunked parallel scan (unchanged)
// ---------------------------------------------------------------------------
#define SCH 128
#define NCH 16
__global__ void scanAG_kernel(float* __restrict__ gi,
                              const float* __restrict__ hconv,
                              const float* __restrict__ fb,
                              float* __restrict__ chA, float* __restrict__ chS) {
    int idx = blockIdx.x * blockDim.x + threadIdx.x;
    if (idx >= Bdim * NCH * HID) return;
    int c = idx % HID;
    int r = idx / HID;
    int ch = r & (NCH - 1);
    int b  = r >> 4;
    const float m8sp = -8.0f * log1pf(expf(fb[c]));
    size_t base = ((size_t)b * Tdim + ch * SCH) * (2*HID) + c;
    size_t hb   = ((size_t)b * Tdim + ch * SCH) * HID + c;
    float ap = 1.f, s = 0.f;
    for (int t = 0; t < SCH; t++) {
        size_t o = base + (size_t)t * (2*HID);
        float f  = gi[o];
        float ip = gi[o + HID];
        float h  = hconv[hb + (size_t)t * HID];
        float alpha = expf(m8sp * sigmoidf_(f));
        float beta  = sqrtf(1.0f - alpha*alpha + 1e-6f);
        float xs = beta * sigmoidf_(ip) * h;
        gi[o]       = alpha;
        gi[o + HID] = xs;
        s = fmaf(alpha, s, xs);
        ap *= alpha;
    }
    chA[idx] = ap;
    chS[idx] = s;
}
__global__ void scanB_kernel(const float* __restrict__ chA, const float* __restrict__ chS,
                             float* __restrict__ sIn) {
    int idx = blockIdx.x * blockDim.x + threadIdx.x;
    if (idx >= Bdim * HID) return;
    int c = idx % HID;
    int b = idx / HID;
    float s = 0.f;
    #pragma unroll
    for (int ch = 0; ch < NCH; ch++) {
        size_t o = ((size_t)(b * NCH + ch)) * HID + c;
        sIn[o] = s;
        s = fmaf(chA[o], s, chS[o]);
    }
}
__global__ void scanC_kernel(const float* __restrict__ gi, const float* __restrict__ gh,
                             const float* __restrict__ sIn,
                             __nv_bfloat16* __restrict__ hi, __nv_bfloat16* __restrict__ lo) {
    int idx = blockIdx.x * blockDim.x + threadIdx.x;
    if (idx >= Bdim * NCH * HID) return;
    int c = idx % HID;
    int r = idx / HID;
    int ch = r & (NCH - 1);
    int b  = r >> 4;
    float st = sIn[idx];
    size_t base = ((size_t)b * Tdim + ch * SCH) * (2*HID) + c;
    size_t ob   = ((size_t)b * Tdim + ch * SCH) * HID + c;
    for (int t = 0; t < SCH; t++) {
        size_t o = base + (size_t)t * (2*HID);
        float a = gi[o];
        float x = gi[o + HID];
        float g = gh[o];
        st = fmaf(a, st, x);
        float y = gelu_exact(g) * st;
        __nv_bfloat16 h, l; split_bf16(y, h, l);
        hi[ob + (size_t)t * HID] = h;
        lo[ob + (size_t)t * HID] = l;
    }
}

// ---------------------------------------------------------------------------
// HMMA flash attention (unchanged from R12): bf16x3 QK^T, PV hi-only P
// ---------------------------------------------------------------------------
#define AQ 128
#define AQH_OFF 0u
#define AQL_OFF 34816u
#define AST_OFF 69632u
#define AKH 0u
#define AKL 17408u
#define AVH 34816u
#define AVL 53248u
#define ASTAGE 71680u
#define ATT_SMEM (69632u + 2u*71680u)   // 212992

__global__ void __launch_bounds__(256, 1)
attn_hmma_kernel(const __nv_bfloat16* __restrict__ qhi, const __nv_bfloat16* __restrict__ qlo,
                 const __nv_bfloat16* __restrict__ khi, const __nv_bfloat16* __restrict__ klo,
                 const __nv_bfloat16* __restrict__ vthi, const __nv_bfloat16* __restrict__ vtlo,
                 __nv_bfloat16* __restrict__ ohi, __nv_bfloat16* __restrict__ olo) {
    extern __shared__ char smc[];
    const uint32_t sb = smem_u32(smc);
    const int tid  = threadIdx.x;
    const int lane = tid & 31;
    const int w    = tid >> 5;
    const int b  = blockIdx.z;
    const int h  = blockIdx.y;
    const int q0 = blockIdx.x * AQ;

    {
        const __nv_bfloat16* qh_ = qhi + ((size_t)(b*QH + h) * Tdim + q0) * HD;
        const __nv_bfloat16* ql_ = qlo + ((size_t)(b*QH + h) * Tdim + q0) * HD;
        #pragma unroll
        for (int it = 0; it < 8; it++) {
            int u = tid + it*256;
            int r = u >> 4, c = u & 15;
            uint32_t d = sb + AQH_OFF + (uint32_t)r*272u + (uint32_t)c*16u;
            cp16(d,           qh_ + (size_t)r*HD + c*8);
            cp16(d + AQL_OFF, ql_ + (size_t)r*HD + c*8);
        }
        asm volatile("cp.async.commit_group;");
    }

    const int ks0 = (q0 >= WINSZ) ? (q0 - WINSZ) : 0;
    const int nt  = (q0 + AQ - ks0) >> 6;

    #define LOAD_KV(stg, ks) do { \
        uint32_t sbase_ = sb + AST_OFF + (uint32_t)(stg)*ASTAGE; \
        const __nv_bfloat16* kh_ = khi + ((size_t)b*Tdim + (ks))*HD; \
        const __nv_bfloat16* kl_ = klo + ((size_t)b*Tdim + (ks))*HD; \
        const __nv_bfloat16* vh_ = vthi + (size_t)b*HD*Tdim + (ks); \
        const __nv_bfloat16* vl_ = vtlo + (size_t)b*HD*Tdim + (ks); \
        _Pragma("unroll") \
        for (int it_ = 0; it_ < 4; it_++) { \
            int u_ = tid + it_*256; \
            int r_ = u_ >> 4, c_ = u_ & 15; \
            uint32_t d_ = sbase_ + AKH + (uint32_t)r_*272u + (uint32_t)c_*16u; \
            cp16(d_,             kh_ + (size_t)r_*HD + c_*8); \
            cp16(d_ + (AKL-AKH), kl_ + (size_t)r_*HD + c_*8); \
            int r2_ = u_ >> 3, c2_ = u_ & 7; \
            uint32_t d2_ = sbase_ + AVH + (uint32_t)r2_*144u + (uint32_t)c2_*16u; \
            cp16(d2_,            vh_ + (size_t)r2_*Tdim + c2_*8); \
            cp16(d2_ + (AVL-AVH), vl_ + (size_t)r2_*Tdim + c2_*8); \
        } \
        asm volatile("cp.async.commit_group;"); \
    } while (0)

    LOAD_KV(0, ks0);
    asm volatile("cp.async.wait_group 1;");
    __syncthreads();

    uint32_t qfh[8][4], qfl[8][4];
    {
        const int arow = w*16 + (lane & 15);
        const int acol = (lane >> 4) * 8;
        uint32_t abase = sb + AQH_OFF + (uint32_t)(arow*136 + acol)*2u;
        #pragma unroll
        for (int k = 0; k < 8; k++) {
            LDSM4(qfh[k][0],qfh[k][1],qfh[k][2],qfh[k][3], abase + (uint32_t)k*32u);
            LDSM4(qfl[k][0],qfl[k][1],qfl[k][2],qfl[k][3], abase + AQL_OFF + (uint32_t)k*32u);
        }
    }

    float o_[16][4];
    #pragma unroll
    for (int j = 0; j < 16; j++)
        #pragma unroll
        for (int v = 0; v < 4; v++) o_[j][v] = 0.f;
    float m0 = -1e30f, m1 = -1e30f, l0 = 0.f, l1 = 0.f;

    const int t0 = q0 + w*16 + (lane >> 2);
    const int t1 = t0 + 8;
    const int cb2 = (lane & 3)*2;
    const int gB  = lane >> 3;
    const int rrB = lane & 7;
    const int browB = rrB + ((gB >> 1) << 3);
    const int bcolB = (gB & 1) * 8;

    for (int i = 0; i < nt; i++) {
        const int stg = i & 1;
        if (i + 1 < nt) {
            LOAD_KV(stg ^ 1, ks0 + (i+1)*64);
            asm volatile("cp.async.wait_group 1;");
        } else {
            asm volatile("cp.async.wait_group 0;");
        }
        __syncthreads();
        const uint32_t kb_ = sb + AST_OFF + (uint32_t)stg*ASTAGE;
        const int ks = ks0 + i*64;

        float s_[8][4];
        #pragma unroll
        for (int j = 0; j < 8; j++)
            #pragma unroll
            for (int v = 0; v < 4; v++) s_[j][v] = 0.f;
        #pragma unroll
        for (int jp = 0; jp < 4; jp++) {
            #pragma unroll
            for (int k = 0; k < 8; k++) {
                uint32_t ad = kb_ + AKH + (uint32_t)((browB + jp*16)*136 + bcolB + k*16)*2u;
                uint32_t bh0,bh1,bh2,bh3, bl0,bl1,bl2,bl3;
                LDSM4(bh0,bh1,bh2,bh3, ad);
                LDSM4(bl0,bl1,bl2,bl3, ad + (AKL-AKH));
                uint32_t ba[2] = {bh0,bh1}, bb[2] = {bh2,bh3};
                uint32_t la[2] = {bl0,bl1}, lb[2] = {bl2,bl3};
                MMA_BF16(s_[2*jp],   qfh[k], ba);
                MMA_BF16(s_[2*jp],   qfl[k], ba);
                MMA_BF16(s_[2*jp],   qfh[k], la);
                MMA_BF16(s_[2*jp+1], qfh[k], bb);
                MMA_BF16(s_[2*jp+1], qfl[k], bb);
                MMA_BF16(s_[2*jp+1], qfh[k], lb);
            }
        }

        float mx0 = -1e30f, mx1 = -1e30f;
        #pragma unroll
        for (int jf = 0; jf < 8; jf++) {
            #pragma unroll
            for (int cc = 0; cc < 2; cc++) {
                int g = ks + jf*8 + cb2 + cc;
                if (!(g <= t0 && g >= t0 - WINSZ)) s_[jf][cc]   = -1e30f;
                if (!(g <= t1 && g >= t1 - WINSZ)) s_[jf][2+cc] = -1e30f;
            }
            mx0 = fmaxf(mx0, fmaxf(s_[jf][0], s_[jf][1]));
            mx1 = fmaxf(mx1, fmaxf(s_[jf][2], s_[jf][3]));
        }
        mx0 = fmaxf(mx0, __shfl_xor_sync(0xffffffffu, mx0, 1));
        mx0 = fmaxf(mx0, __shfl_xor_sync(0xffffffffu, mx0, 2));
        mx1 = fmaxf(mx1, __shfl_xor_sync(0xffffffffu, mx1, 1));
        mx1 = fmaxf(mx1, __shfl_xor_sync(0xffffffffu, mx1, 2));
        float m0n = fmaxf(m0, mx0), m1n = fmaxf(m1, mx1);
        float c0 = exp2f((m0 - m0n)*LOG2E), c1 = exp2f((m1 - m1n)*LOG2E);

        float rs0 = 0.f, rs1 = 0.f;
        uint32_t pfh[4][4];
        #pragma unroll
        for (int kf = 0; kf < 4; kf++) {
            #pragma unroll
            for (int jj = 0; jj < 2; jj++) {
                const int jf = 2*kf + jj;
                float p0 = (s_[jf][0] > -1e29f) ? exp2f((s_[jf][0] - m0n)*LOG2E) : 0.f;
                float p1 = (s_[jf][1] > -1e29f) ? exp2f((s_[jf][1] - m0n)*LOG2E) : 0.f;
                float p2 = (s_[jf][2] > -1e29f) ? exp2f((s_[jf][2] - m1n)*LOG2E) : 0.f;
                float p3 = (s_[jf][3] > -1e29f) ? exp2f((s_[jf][3] - m1n)*LOG2E) : 0.f;
                rs0 += p0 + p1;
                rs1 += p2 + p3;
                __nv_bfloat162 hA(__float2bfloat16(p0), __float2bfloat16(p1));
                __nv_bfloat162 hB(__float2bfloat16(p2), __float2bfloat16(p3));
                pfh[kf][0 + 2*jj] = *(uint32_t*)&hA;
                pfh[kf][1 + 2*jj] = *(uint32_t*)&hB;
            }
        }
        rs0 += __shfl_xor_sync(0xffffffffu, rs0, 1);
        rs0 += __shfl_xor_sync(0xffffffffu, rs0, 2);
        rs1 += __shfl_xor_sync(0xffffffffu, rs1, 1);
        rs1 += __shfl_xor_sync(0xffffffffu, rs1, 2);
        l0 = l0*c0 + rs0;
        l1 = l1*c1 + rs1;
        m0 = m0n; m1 = m1n;
        #pragma unroll
        for (int j = 0; j < 16; j++) {
            o_[j][0] *= c0; o_[j][1] *= c0;
            o_[j][2] *= c1; o_[j][3] *= c1;
        }

        // O += P V  (P bf16, V split hi+lo)
        #pragma unroll
        for (int jp = 0; jp < 8; jp++) {
            #pragma unroll
            for (int kf = 0; kf < 4; kf++) {
                uint32_t ad = kb_ + AVH + (uint32_t)((browB + jp*16)*72 + bcolB + kf*16)*2u;
                uint32_t vh0,vh1,vh2,vh3, vl0,vl1,vl2,vl3;
                LDSM4(vh0,vh1,vh2,vh3, ad);
                LDSM4(vl0,vl1,vl2,vl3, ad + (AVL-AVH));
                uint32_t va[2] = {vh0,vh1}, vb[2] = {vh2,vh3};
                uint32_t wa[2] = {vl0,vl1}, wb[2] = {vl2,vl3};
                MMA_BF16(o_[2*jp],   pfh[kf], va);
                MMA_BF16(o_[2*jp],   pfh[kf], wa);
                MMA_BF16(o_[2*jp+1], pfh[kf], vb);
                MMA_BF16(o_[2*jp+1], pfh[kf], wb);
            }
        }
        __syncthreads();
    }
    #undef LOAD_KV

    const float inv0 = 1.0f / l0;
    const float inv1 = 1.0f / l1;
    const size_t ob0 = ((size_t)(b*Tdim) + t0) * (QH*HD) + h*HD;
    const size_t ob1 = ((size_t)(b*Tdim) + t1) * (QH*HD) + h*HD;
    #pragma unroll
    for (int jn = 0; jn < 16; jn++) {
        int d = jn*8 + cb2;
        float y0 = o_[jn][0]*inv0, y1 = o_[jn][1]*inv0;
        float y2 = o_[jn][2]*inv1, y3 = o_[jn][3]*inv1;
        __nv_bfloat16 h0,lo0,h1,lo1,h2,lo2,h3,lo3;
        split_bf16(y0,h0,lo0); split_bf16(y1,h1,lo1);
        split_bf16(y2,h2,lo2); split_bf16(y3,h3,lo3);
        *(__nv_bfloat162*)(ohi + ob0 + d) = __nv_bfloat162(h0,h1);
        *(__nv_bfloat162*)(olo + ob0 + d) = __nv_bfloat162(lo0,lo1);
        *(__nv_bfloat162*)(ohi + ob1 + d) = __nv_bfloat162(h2,h3);
        *(__nv_bfloat162*)(olo + ob1 + d) = __nv_bfloat162(lo2,lo3);
    }
}

// ---------------------------------------------------------------------------
// launch helper (grid passed explicitly)
// ---------------------------------------------------------------------------
#define LAUNCH_G(g, EPI, BIAS, RES, ...) \
    bgemm_kernel<EPI, BIAS, RES><<<(g), 256, GEMM_SMEM_BYTES>>>(__VA_ARGS__)

extern "C" void kernel_launch(void* const* d_in, const int* in_sizes, int n_in,
                              void* d_out, int out_size) {
    const float* x         = (const float*)d_in[0];
    const float* gn_hawk   = (const float*)d_in[1];
    const float* gn_hgmlp  = (const float*)d_in[2];
    const float* gn_smqa   = (const float*)d_in[3];
    const float* gn_sgmlp  = (const float*)d_in[4];
    const float* hawk_Win  = (const float*)d_in[5];
    const float* hawk_cw   = (const float*)d_in[6];
    const float* hawk_cb   = (const float*)d_in[7];
    const float* hawk_Wg   = (const float*)d_in[8];
    const float* hawk_bg   = (const float*)d_in[9];
    const float* hawk_fb   = (const float*)d_in[10];
    const float* hawk_Wout = (const float*)d_in[11];
    const float* g1_Wgrow  = (const float*)d_in[12];
    const float* g1_Wshr   = (const float*)d_in[13];
    const float* g2_Wgrow  = (const float*)d_in[14];
    const float* g2_Wshr   = (const float*)d_in[15];
    const float* smqa_Wq   = (const float*)d_in[16];
    const float* smqa_Wkv  = (const float*)d_in[17];
    const float* smqa_Wout = (const float*)d_in[18];
    float* out = (float*)d_out;

    float *big, *mid, *small, *chA, *chS, *sIn;
    __nv_bfloat16 *Ahi, *Alo, *Whi, *Wlo;
    cudaGetSymbolAddress((void**)&big,   g_big);
    cudaGetSymbolAddress((void**)&mid,   g_mid);
    cudaGetSymbolAddress((void**)&small, g_small);
    cudaGetSymbolAddress((void**)&Ahi,   g_Ahi);
    cudaGetSymbolAddress((void**)&Alo,   g_Alo);
    cudaGetSymbolAddress((void**)&Whi,   g_Whi);
    cudaGetSymbolAddress((void**)&Wlo,   g_Wlo);
    cudaGetSymbolAddress((void**)&chA,   g_chA);
    cudaGetSymbolAddress((void**)&chS,   g_chS);
    cudaGetSymbolAddress((void**)&sIn,   g_sIn);

    cudaFuncSetAttribute((const void*)attn_hmma_kernel,
                         cudaFuncAttributeMaxDynamicSharedMemorySize, (int)ATT_SMEM);
    cudaFuncSetAttribute((const void*)bgemm_kernel<0,false,false>,
                         cudaFuncAttributeMaxDynamicSharedMemorySize, GEMM_SMEM_BYTES);
    cudaFuncSetAttribute((const void*)bgemm_kernel<0,true,false>,
                         cudaFuncAttributeMaxDynamicSharedMemorySize, GEMM_SMEM_BYTES);
    cudaFuncSetAttribute((const void*)bgemm_kernel<0,false,true>,
                         cudaFuncAttributeMaxDynamicSharedMemorySize, GEMM_SMEM_BYTES);
    cudaFuncSetAttribute((const void*)bgemm_kernel<1,false,false>,
                         cudaFuncAttributeMaxDynamicSharedMemorySize, GEMM_SMEM_BYTES);
    cudaFuncSetAttribute((const void*)bgemm_kernel<4,false,false>,
                         cudaFuncAttributeMaxDynamicSharedMemorySize, GEMM_SMEM_BYTES);

    const int EW = 256;
    __nv_bfloat16* nb = nullptr;

    // weight slices
    __nv_bfloat16* WinH  = Whi + (size_t)W_WIN*4;   __nv_bfloat16* WinL  = Wlo + (size_t)W_WIN*4;
    __nv_bfloat16* WgH   = Whi + (size_t)W_WG*4;    __nv_bfloat16* WgL   = Wlo + (size_t)W_WG*4;
    __nv_bfloat16* WoutH = Whi + (size_t)W_WOUT*4;  __nv_bfloat16* WoutL = Wlo + (size_t)W_WOUT*4;
    __nv_bfloat16* G1gH  = Whi + (size_t)W_G1G*4;   __nv_bfloat16* G1gL  = Wlo + (size_t)W_G1G*4;
    __nv_bfloat16* G1sH  = Whi + (size_t)W_G1S*4;   __nv_bfloat16* G1sL  = Wlo + (size_t)W_G1S*4;
    __nv_bfloat16* G2gH  = Whi + (size_t)W_G2G*4;   __nv_bfloat16* G2gL  = Wlo + (size_t)W_G2G*4;
    __nv_bfloat16* G2sH  = Whi + (size_t)W_G2S*4;   __nv_bfloat16* G2sL  = Wlo + (size_t)W_G2S*4;
    __nv_bfloat16* WqH   = Whi + (size_t)W_Q*4;     __nv_bfloat16* WqL   = Wlo + (size_t)W_Q*4;   // Wq+Wkv contiguous
    __nv_bfloat16* Wo2H  = Whi + (size_t)W_O2*4;    __nv_bfloat16* Wo2L  = Wlo + (size_t)W_O2*4;

    // grids (CTN=128, R12 config)
    const dim3 gridWin((2*HID)/CTN, MROWS/CTM);     // 24 x 64
    const dim3 gridDim_(DIM/CTN, MROWS/CTM);        // 8 x 64
    const dim3 gridGrow((2*GH)/CTN, MROWS/CTM);     // 32 x 64
    const dim3 gridQKV((QH*HD + 2*HD)/CTN, MROWS/CTM);  // 10 x 64 (merged)

    // attn bf16 buffers inside g_mid
    __nv_bfloat16* qhi  = (__nv_bfloat16*)mid;
    __nv_bfloat16* qlo  = (__nv_bfloat16*)(mid + 4194304);
    __nv_bfloat16* khi  = (__nv_bfloat16*)(mid + 8388608);
    __nv_bfloat16* klo  = (__nv_bfloat16*)(mid + 8912896);
    __nv_bfloat16* vthi = (__nv_bfloat16*)(mid + 9437184);
    __nv_bfloat16* vtlo = (__nv_bfloat16*)(mid + 9961472);
    __nv_bfloat16* acth = (__nv_bfloat16*)mid;
    __nv_bfloat16* actl = (__nv_bfloat16*)(mid + 8388608);

    // ---------------- one-shot: convert all weights ----------------
    convw_all_kernel<<<(W_TOT + EW - 1)/EW, EW>>>(
        hawk_Win, hawk_Wg, hawk_Wout, g1_Wgrow, g1_Wshr,
        g2_Wgrow, g2_Wshr, smqa_Wq, smqa_Wkv, smqa_Wout, Whi, Wlo);

    // ---------------- stage 1: hawk ----------------
    rmsnorm_bf16_kernel<<<MROWS, 256>>>(x, gn_hawk, Ahi, Alo);
    LAUNCH_G(gridWin, 0,false,false, Ahi,Alo,WinH,WinL, nullptr,nullptr, big, 2*HID, DIM,
             nb,nb,nb,nb,nb,nb);
    conv_kernel<<<dim3(Tdim/TCH, Bdim), 384>>>(big, hawk_cw, hawk_cb, small, Ahi, Alo);
    LAUNCH_G(gridWin, 0,true,false, Ahi,Alo,WgH,WgL, hawk_bg,nullptr, mid, 2*HID, HID,
             nb,nb,nb,nb,nb,nb);
    scanAG_kernel<<<(Bdim*NCH*HID + EW - 1)/EW, EW>>>(mid, small, hawk_fb, chA, chS);
    scanB_kernel<<<(Bdim*HID + EW - 1)/EW, EW>>>(chA, chS, sIn);
    scanC_kernel<<<(Bdim*NCH*HID + EW - 1)/EW, EW>>>(mid, big, sIn, Ahi, Alo);
    LAUNCH_G(gridDim_, 0,false,true, Ahi,Alo,WoutH,WoutL, nullptr,x, out, DIM, HID,
             nb,nb,nb,nb,nb,nb);

    // ---------------- stage 2: gated MLP 1 ----------------
    rmsnorm_bf16_kernel<<<MROWS, 256>>>(out, gn_hgmlp, Ahi, Alo);
    LAUNCH_G(gridGrow, 1,false,false, Ahi,Alo,G1gH,G1gL, nullptr,nullptr, nullptr, 2*GH, DIM,
             acth, actl, nb, nb, nb, nb);
    LAUNCH_G(gridDim_, 0,false,true, acth,actl,G1sH,G1sL, nullptr,out, out, DIM, GH,
             nb,nb,nb,nb,nb,nb);

    // ---------------- stage 3: sliding-window MQA ----------------
    rmsnorm_bf16_kernel<<<MROWS, 256>>>(out, gn_smqa, Ahi, Alo);
    LAUNCH_G(gridQKV, 4,false,false, Ahi,Alo,WqH,WqL, nullptr,nullptr, nullptr, QH*HD + 2*HD, DIM,
             qhi, qlo, khi, klo, vthi, vtlo);
    attn_hmma_kernel<<<dim3(Tdim/AQ, QH, Bdim), 256, ATT_SMEM>>>(
        qhi, qlo, khi, klo, vthi, vtlo, Ahi, Alo);
    LAUNCH_G(gridDim_, 0,false,true, Ahi,Alo,Wo2H,Wo2L, nullptr,out, out, DIM, DIM,
             nb,nb,nb,nb,nb,nb);

    // ---------------- stage 4: gated MLP 2 ----------------
    rmsnorm_bf16_kernel<<<MROWS, 256>>>(out, gn_sgmlp, Ahi, Alo);
    LAUNCH_G(gridGrow, 1,false,false, Ahi,Alo,G2gH,G2gL, nullptr,nullptr, nullptr, 2*GH, DIM,
             acth, actl, nb, nb, nb, nb);
    LAUNCH_G(gridDim_, 0,false,true, acth,actl,G2sH,G2sL, nullptr,out, out, DIM, GH,
             nb,nb,nb,nb,nb,nb);
}

// round 15
// speedup vs baseline: 1.1034x; 1.0111x over previous
#include <cuda_runtime.h>
#include <cuda_bf16.h>
#include <math.h>
#include <stdint.h>

// ---------------------------------------------------------------------------
// GriffinBlock: HMMA bf16x3 GEMMs (R12 config) + HMMA flash attn
// hconv fp32 buffer eliminated (scanAG reconstructs from bf16 hi/lo)
// B=4, T=2048, DIM=1024, HID=1536, GH=2048, K=4, HD=128, QH=8, W=1024
// ---------------------------------------------------------------------------

#define Bdim 4
#define Tdim 2048
#define DIM 1024
#define HID 1536
#define GH  2048
#define KCONV 4
#define HD  128
#define QH  8
#define WINSZ 1024
#define MROWS (Bdim*Tdim)   // 8192
#define LOG2E 1.4426950408889634f
#define QSCALE 0.088388347648318447f
#define ROT_C (9.210340371976184f / 128.0f)

// ---------------- static scratch ----------------
__device__ float g_big[33554432];      // 8192*4096
__device__ float g_mid[25165824];      // 8192*3072 (hawk gi; act/attn bf16 scratch)
__device__ float g_small[12582912];    // 8192*1536 (unused by hawk now; spare)
__device__ __nv_bfloat16 g_Ahi[16777216];  // 8192*2048 max
__device__ __nv_bfloat16 g_Alo[16777216];
__device__ __nv_bfloat16 g_Whi[24379392];  // all weights, bf16 hi
__device__ __nv_bfloat16 g_Wlo[24379392];  // all weights, bf16 lo
__device__ float g_chA[98304];
__device__ float g_chS[98304];
__device__ float g_sIn[98304];

// weight slice offsets in float4 units (x4 for elements)
#define W_WIN  0u
#define W_WG   786432u
#define W_WOUT 1966080u
#define W_G1G  2359296u
#define W_G1S  3407872u
#define W_G2G  3932160u
#define W_G2S  4980736u
#define W_Q    5505024u
#define W_KV   5767168u
#define W_O2   5832704u
#define W_TOT  6094848u

__device__ __forceinline__ float gelu_exact(float x) {
    return 0.5f * x * (1.0f + erff(x * 0.70710678118654752f));
}
__device__ __forceinline__ float sigmoidf_(float x) {
    return 1.0f / (1.0f + expf(-x));
}
__device__ __forceinline__ void split_bf16(float v, __nv_bfloat16& h, __nv_bfloat16& l) {
    h = __float2bfloat16(v);
    l = __float2bfloat16(v - __bfloat162float(h));
}

__device__ __forceinline__ uint32_t smem_u32(const void* p) {
    uint32_t a;
    asm("{ .reg .u64 t; cvta.to.shared.u64 t, %1; cvt.u32.u64 %0, t; }" : "=r"(a) : "l"(p));
    return a;
}
__device__ __forceinline__ void cp16(uint32_t dst, const void* src) {
    asm volatile("cp.async.ca.shared.global [%0], [%1], 16;" :: "r"(dst), "l"(src));
}

#define LDSM4(r0, r1, r2, r3, addr) \
    asm volatile("ldmatrix.sync.aligned.m8n8.x4.shared.b16 {%0,%1,%2,%3}, [%4];" \
        : "=r"(r0), "=r"(r1), "=r"(r2), "=r"(r3) : "r"(addr))

#define MMA_BF16(d, a, b) \
    asm volatile("mma.sync.aligned.m16n8k16.row.col.f32.bf16.bf16.f32 " \
        "{%0,%1,%2,%3}, {%4,%5,%6,%7}, {%8,%9}, {%0,%1,%2,%3};" \
        : "+f"((d)[0]), "+f"((d)[1]), "+f"((d)[2]), "+f"((d)[3]) \
        : "r"((a)[0]), "r"((a)[1]), "r"((a)[2]), "r"((a)[3]), \
          "r"((b)[0]), "r"((b)[1]))

// ---------------------------------------------------------------------------
// bf16x3 HMMA GEMM (R12 EXACT): CTA 128x128, warp 32x64, CTK=64, 2-stage.
// EPI: 0 = plain fp32 C (+bias/res), 1 = gelu-gate pair -> bf16 hi/lo,
//      2 = q rotary+scale -> bf16, 3 = kv rotary / v-transpose -> bf16
// ---------------------------------------------------------------------------
#define CTM 128
#define CTN 128
#define CTK 64
#define APITCH 72
#define OFF_SALO_B 18432u
#define OFF_SBHI_B 36864u
#define OFF_SBLO_B 55296u
#define STAGE_BYTES 73728u
#define GEMM_SMEM_BYTES (2u*STAGE_BYTES)  // 147456

template<int EPI, bool HAS_BIAS, bool HAS_RES>
__global__ void __launch_bounds__(256, 1)
bgemm_kernel(const __nv_bfloat16* __restrict__ Ahi, const __nv_bfloat16* __restrict__ Alo,
             const __nv_bfloat16* __restrict__ Whi, const __nv_bfloat16* __restrict__ Wlo,
             const float* __restrict__ bias, const float* __restrict__ res,
             float* __restrict__ C, int N, int K,
             __nv_bfloat16* __restrict__ e0, __nv_bfloat16* __restrict__ e1,
             __nv_bfloat16* __restrict__ e2, __nv_bfloat16* __restrict__ e3) {
    extern __shared__ char smc[];
    const uint32_t sb = smem_u32(smc);
    const int tid = threadIdx.x;
    const int lane = tid & 31;
    const int wid = tid >> 5;
    const int wy = wid & 3;
    const int wx = wid >> 2;
    const int m0 = blockIdx.y * CTM;
    const int n0 = blockIdx.x * CTN;

    const int arow = wy*32 + (lane & 15);
    const int acol = (lane >> 4) * 8;
    const uint32_t aoff = (uint32_t)(arow*APITCH + acol) * 2u;
    const int g  = lane >> 3;
    const int rr = lane & 7;
    const int brow = wx*64 + rr + ((g >> 1) << 3);
    const int bcol = (g & 1) * 8;
    const uint32_t boff = (uint32_t)(brow*APITCH + bcol) * 2u;

    float acc[2][8][4];
    #pragma unroll
    for (int i = 0; i < 2; i++)
        #pragma unroll
        for (int j = 0; j < 8; j++)
            #pragma unroll
            for (int v = 0; v < 4; v++) acc[i][j][v] = 0.f;

    const int NC = K / CTK;

    #define LOAD_STAGE(stg, kb) do { \
        uint32_t sbase_ = sb + (stg)*STAGE_BYTES; \
        _Pragma("unroll") \
        for (int it_ = 0; it_ < 4; it_++) { \
            int u_ = tid + it_*256; \
            int r_ = u_ >> 3; \
            int c_ = u_ & 7; \
            uint32_t d_ = sbase_ + (uint32_t)r_*144u + (uint32_t)c_*16u; \
            size_t ga_ = (size_t)(m0 + r_) * K + (kb) + c_*8; \
            size_t gb_ = (size_t)(n0 + r_) * K + (kb) + c_*8; \
            cp16(d_,              Ahi + ga_); \
            cp16(d_ + OFF_SALO_B, Alo + ga_); \
            cp16(d_ + OFF_SBHI_B, Whi + gb_); \
            cp16(d_ + OFF_SBLO_B, Wlo + gb_); \
        } \
        asm volatile("cp.async.commit_group;"); \
    } while (0)

    LOAD_STAGE(0, 0);

    for (int ch = 0; ch < NC; ch++) {
        const int stg = ch & 1;
        if (ch + 1 < NC) {
            LOAD_STAGE(stg ^ 1, (ch + 1) * CTK);
            asm volatile("cp.async.wait_group 1;");
        } else {
            asm volatile("cp.async.wait_group 0;");
        }
        __syncthreads();

        const uint32_t sbase = sb + stg * STAGE_BYTES;
        #pragma unroll
        for (int k16 = 0; k16 < 4; k16++) {
            uint32_t ah[2][4], al[2][4], bh[8][2], bl[8][2];
            #pragma unroll
            for (int mt = 0; mt < 2; mt++) {
                uint32_t ad = sbase + aoff + (uint32_t)mt*(16*APITCH*2) + (uint32_t)k16*32u;
                LDSM4(ah[mt][0], ah[mt][1], ah[mt][2], ah[mt][3], ad);
                LDSM4(al[mt][0], al[mt][1], al[mt][2], al[mt][3], ad + OFF_SALO_B);
            }
            #pragma unroll
            for (int jp = 0; jp < 4; jp++) {
                uint32_t bd = sbase + boff + (uint32_t)jp*(16*APITCH*2) + (uint32_t)k16*32u;
                LDSM4(bh[2*jp][0], bh[2*jp][1], bh[2*jp+1][0], bh[2*jp+1][1], bd + OFF_SBHI_B);
                LDSM4(bl[2*jp][0], bl[2*jp][1], bl[2*jp+1][0], bl[2*jp+1][1], bd + OFF_SBLO_B);
            }
            #pragma unroll
            for (int mt = 0; mt < 2; mt++)
                #pragma unroll
                for (int j = 0; j < 8; j++) {
                    MMA_BF16(acc[mt][j], ah[mt], bh[j]);
                    MMA_BF16(acc[mt][j], ah[mt], bl[j]);
                    MMA_BF16(acc[mt][j], al[mt], bh[j]);
                }
        }
        __syncthreads();
    }
    #undef LOAD_STAGE

    // ---- epilogues ----
    const int rbase = m0 + wy*32 + (lane >> 2);
    const int cbase = wx*64 + (lane & 3)*2;   // tile-local, even
    #pragma unroll
    for (int mt = 0; mt < 2; mt++) {
        #pragma unroll
        for (int half = 0; half < 2; half++) {
            const int row = rbase + mt*16 + half*8;
            #pragma unroll
            for (int j = 0; j < 8; j++) {
                const int coll = cbase + j*8;     // local col (even)
                const int col  = n0 + coll;       // global col
                float v0 = acc[mt][j][half*2 + 0];
                float v1 = acc[mt][j][half*2 + 1];
                if (EPI == 0) {
                    if (HAS_BIAS) { v0 += bias[col]; v1 += bias[col + 1]; }
                    if (HAS_RES) {
                        const float2 rv = *(const float2*)(res + (size_t)row * N + col);
                        v0 += rv.x; v1 += rv.y;
                    }
                    float2 o; o.x = v0; o.y = v1;
                    *(float2*)(C + (size_t)row * N + col) = o;
                } else if (EPI == 1) {
                    float y = gelu_exact(v0) * v1;
                    __nv_bfloat16 hh, ll; split_bf16(y, hh, ll);
                    size_t o = (size_t)row * GH + (col >> 1);
                    e0[o] = hh; e1[o] = ll;
                } else if (EPI == 2) {
                    int d = col & (HD - 1);
                    int hh_ = col >> 7;
                    int t = row & (Tdim - 1);
                    int b = row >> 11;
                    float inv = expf(-(float)d * ROT_C);
                    float sn, cs; sincosf((float)t * inv, &sn, &cs);
                    float y0 = (v0*cs - v1*sn) * QSCALE;
                    float y1 = (v1*cs + v0*sn) * QSCALE;
                    __nv_bfloat16 h0,l0,h1,l1;
                    split_bf16(y0,h0,l0); split_bf16(y1,h1,l1);
                    size_t o = (((size_t)(b*QH + hh_)) * Tdim + t) * HD + d;
                    *(__nv_bfloat162*)(e0 + o) = __nv_bfloat162(h0,h1);
                    *(__nv_bfloat162*)(e1 + o) = __nv_bfloat162(l0,l1);
                } else {
                    int t = row & (Tdim - 1);
                    int b = row >> 11;
                    if (col < HD) {
                        int d = col;
                        float inv = expf(-(float)d * ROT_C);
                        float sn, cs; sincosf((float)t * inv, &sn, &cs);
                        float y0 = v0*cs - v1*sn;
                        float y1 = v1*cs + v0*sn;
                        __nv_bfloat16 h0,l0,h1,l1;
                        split_bf16(y0,h0,l0); split_bf16(y1,h1,l1);
                        size_t o = (size_t)row * HD + d;
                        *(__nv_bfloat162*)(e0 + o) = __nv_bfloat162(h0,h1);
                        *(__nv_bfloat162*)(e1 + o) = __nv_bfloat162(l0,l1);
                    } else {
                        int d = col - HD;
                        __nv_bfloat16 h0,l0,h1,l1;
                        split_bf16(v0,h0,l0); split_bf16(v1,h1,l1);
                        size_t o0 = ((size_t)(b*HD + d)) * Tdim + t;
                        size_t o1 = ((size_t)(b*HD + d + 1)) * Tdim + t;
                        e2[o0] = h0; e3[o0] = l0;
                        e2[o1] = h1; e3[o1] = l1;
                    }
                }
            }
        }
    }
}

// ---------------------------------------------------------------------------
// ONE-SHOT weight conversion (unchanged)
// ---------------------------------------------------------------------------
__device__ __forceinline__ void conv_store(__nv_bfloat16* hi, __nv_bfloat16* lo,
                                           uint32_t dst4, float4 v) {
    __nv_bfloat16 h0, h1, h2, h3, l0, l1, l2, l3;
    split_bf16(v.x, h0, l0); split_bf16(v.y, h1, l1);
    split_bf16(v.z, h2, l2); split_bf16(v.w, h3, l3);
    __nv_bfloat162* hp = (__nv_bfloat162*)hi;
    __nv_bfloat162* lp = (__nv_bfloat162*)lo;
    hp[2*(size_t)dst4]   = __nv_bfloat162(h0, h1);
    hp[2*(size_t)dst4+1] = __nv_bfloat162(h2, h3);
    lp[2*(size_t)dst4]   = __nv_bfloat162(l0, l1);
    lp[2*(size_t)dst4+1] = __nv_bfloat162(l2, l3);
}

__global__ void convw_all_kernel(
    const float* __restrict__ win, const float* __restrict__ wg,
    const float* __restrict__ wout, const float* __restrict__ g1g,
    const float* __restrict__ g1s, const float* __restrict__ g2g,
    const float* __restrict__ g2s, const float* __restrict__ wq,
    const float* __restrict__ wkv, const float* __restrict__ wo2,
    __nv_bfloat16* __restrict__ hi, __nv_bfloat16* __restrict__ lo) {
    uint32_t i = blockIdx.x * blockDim.x + threadIdx.x;
    if (i >= W_TOT) return;
    const float* src;
    uint32_t base, local;
    bool ilv = false;
    if      (i < W_WG)   { src = win;  base = W_WIN;  }
    else if (i < W_WOUT) { src = wg;   base = W_WG;   }
    else if (i < W_G1G)  { src = wout; base = W_WOUT; }
    else if (i < W_G1S)  { src = g1g;  base = W_G1G;  ilv = true; }
    else if (i < W_G2G)  { src = g1s;  base = W_G1S;  }
    else if (i < W_G2S)  { src = g2g;  base = W_G2G;  ilv = true; }
    else if (i < W_Q)    { src = g2s;  base = W_G2S;  }
    else if (i < W_KV)   { src = wq;   base = W_Q;    }
    else if (i < W_O2)   { src = wkv;  base = W_KV;   }
    else                 { src = wo2;  base = W_O2;   }
    local = i - base;
    float4 v = ((const float4*)src)[local];
    uint32_t dlocal = local;
    if (ilv) {
        uint32_t r  = local >> 8;
        uint32_t c4 = local & 255u;
        uint32_t rp = (r < GH) ? (2u*r) : (2u*(r - GH) + 1u);
        dlocal = rp*256u + c4;
    }
    conv_store(hi, lo, base + dlocal, v);
}

// ---------------------------------------------------------------------------
// RMSNorm -> bf16 hi/lo
// ---------------------------------------------------------------------------
__global__ void rmsnorm_bf16_kernel(const float* __restrict__ x,
                                    const float* __restrict__ gamma,
                                    __nv_bfloat16* __restrict__ hi,
                                    __nv_bfloat16* __restrict__ lo) {
    int row = blockIdx.x;
    int tid = threadIdx.x;
    float4 v = ((const float4*)(x + (size_t)row * DIM))[tid];
    float ss = v.x*v.x + v.y*v.y + v.z*v.z + v.w*v.w;
    #pragma unroll
    for (int o = 16; o; o >>= 1) ss += __shfl_xor_sync(0xffffffffu, ss, o);
    __shared__ float red[8];
    __shared__ float stot;
    if ((tid & 31) == 0) red[tid >> 5] = ss;
    __syncthreads();
    if (tid == 0) {
        float s = 0.f;
        #pragma unroll
        for (int i = 0; i < 8; i++) s += red[i];
        stot = s;
    }
    __syncthreads();
    float scale = 32.0f * rsqrtf(stot);
    float4 g = ((const float4*)gamma)[tid];
    float o0 = v.x*scale*g.x, o1 = v.y*scale*g.y, o2 = v.z*scale*g.z, o3 = v.w*scale*g.w;
    __nv_bfloat16 h0,h1,h2,h3,l0,l1,l2,l3;
    split_bf16(o0,h0,l0); split_bf16(o1,h1,l1); split_bf16(o2,h2,l2); split_bf16(o3,h3,l3);
    __nv_bfloat162* hp = (__nv_bfloat162*)(hi + (size_t)row * DIM);
    __nv_bfloat162* lp = (__nv_bfloat162*)(lo + (size_t)row * DIM);
    hp[2*tid]   = __nv_bfloat162(h0,h1);
    hp[2*tid+1] = __nv_bfloat162(h2,h3);
    lp[2*tid]   = __nv_bfloat162(l0,l1);
    lp[2*tid+1] = __nv_bfloat162(l2,l3);
}

// ---------------------------------------------------------------------------
// hawk depthwise causal conv (K=4), sliding-window; bf16 hi/lo output ONLY
// ---------------------------------------------------------------------------
#define TCH 32
__global__ void __launch_bounds__(384)
conv_kernel(const float* __restrict__ gh,
            const float* __restrict__ cw,
            const float* __restrict__ cb,
            __nv_bfloat16* __restrict__ hi,
            __nv_bfloat16* __restrict__ lo) {
    __shared__ float scw[HID*KCONV];
    const int tb = blockIdx.x;
    const int b  = blockIdx.y;
    const int c4 = threadIdx.x;
    const int c  = c4 * 4;
    for (int i = threadIdx.x; i < (HID*KCONV)/4; i += 384)
        ((float4*)scw)[i] = ((const float4*)cw)[i];
    __syncthreads();
    float w[4][4];
    #pragma unroll
    for (int i = 0; i < 4; i++)
        #pragma unroll
        for (int k = 0; k < 4; k++) w[i][k] = scw[(c+i)*KCONV + k];
    const float4 bias = ((const float4*)cb)[c4];
    const int t0 = tb * TCH;
    float4 win[4];
    #pragma unroll
    for (int k = 0; k < 3; k++) {
        int tt = t0 - 3 + k;
        win[k] = make_float4(0.f, 0.f, 0.f, 0.f);
        if (tt >= 0)
            win[k] = *(const float4*)(gh + (size_t)(b*Tdim + tt)*(2*HID) + HID + c);
    }
    for (int dt = 0; dt < TCH; dt++) {
        const int t = t0 + dt;
        win[3] = *(const float4*)(gh + (size_t)(b*Tdim + t)*(2*HID) + HID + c);
        float4 acc = bias;
        #pragma unroll
        for (int k = 0; k < 4; k++) {
            acc.x = fmaf(w[0][k], win[k].x, acc.x);
            acc.y = fmaf(w[1][k], win[k].y, acc.y);
            acc.z = fmaf(w[2][k], win[k].z, acc.z);
            acc.w = fmaf(w[3][k], win[k].w, acc.w);
        }
        const size_t bt = (size_t)(b*Tdim + t);
        __nv_bfloat16 h0,h1,h2,h3,l0,l1,l2,l3;
        split_bf16(acc.x,h0,l0); split_bf16(acc.y,h1,l1);
        split_bf16(acc.z,h2,l2); split_bf16(acc.w,h3,l3);
        __nv_bfloat162* hp = (__nv_bfloat162*)(hi + bt * HID + c);
        __nv_bfloat162* lp = (__nv_bfloat162*)(lo + bt * HID + c);
        hp[0] = __nv_bfloat162(h0,h1);
        hp[1] = __nv_bfloat162(h2,h3);
        lp[0] = __nv_bfloat162(l0,l1);
        lp[1] = __nv_bfloat162(l2,l3);
        win[0] = win[1]; win[1] = win[2]; win[2] = win[3];
    }
}

// ---------------------------------------------------------------------------
// chunked parallel scan; gates fused into phase A. h reconstructed from
// bf16 hi/lo (hconv fp32 buffer eliminated).
// ---------------------------------------------------------------------------
#define SCH 128
#define NCH 16
__global__ void scanAG_kernel(float* __restrict__ gi,
                              const __nv_bfloat16* __restrict__ hhi,
                              const __nv_bfloat16* __restrict__ hlo,
                              const float* __restrict__ fb,
                              float* __restrict__ chA, float* __restrict__ chS) {
    int idx = blockIdx.x * blockDim.x + threadIdx.x;
    if (idx >= Bdim * NCH * HID) return;
    int c = idx % HID;
    int r = idx / HID;
    int ch = r & (NCH - 1);
    int b  = r >> 4;
    const float m8sp = -8.0f * log1pf(expf(fb[c]));
    size_t base = ((size_t)b * Tdim + ch * SCH) * (2*HID) + c;
    size_t hb   = ((size_t)b * Tdim + ch * SCH) * HID + c;
    float ap = 1.f, s = 0.f;
    for (int t = 0; t < SCH; t++) {
        size_t o = base + (size_t)t * (2*HID);
        float f  = gi[o];
        float ip = gi[o + HID];
        size_t ho = hb + (size_t)t * HID;
        float h  = __bfloat162float(hhi[ho]) + __bfloat162float(hlo[ho]);
        float alpha = expf(m8sp * sigmoidf_(f));
        float beta  = sqrtf(1.0f - alpha*alpha + 1e-6f);
        float xs = beta * sigmoidf_(ip) * h;
        gi[o]       = alpha;
        gi[o + HID] = xs;
        s = fmaf(alpha, s, xs);
        ap *= alpha;
    }
    chA[idx] = ap;
    chS[idx] = s;
}
__global__ void scanB_kernel(const float* __restrict__ chA, const float* __restrict__ chS,
                             float* __restrict__ sIn) {
    int idx = blockIdx.x * blockDim.x + threadIdx.x;
    if (idx >= Bdim * HID) return;
    int c = idx % HID;
    int b = idx / HID;
    float s = 0.f;
    #pragma unroll
    for (int ch = 0; ch < NCH; ch++) {
        size_t o = ((size_t)(b * NCH + ch)) * HID + c;
        sIn[o] = s;
        s = fmaf(chA[o], s, chS[o]);
    }
}
__global__ void scanC_kernel(const float* __restrict__ gi, const float* __restrict__ gh,
                             const float* __restrict__ sIn,
                             __nv_bfloat16* __restrict__ hi, __nv_bfloat16* __restrict__ lo) {
    int idx = blockIdx.x * blockDim.x + threadIdx.x;
    if (idx >= Bdim * NCH * HID) return;
    int c = idx % HID;
    int r = idx / HID;
    int ch = r & (NCH - 1);
    int b  = r >> 4;
    float st = sIn[idx];
    size_t base = ((size_t)b * Tdim + ch * SCH) * (2*HID) + c;
    size_t ob   = ((size_t)b * Tdim + ch * SCH) * HID + c;
    for (int t = 0; t < SCH; t++) {
        size_t o = base + (size_t)t * (2*HID);
        float a = gi[o];
        float x = gi[o + HID];
        float g = gh[o];
        st = fmaf(a, st, x);
        float y = gelu_exact(g) * st;
        __nv_bfloat16 h, l; split_bf16(y, h, l);
        hi[ob + (size_t)t * HID] = h;
        lo[ob + (size_t)t * HID] = l;
    }
}

// ---------------------------------------------------------------------------
// HMMA flash attention (unchanged from R12): bf16x3 QK^T, PV hi-only P
// ---------------------------------------------------------------------------
#define AQ 128
#define AQH_OFF 0u
#define AQL_OFF 34816u
#define AST_OFF 69632u
#define AKH 0u
#define AKL 17408u
#define AVH 34816u
#define AVL 53248u
#define ASTAGE 71680u
#define ATT_SMEM (69632u + 2u*71680u)   // 212992

__global__ void __launch_bounds__(256, 1)
attn_hmma_kernel(const __nv_bfloat16* __restrict__ qhi, const __nv_bfloat16* __restrict__ qlo,
                 const __nv_bfloat16* __restrict__ khi, const __nv_bfloat16* __restrict__ klo,
                 const __nv_bfloat16* __restrict__ vthi, const __nv_bfloat16* __restrict__ vtlo,
                 __nv_bfloat16* __restrict__ ohi, __nv_bfloat16* __restrict__ olo) {
    extern __shared__ char smc[];
    const uint32_t sb = smem_u32(smc);
    const int tid  = threadIdx.x;
    const int lane = tid & 31;
    const int w    = tid >> 5;
    const int b  = blockIdx.z;
    const int h  = blockIdx.y;
    const int q0 = blockIdx.x * AQ;

    {
        const __nv_bfloat16* qh_ = qhi + ((size_t)(b*QH + h) * Tdim + q0) * HD;
        const __nv_bfloat16* ql_ = qlo + ((size_t)(b*QH + h) * Tdim + q0) * HD;
        #pragma unroll
        for (int it = 0; it < 8; it++) {
            int u = tid + it*256;
            int r = u >> 4, c = u & 15;
            uint32_t d = sb + AQH_OFF + (uint32_t)r*272u + (uint32_t)c*16u;
            cp16(d,           qh_ + (size_t)r*HD + c*8);
            cp16(d + AQL_OFF, ql_ + (size_t)r*HD + c*8);
        }
        asm volatile("cp.async.commit_group;");
    }

    const int ks0 = (q0 >= WINSZ) ? (q0 - WINSZ) : 0;
    const int nt  = (q0 + AQ - ks0) >> 6;

    #define LOAD_KV(stg, ks) do { \
        uint32_t sbase_ = sb + AST_OFF + (uint32_t)(stg)*ASTAGE; \
        const __nv_bfloat16* kh_ = khi + ((size_t)b*Tdim + (ks))*HD; \
        const __nv_bfloat16* kl_ = klo + ((size_t)b*Tdim + (ks))*HD; \
        const __nv_bfloat16* vh_ = vthi + (size_t)b*HD*Tdim + (ks); \
        const __nv_bfloat16* vl_ = vtlo + (size_t)b*HD*Tdim + (ks); \
        _Pragma("unroll") \
        for (int it_ = 0; it_ < 4; it_++) { \
            int u_ = tid + it_*256; \
            int r_ = u_ >> 4, c_ = u_ & 15; \
            uint32_t d_ = sbase_ + AKH + (uint32_t)r_*272u + (uint32_t)c_*16u; \
            cp16(d_,             kh_ + (size_t)r_*HD + c_*8); \
            cp16(d_ + (AKL-AKH), kl_ + (size_t)r_*HD + c_*8); \
            int r2_ = u_ >> 3, c2_ = u_ & 7; \
            uint32_t d2_ = sbase_ + AVH + (uint32_t)r2_*144u + (uint32_t)c2_*16u; \
            cp16(d2_,            vh_ + (size_t)r2_*Tdim + c2_*8); \
            cp16(d2_ + (AVL-AVH), vl_ + (size_t)r2_*Tdim + c2_*8); \
        } \
        asm volatile("cp.async.commit_group;"); \
    } while (0)

    LOAD_KV(0, ks0);
    asm volatile("cp.async.wait_group 1;");
    __syncthreads();

    uint32_t qfh[8][4], qfl[8][4];
    {
        const int arow = w*16 + (lane & 15);
        const int acol = (lane >> 4) * 8;
        uint32_t abase = sb + AQH_OFF + (uint32_t)(arow*136 + acol)*2u;
        #pragma unroll
        for (int k = 0; k < 8; k++) {
            LDSM4(qfh[k][0],qfh[k][1],qfh[k][2],qfh[k][3], abase + (uint32_t)k*32u);
            LDSM4(qfl[k][0],qfl[k][1],qfl[k][2],qfl[k][3], abase + AQL_OFF + (uint32_t)k*32u);
        }
    }

    float o_[16][4];
    #pragma unroll
    for (int j = 0; j < 16; j++)
        #pragma unroll
        for (int v = 0; v < 4; v++) o_[j][v] = 0.f;
    float m0 = -1e30f, m1 = -1e30f, l0 = 0.f, l1 = 0.f;

    const int t0 = q0 + w*16 + (lane >> 2);
    const int t1 = t0 + 8;
    const int cb2 = (lane & 3)*2;
    const int gB  = lane >> 3;
    const int rrB = lane & 7;
    const int browB = rrB + ((gB >> 1) << 3);
    const int bcolB = (gB & 1) * 8;

    for (int i = 0; i < nt; i++) {
        const int stg = i & 1;
        if (i + 1 < nt) {
            LOAD_KV(stg ^ 1, ks0 + (i+1)*64);
            asm volatile("cp.async.wait_group 1;");
        } else {
            asm volatile("cp.async.wait_group 0;");
        }
        __syncthreads();
        const uint32_t kb_ = sb + AST_OFF + (uint32_t)stg*ASTAGE;
        const int ks = ks0 + i*64;

        float s_[8][4];
        #pragma unroll
        for (int j = 0; j < 8; j++)
            #pragma unroll
            for (int v = 0; v < 4; v++) s_[j][v] = 0.f;
        #pragma unroll
        for (int jp = 0; jp < 4; jp++) {
            #pragma unroll
            for (int k = 0; k < 8; k++) {
                uint32_t ad = kb_ + AKH + (uint32_t)((browB + jp*16)*136 + bcolB + k*16)*2u;
                uint32_t bh0,bh1,bh2,bh3, bl0,bl1,bl2,bl3;
                LDSM4(bh0,bh1,bh2,bh3, ad);
                LDSM4(bl0,bl1,bl2,bl3, ad + (AKL-AKH));
                uint32_t ba[2] = {bh0,bh1}, bb[2] = {bh2,bh3};
                uint32_t la[2] = {bl0,bl1}, lb[2] = {bl2,bl3};
                MMA_BF16(s_[2*jp],   qfh[k], ba);
                MMA_BF16(s_[2*jp],   qfl[k], ba);
                MMA_BF16(s_[2*jp],   qfh[k], la);
                MMA_BF16(s_[2*jp+1], qfh[k], bb);
                MMA_BF16(s_[2*jp+1], qfl[k], bb);
                MMA_BF16(s_[2*jp+1], qfh[k], lb);
            }
        }

        float mx0 = -1e30f, mx1 = -1e30f;
        #pragma unroll
        for (int jf = 0; jf < 8; jf++) {
            #pragma unroll
            for (int cc = 0; cc < 2; cc++) {
                int g = ks + jf*8 + cb2 + cc;
                if (!(g <= t0 && g >= t0 - WINSZ)) s_[jf][cc]   = -1e30f;
                if (!(g <= t1 && g >= t1 - WINSZ)) s_[jf][2+cc] = -1e30f;
            }
            mx0 = fmaxf(mx0, fmaxf(s_[jf][0], s_[jf][1]));
            mx1 = fmaxf(mx1, fmaxf(s_[jf][2], s_[jf][3]));
        }
        mx0 = fmaxf(mx0, __shfl_xor_sync(0xffffffffu, mx0, 1));
        mx0 = fmaxf(mx0, __shfl_xor_sync(0xffffffffu, mx0, 2));
        mx1 = fmaxf(mx1, __shfl_xor_sync(0xffffffffu, mx1, 1));
        mx1 = fmaxf(mx1, __shfl_xor_sync(0xffffffffu, mx1, 2));
        float m0n = fmaxf(m0, mx0), m1n = fmaxf(m1, mx1);
        float c0 = exp2f((m0 - m0n)*LOG2E), c1 = exp2f((m1 - m1n)*LOG2E);

        float rs0 = 0.f, rs1 = 0.f;
        uint32_t pfh[4][4];
        #pragma unroll
        for (int kf = 0; kf < 4; kf++) {
            #pragma unroll
            for (int jj = 0; jj < 2; jj++) {
                const int jf = 2*kf + jj;
                float p0 = (s_[jf][0] > -1e29f) ? exp2f((s_[jf][0] - m0n)*LOG2E) : 0.f;
                float p1 = (s_[jf][1] > -1e29f) ? exp2f((s_[jf][1] - m0n)*LOG2E) : 0.f;
                float p2 = (s_[jf][2] > -1e29f) ? exp2f((s_[jf][2] - m1n)*LOG2E) : 0.f;
                float p3 = (s_[jf][3] > -1e29f) ? exp2f((s_[jf][3] - m1n)*LOG2E) : 0.f;
                rs0 += p0 + p1;
                rs1 += p2 + p3;
                __nv_bfloat162 hA(__float2bfloat16(p0), __float2bfloat16(p1));
                __nv_bfloat162 hB(__float2bfloat16(p2), __float2bfloat16(p3));
                pfh[kf][0 + 2*jj] = *(uint32_t*)&hA;
                pfh[kf][1 + 2*jj] = *(uint32_t*)&hB;
            }
        }
        rs0 += __shfl_xor_sync(0xffffffffu, rs0, 1);
        rs0 += __shfl_xor_sync(0xffffffffu, rs0, 2);
        rs1 += __shfl_xor_sync(0xffffffffu, rs1, 1);
        rs1 += __shfl_xor_sync(0xffffffffu, rs1, 2);
        l0 = l0*c0 + rs0;
        l1 = l1*c1 + rs1;
        m0 = m0n; m1 = m1n;
        #pragma unroll
        for (int j = 0; j < 16; j++) {
            o_[j][0] *= c0; o_[j][1] *= c0;
            o_[j][2] *= c1; o_[j][3] *= c1;
        }

        // O += P V  (P bf16, V split hi+lo)
        #pragma unroll
        for (int jp = 0; jp < 8; jp++) {
            #pragma unroll
            for (int kf = 0; kf < 4; kf++) {
                uint32_t ad = kb_ + AVH + (uint32_t)((browB + jp*16)*72 + bcolB + kf*16)*2u;
                uint32_t vh0,vh1,vh2,vh3, vl0,vl1,vl2,vl3;
                LDSM4(vh0,vh1,vh2,vh3, ad);
                LDSM4(vl0,vl1,vl2,vl3, ad + (AVL-AVH));
                uint32_t va[2] = {vh0,vh1}, vb[2] = {vh2,vh3};
                uint32_t wa[2] = {vl0,vl1}, wb[2] = {vl2,vl3};
                MMA_BF16(o_[2*jp],   pfh[kf], va);
                MMA_BF16(o_[2*jp],   pfh[kf], wa);
                MMA_BF16(o_[2*jp+1], pfh[kf], vb);
                MMA_BF16(o_[2*jp+1], pfh[kf], wb);
            }
        }
        __syncthreads();
    }
    #undef LOAD_KV

    const float inv0 = 1.0f / l0;
    const float inv1 = 1.0f / l1;
    const size_t ob0 = ((size_t)(b*Tdim) + t0) * (QH*HD) + h*HD;
    const size_t ob1 = ((size_t)(b*Tdim) + t1) * (QH*HD) + h*HD;
    #pragma unroll
    for (int jn = 0; jn < 16; jn++) {
        int d = jn*8 + cb2;
        float y0 = o_[jn][0]*inv0, y1 = o_[jn][1]*inv0;
        float y2 = o_[jn][2]*inv1, y3 = o_[jn][3]*inv1;
        __nv_bfloat16 h0,lo0,h1,lo1,h2,lo2,h3,lo3;
        split_bf16(y0,h0,lo0); split_bf16(y1,h1,lo1);
        split_bf16(y2,h2,lo2); split_bf16(y3,h3,lo3);
        *(__nv_bfloat162*)(ohi + ob0 + d) = __nv_bfloat162(h0,h1);
        *(__nv_bfloat162*)(olo + ob0 + d) = __nv_bfloat162(lo0,lo1);
        *(__nv_bfloat162*)(ohi + ob1 + d) = __nv_bfloat162(h2,h3);
        *(__nv_bfloat162*)(olo + ob1 + d) = __nv_bfloat162(lo2,lo3);
    }
}

// ---------------------------------------------------------------------------
// launch helper (grid passed explicitly)
// ---------------------------------------------------------------------------
#define LAUNCH_G(g, EPI, BIAS, RES, ...) \
    bgemm_kernel<EPI, BIAS, RES><<<(g), 256, GEMM_SMEM_BYTES>>>(__VA_ARGS__)

extern "C" void kernel_launch(void* const* d_in, const int* in_sizes, int n_in,
                              void* d_out, int out_size) {
    const float* x         = (const float*)d_in[0];
    const float* gn_hawk   = (const float*)d_in[1];
    const float* gn_hgmlp  = (const float*)d_in[2];
    const float* gn_smqa   = (const float*)d_in[3];
    const float* gn_sgmlp  = (const float*)d_in[4];
    const float* hawk_Win  = (const float*)d_in[5];
    const float* hawk_cw   = (const float*)d_in[6];
    const float* hawk_cb   = (const float*)d_in[7];
    const float* hawk_Wg   = (const float*)d_in[8];
    const float* hawk_bg   = (const float*)d_in[9];
    const float* hawk_fb   = (const float*)d_in[10];
    const float* hawk_Wout = (const float*)d_in[11];
    const float* g1_Wgrow  = (const float*)d_in[12];
    const float* g1_Wshr   = (const float*)d_in[13];
    const float* g2_Wgrow  = (const float*)d_in[14];
    const float* g2_Wshr   = (const float*)d_in[15];
    const float* smqa_Wq   = (const float*)d_in[16];
    const float* smqa_Wkv  = (const float*)d_in[17];
    const float* smqa_Wout = (const float*)d_in[18];
    float* out = (float*)d_out;

    float *big, *mid, *small, *chA, *chS, *sIn;
    __nv_bfloat16 *Ahi, *Alo, *Whi, *Wlo;
    cudaGetSymbolAddress((void**)&big,   g_big);
    cudaGetSymbolAddress((void**)&mid,   g_mid);
    cudaGetSymbolAddress((void**)&small, g_small);
    cudaGetSymbolAddress((void**)&Ahi,   g_Ahi);
    cudaGetSymbolAddress((void**)&Alo,   g_Alo);
    cudaGetSymbolAddress((void**)&Whi,   g_Whi);
    cudaGetSymbolAddress((void**)&Wlo,   g_Wlo);
    cudaGetSymbolAddress((void**)&chA,   g_chA);
    cudaGetSymbolAddress((void**)&chS,   g_chS);
    cudaGetSymbolAddress((void**)&sIn,   g_sIn);

    cudaFuncSetAttribute((const void*)attn_hmma_kernel,
                         cudaFuncAttributeMaxDynamicSharedMemorySize, (int)ATT_SMEM);
    cudaFuncSetAttribute((const void*)bgemm_kernel<0,false,false>,
                         cudaFuncAttributeMaxDynamicSharedMemorySize, GEMM_SMEM_BYTES);
    cudaFuncSetAttribute((const void*)bgemm_kernel<0,true,false>,
                         cudaFuncAttributeMaxDynamicSharedMemorySize, GEMM_SMEM_BYTES);
    cudaFuncSetAttribute((const void*)bgemm_kernel<0,false,true>,
                         cudaFuncAttributeMaxDynamicSharedMemorySize, GEMM_SMEM_BYTES);
    cudaFuncSetAttribute((const void*)bgemm_kernel<1,false,false>,
                         cudaFuncAttributeMaxDynamicSharedMemorySize, GEMM_SMEM_BYTES);
    cudaFuncSetAttribute((const void*)bgemm_kernel<2,false,false>,
                         cudaFuncAttributeMaxDynamicSharedMemorySize, GEMM_SMEM_BYTES);
    cudaFuncSetAttribute((const void*)bgemm_kernel<3,false,false>,
                         cudaFuncAttributeMaxDynamicSharedMemorySize, GEMM_SMEM_BYTES);

    const int EW = 256;
    __nv_bfloat16* nb = nullptr;

    // weight slices
    __nv_bfloat16* WinH  = Whi + (size_t)W_WIN*4;   __nv_bfloat16* WinL  = Wlo + (size_t)W_WIN*4;
    __nv_bfloat16* WgH   = Whi + (size_t)W_WG*4;    __nv_bfloat16* WgL   = Wlo + (size_t)W_WG*4;
    __nv_bfloat16* WoutH = Whi + (size_t)W_WOUT*4;  __nv_bfloat16* WoutL = Wlo + (size_t)W_WOUT*4;
    __nv_bfloat16* G1gH  = Whi + (size_t)W_G1G*4;   __nv_bfloat16* G1gL  = Wlo + (size_t)W_G1G*4;
    __nv_bfloat16* G1sH  = Whi + (size_t)W_G1S*4;   __nv_bfloat16* G1sL  = Wlo + (size_t)W_G1S*4;
    __nv_bfloat16* G2gH  = Whi + (size_t)W_G2G*4;   __nv_bfloat16* G2gL  = Wlo + (size_t)W_G2G*4;
    __nv_bfloat16* G2sH  = Whi + (size_t)W_G2S*4;   __nv_bfloat16* G2sL  = Wlo + (size_t)W_G2S*4;
    __nv_bfloat16* WqH   = Whi + (size_t)W_Q*4;     __nv_bfloat16* WqL   = Wlo + (size_t)W_Q*4;
    __nv_bfloat16* WkvH  = Whi + (size_t)W_KV*4;    __nv_bfloat16* WkvL  = Wlo + (size_t)W_KV*4;
    __nv_bfloat16* Wo2H  = Whi + (size_t)W_O2*4;    __nv_bfloat16* Wo2L  = Wlo + (size_t)W_O2*4;

    // grids (CTN=128, R12 config)
    const dim3 gridWin((2*HID)/CTN, MROWS/CTM);   // 24 x 64
    const dim3 gridDim_(DIM/CTN, MROWS/CTM);      // 8 x 64
    const dim3 gridGrow((2*GH)/CTN, MROWS/CTM);   // 32 x 64
    const dim3 gridQ((QH*HD)/CTN, MROWS/CTM);     // 8 x 64
    const dim3 gridKV((2*HD)/CTN, MROWS/CTM);     // 2 x 64

    // attn bf16 buffers inside g_mid
    __nv_bfloat16* qhi  = (__nv_bfloat16*)mid;
    __nv_bfloat16* qlo  = (__nv_bfloat16*)(mid + 4194304);
    __nv_bfloat16* khi  = (__nv_bfloat16*)(mid + 8388608);
    __nv_bfloat16* klo  = (__nv_bfloat16*)(mid + 8912896);
    __nv_bfloat16* vthi = (__nv_bfloat16*)(mid + 9437184);
    __nv_bfloat16* vtlo = (__nv_bfloat16*)(mid + 9961472);
    __nv_bfloat16* acth = (__nv_bfloat16*)mid;
    __nv_bfloat16* actl = (__nv_bfloat16*)(mid + 8388608);

    // ---------------- one-shot: convert all weights ----------------
    convw_all_kernel<<<(W_TOT + EW - 1)/EW, EW>>>(
        hawk_Win, hawk_Wg, hawk_Wout, g1_Wgrow, g1_Wshr,
        g2_Wgrow, g2_Wshr, smqa_Wq, smqa_Wkv, smqa_Wout, Whi, Wlo);

    // ---------------- stage 1: hawk ----------------
    rmsnorm_bf16_kernel<<<MROWS, 256>>>(x, gn_hawk, Ahi, Alo);
    LAUNCH_G(gridWin, 0,false,false, Ahi,Alo,WinH,WinL, nullptr,nullptr, big, 2*HID, DIM, nb,nb,nb,nb);
    conv_kernel<<<dim3(Tdim/TCH, Bdim), 384>>>(big, hawk_cw, hawk_cb, Ahi, Alo);
    LAUNCH_G(gridWin, 0,true,false, Ahi,Alo,WgH,WgL, hawk_bg,nullptr, mid, 2*HID, HID, nb,nb,nb,nb);
    scanAG_kernel<<<(Bdim*NCH*HID + EW - 1)/EW, EW>>>(mid, Ahi, Alo, hawk_fb, chA, chS);
    scanB_kernel<<<(Bdim*HID + EW - 1)/EW, EW>>>(chA, chS, sIn);
    scanC_kernel<<<(Bdim*NCH*HID + EW - 1)/EW, EW>>>(mid, big, sIn, Ahi, Alo);
    LAUNCH_G(gridDim_, 0,false,true, Ahi,Alo,WoutH,WoutL, nullptr,x, out, DIM, HID, nb,nb,nb,nb);

    // ---------------- stage 2: gated MLP 1 ----------------
    rmsnorm_bf16_kernel<<<MROWS, 256>>>(out, gn_hgmlp, Ahi, Alo);
    LAUNCH_G(gridGrow, 1,false,false, Ahi,Alo,G1gH,G1gL, nullptr,nullptr, nullptr, 2*GH, DIM,
             acth, actl, nb, nb);
    LAUNCH_G(gridDim_, 0,false,true, acth,actl,G1sH,G1sL, nullptr,out, out, DIM, GH, nb,nb,nb,nb);

    // ---------------- stage 3: sliding-window MQA ----------------
    rmsnorm_bf16_kernel<<<MROWS, 256>>>(out, gn_smqa, Ahi, Alo);
    LAUNCH_G(gridQ, 2,false,false, Ahi,Alo,WqH,WqL, nullptr,nullptr, nullptr, QH*HD, DIM,
             qhi, qlo, nb, nb);
    LAUNCH_G(gridKV, 3,false,false, Ahi,Alo,WkvH,WkvL, nullptr,nullptr, nullptr, 2*HD, DIM,
             khi, klo, vthi, vtlo);
    attn_hmma_kernel<<<dim3(Tdim/AQ, QH, Bdim), 256, ATT_SMEM>>>(
        qhi, qlo, khi, klo, vthi, vtlo, Ahi, Alo);
    LAUNCH_G(gridDim_, 0,false,true, Ahi,Alo,Wo2H,Wo2L, nullptr,out, out, DIM, DIM, nb,nb,nb,nb);

    // ---------------- stage 4: gated MLP 2 ----------------
    rmsnorm_bf16_kernel<<<MROWS, 256>>>(out, gn_sgmlp, Ahi, Alo);
    LAUNCH_G(gridGrow, 1,false,false, Ahi,Alo,G2gH,G2gL, nullptr,nullptr, nullptr, 2*GH, DIM,
             acth, actl, nb, nb);
    LAUNCH_G(gridDim_, 0,false,true, acth,actl,G2sH,G2sL, nullptr,out, out, DIM, GH, nb,nb,nb,nb);
}

// round 16
// speedup vs baseline: 1.1073x; 1.0036x over previous
#include <cuda_runtime.h>
#include <cuda_bf16.h>
#include <math.h>
#include <stdint.h>

// ---------------------------------------------------------------------------
// GriffinBlock: HMMA bf16x3 GEMMs (R12 config) + HMMA flash attn
// R16: hawk gates fused into Wg GEMM epilogue (EPI=5, interleaved Wg rows)
// B=4, T=2048, DIM=1024, HID=1536, GH=2048, K=4, HD=128, QH=8, W=1024
// ---------------------------------------------------------------------------

#define Bdim 4
#define Tdim 2048
#define DIM 1024
#define HID 1536
#define GH  2048
#define KCONV 4
#define HD  128
#define QH  8
#define WINSZ 1024
#define MROWS (Bdim*Tdim)   // 8192
#define LOG2E 1.4426950408889634f
#define QSCALE 0.088388347648318447f
#define ROT_C (9.210340371976184f / 128.0f)

// ---------------- static scratch ----------------
__device__ float g_big[33554432];      // 8192*4096
__device__ float g_mid[25165824];      // 8192*3072 (hawk gi; act/attn bf16 scratch)
__device__ float g_small[12582912];    // m8sp table lives at [0..HID)
__device__ __nv_bfloat16 g_Ahi[16777216];  // 8192*2048 max
__device__ __nv_bfloat16 g_Alo[16777216];
__device__ __nv_bfloat16 g_Whi[24379392];  // all weights, bf16 hi
__device__ __nv_bfloat16 g_Wlo[24379392];  // all weights, bf16 lo
__device__ float g_chA[98304];
__device__ float g_chS[98304];
__device__ float g_sIn[98304];

// weight slice offsets in float4 units (x4 for elements)
#define W_WIN  0u
#define W_WG   786432u
#define W_WOUT 1966080u
#define W_G1G  2359296u
#define W_G1S  3407872u
#define W_G2G  3932160u
#define W_G2S  4980736u
#define W_Q    5505024u
#define W_KV   5767168u
#define W_O2   5832704u
#define W_TOT  6094848u

__device__ __forceinline__ float gelu_exact(float x) {
    return 0.5f * x * (1.0f + erff(x * 0.70710678118654752f));
}
__device__ __forceinline__ float sigmoidf_(float x) {
    return 1.0f / (1.0f + expf(-x));
}
__device__ __forceinline__ void split_bf16(float v, __nv_bfloat16& h, __nv_bfloat16& l) {
    h = __float2bfloat16(v);
    l = __float2bfloat16(v - __bfloat162float(h));
}

__device__ __forceinline__ uint32_t smem_u32(const void* p) {
    uint32_t a;
    asm("{ .reg .u64 t; cvta.to.shared.u64 t, %1; cvt.u32.u64 %0, t; }" : "=r"(a) : "l"(p));
    return a;
}
__device__ __forceinline__ void cp16(uint32_t dst, const void* src) {
    asm volatile("cp.async.ca.shared.global [%0], [%1], 16;" :: "r"(dst), "l"(src));
}

#define LDSM4(r0, r1, r2, r3, addr) \
    asm volatile("ldmatrix.sync.aligned.m8n8.x4.shared.b16 {%0,%1,%2,%3}, [%4];" \
        : "=r"(r0), "=r"(r1), "=r"(r2), "=r"(r3) : "r"(addr))

#define MMA_BF16(d, a, b) \
    asm volatile("mma.sync.aligned.m16n8k16.row.col.f32.bf16.bf16.f32 " \
        "{%0,%1,%2,%3}, {%4,%5,%6,%7}, {%8,%9}, {%0,%1,%2,%3};" \
        : "+f"((d)[0]), "+f"((d)[1]), "+f"((d)[2]), "+f"((d)[3]) \
        : "r"((a)[0]), "r"((a)[1]), "r"((a)[2]), "r"((a)[3]), \
          "r"((b)[0]), "r"((b)[1]))

// ---------------------------------------------------------------------------
// bf16x3 HMMA GEMM (R12 config): CTA 128x128, warp 32x64, CTK=64, 2-stage.
// EPI: 0 = plain fp32 C (+bias/res), 1 = gelu-gate pair -> bf16 hi/lo,
//      2 = q rotary+scale -> bf16, 3 = kv rotary / v-transpose -> bf16,
//      5 = hawk gates (interleaved Wg): {alpha, xs} float2 -> C
//          (bias = hawk_bg fp32[2*HID], res = m8sp table fp32[HID],
//           e0/e1 = hconv bf16 hi/lo)
// ---------------------------------------------------------------------------
#define CTM 128
#define CTN 128
#define CTK 64
#define APITCH 72
#define OFF_SALO_B 18432u
#define OFF_SBHI_B 36864u
#define OFF_SBLO_B 55296u
#define STAGE_BYTES 73728u
#define GEMM_SMEM_BYTES (2u*STAGE_BYTES)  // 147456

template<int EPI, bool HAS_BIAS, bool HAS_RES>
__global__ void __launch_bounds__(256, 1)
bgemm_kernel(const __nv_bfloat16* __restrict__ Ahi, const __nv_bfloat16* __restrict__ Alo,
             const __nv_bfloat16* __restrict__ Whi, const __nv_bfloat16* __restrict__ Wlo,
             const float* __restrict__ bias, const float* __restrict__ res,
             float* __restrict__ C, int N, int K,
             __nv_bfloat16* __restrict__ e0, __nv_bfloat16* __restrict__ e1,
             __nv_bfloat16* __restrict__ e2, __nv_bfloat16* __restrict__ e3) {
    extern __shared__ char smc[];
    const uint32_t sb = smem_u32(smc);
    const int tid = threadIdx.x;
    const int lane = tid & 31;
    const int wid = tid >> 5;
    const int wy = wid & 3;
    const int wx = wid >> 2;
    const int m0 = blockIdx.y * CTM;
    const int n0 = blockIdx.x * CTN;

    const int arow = wy*32 + (lane & 15);
    const int acol = (lane >> 4) * 8;
    const uint32_t aoff = (uint32_t)(arow*APITCH + acol) * 2u;
    const int g  = lane >> 3;
    const int rr = lane & 7;
    const int brow = wx*64 + rr + ((g >> 1) << 3);
    const int bcol = (g & 1) * 8;
    const uint32_t boff = (uint32_t)(brow*APITCH + bcol) * 2u;

    float acc[2][8][4];
    #pragma unroll
    for (int i = 0; i < 2; i++)
        #pragma unroll
        for (int j = 0; j < 8; j++)
            #pragma unroll
            for (int v = 0; v < 4; v++) acc[i][j][v] = 0.f;

    const int NC = K / CTK;

    #define LOAD_STAGE(stg, kb) do { \
        uint32_t sbase_ = sb + (stg)*STAGE_BYTES; \
        _Pragma("unroll") \
        for (int it_ = 0; it_ < 4; it_++) { \
            int u_ = tid + it_*256; \
            int r_ = u_ >> 3; \
            int c_ = u_ & 7; \
            uint32_t d_ = sbase_ + (uint32_t)r_*144u + (uint32_t)c_*16u; \
            size_t ga_ = (size_t)(m0 + r_) * K + (kb) + c_*8; \
            size_t gb_ = (size_t)(n0 + r_) * K + (kb) + c_*8; \
            cp16(d_,              Ahi + ga_); \
            cp16(d_ + OFF_SALO_B, Alo + ga_); \
            cp16(d_ + OFF_SBHI_B, Whi + gb_); \
            cp16(d_ + OFF_SBLO_B, Wlo + gb_); \
        } \
        asm volatile("cp.async.commit_group;"); \
    } while (0)

    LOAD_STAGE(0, 0);

    for (int ch = 0; ch < NC; ch++) {
        const int stg = ch & 1;
        if (ch + 1 < NC) {
            LOAD_STAGE(stg ^ 1, (ch + 1) * CTK);
            asm volatile("cp.async.wait_group 1;");
        } else {
            asm volatile("cp.async.wait_group 0;");
        }
        __syncthreads();

        const uint32_t sbase = sb + stg * STAGE_BYTES;
        #pragma unroll
        for (int k16 = 0; k16 < 4; k16++) {
            uint32_t ah[2][4], al[2][4], bh[8][2], bl[8][2];
            #pragma unroll
            for (int mt = 0; mt < 2; mt++) {
                uint32_t ad = sbase + aoff + (uint32_t)mt*(16*APITCH*2) + (uint32_t)k16*32u;
                LDSM4(ah[mt][0], ah[mt][1], ah[mt][2], ah[mt][3], ad);
                LDSM4(al[mt][0], al[mt][1], al[mt][2], al[mt][3], ad + OFF_SALO_B);
            }
            #pragma unroll
            for (int jp = 0; jp < 4; jp++) {
                uint32_t bd = sbase + boff + (uint32_t)jp*(16*APITCH*2) + (uint32_t)k16*32u;
                LDSM4(bh[2*jp][0], bh[2*jp][1], bh[2*jp+1][0], bh[2*jp+1][1], bd + OFF_SBHI_B);
                LDSM4(bl[2*jp][0], bl[2*jp][1], bl[2*jp+1][0], bl[2*jp+1][1], bd + OFF_SBLO_B);
            }
            #pragma unroll
            for (int mt = 0; mt < 2; mt++)
                #pragma unroll
                for (int j = 0; j < 8; j++) {
                    MMA_BF16(acc[mt][j], ah[mt], bh[j]);
                    MMA_BF16(acc[mt][j], ah[mt], bl[j]);
                    MMA_BF16(acc[mt][j], al[mt], bh[j]);
                }
        }
        __syncthreads();
    }
    #undef LOAD_STAGE

    // ---- epilogues ----
    const int rbase = m0 + wy*32 + (lane >> 2);
    const int cbase = wx*64 + (lane & 3)*2;   // tile-local, even
    #pragma unroll
    for (int mt = 0; mt < 2; mt++) {
        #pragma unroll
        for (int half = 0; half < 2; half++) {
            const int row = rbase + mt*16 + half*8;
            #pragma unroll
            for (int j = 0; j < 8; j++) {
                const int coll = cbase + j*8;     // local col (even)
                const int col  = n0 + coll;       // global col
                float v0 = acc[mt][j][half*2 + 0];
                float v1 = acc[mt][j][half*2 + 1];
                if (EPI == 0) {
                    if (HAS_BIAS) { v0 += bias[col]; v1 += bias[col + 1]; }
                    if (HAS_RES) {
                        const float2 rv = *(const float2*)(res + (size_t)row * N + col);
                        v0 += rv.x; v1 += rv.y;
                    }
                    float2 o; o.x = v0; o.y = v1;
                    *(float2*)(C + (size_t)row * N + col) = o;
                } else if (EPI == 1) {
                    float y = gelu_exact(v0) * v1;
                    __nv_bfloat16 hh, ll; split_bf16(y, hh, ll);
                    size_t o = (size_t)row * GH + (col >> 1);
                    e0[o] = hh; e1[o] = ll;
                } else if (EPI == 2) {
                    int d = col & (HD - 1);
                    int hh_ = col >> 7;
                    int t = row & (Tdim - 1);
                    int b = row >> 11;
                    float inv = expf(-(float)d * ROT_C);
                    float sn, cs; sincosf((float)t * inv, &sn, &cs);
                    float y0 = (v0*cs - v1*sn) * QSCALE;
                    float y1 = (v1*cs + v0*sn) * QSCALE;
                    __nv_bfloat16 h0,l0,h1,l1;
                    split_bf16(y0,h0,l0); split_bf16(y1,h1,l1);
                    size_t o = (((size_t)(b*QH + hh_)) * Tdim + t) * HD + d;
                    *(__nv_bfloat162*)(e0 + o) = __nv_bfloat162(h0,h1);
                    *(__nv_bfloat162*)(e1 + o) = __nv_bfloat162(l0,l1);
                } else if (EPI == 3) {
                    int t = row & (Tdim - 1);
                    int b = row >> 11;
                    if (col < HD) {
                        int d = col;
                        float inv = expf(-(float)d * ROT_C);
                        float sn, cs; sincosf((float)t * inv, &sn, &cs);
                        float y0 = v0*cs - v1*sn;
                        float y1 = v1*cs + v0*sn;
                        __nv_bfloat16 h0,l0,h1,l1;
                        split_bf16(y0,h0,l0); split_bf16(y1,h1,l1);
                        size_t o = (size_t)row * HD + d;
                        *(__nv_bfloat162*)(e0 + o) = __nv_bfloat162(h0,h1);
                        *(__nv_bfloat162*)(e1 + o) = __nv_bfloat162(l0,l1);
                    } else {
                        int d = col - HD;
                        __nv_bfloat16 h0,l0,h1,l1;
                        split_bf16(v0,h0,l0); split_bf16(v1,h1,l1);
                        size_t o0 = ((size_t)(b*HD + d)) * Tdim + t;
                        size_t o1 = ((size_t)(b*HD + d + 1)) * Tdim + t;
                        e2[o0] = h0; e3[o0] = l0;
                        e2[o1] = h1; e3[o1] = l1;
                    }
                } else {
                    // EPI == 5: hawk gates. col even pair = channel c.
                    // v0 = forget pre-bias, v1 = inp pre-bias.
                    int c = col >> 1;
                    float f  = v0 + bias[c];
                    float ip = v1 + bias[HID + c];
                    size_t ho = (size_t)row * HID + c;
                    float h = __bfloat162float(e0[ho]) + __bfloat162float(e1[ho]);
                    float alpha = expf(res[c] * sigmoidf_(f));
                    float beta  = sqrtf(1.0f - alpha*alpha + 1e-6f);
                    float xs = beta * sigmoidf_(ip) * h;
                    float2 o; o.x = alpha; o.y = xs;
                    *(float2*)(C + (size_t)row * N + col) = o;
                }
            }
        }
    }
}

// ---------------------------------------------------------------------------
// ONE-SHOT weight conversion. grow weights: gate/h row-interleaved (DIM cols).
// Wg weights: forget/inp row-interleaved (HID cols).
// ---------------------------------------------------------------------------
__device__ __forceinline__ void conv_store(__nv_bfloat16* hi, __nv_bfloat16* lo,
                                           uint32_t dst4, float4 v) {
    __nv_bfloat16 h0, h1, h2, h3, l0, l1, l2, l3;
    split_bf16(v.x, h0, l0); split_bf16(v.y, h1, l1);
    split_bf16(v.z, h2, l2); split_bf16(v.w, h3, l3);
    __nv_bfloat162* hp = (__nv_bfloat162*)hi;
    __nv_bfloat162* lp = (__nv_bfloat162*)lo;
    hp[2*(size_t)dst4]   = __nv_bfloat162(h0, h1);
    hp[2*(size_t)dst4+1] = __nv_bfloat162(h2, h3);
    lp[2*(size_t)dst4]   = __nv_bfloat162(l0, l1);
    lp[2*(size_t)dst4+1] = __nv_bfloat162(l2, l3);
}

__global__ void convw_all_kernel(
    const float* __restrict__ win, const float* __restrict__ wg,
    const float* __restrict__ wout, const float* __restrict__ g1g,
    const float* __restrict__ g1s, const float* __restrict__ g2g,
    const float* __restrict__ g2s, const float* __restrict__ wq,
    const float* __restrict__ wkv, const float* __restrict__ wo2,
    __nv_bfloat16* __restrict__ hi, __nv_bfloat16* __restrict__ lo) {
    uint32_t i = blockIdx.x * blockDim.x + threadIdx.x;
    if (i >= W_TOT) return;
    const float* src;
    uint32_t base, local;
    int ilv = 0;   // 0 none, 1 = grow (DIM cols, GH half), 2 = Wg (HID cols, HID half)
    if      (i < W_WG)   { src = win;  base = W_WIN;  }
    else if (i < W_WOUT) { src = wg;   base = W_WG;   ilv = 2; }
    else if (i < W_G1G)  { src = wout; base = W_WOUT; }
    else if (i < W_G1S)  { src = g1g;  base = W_G1G;  ilv = 1; }
    else if (i < W_G2G)  { src = g1s;  base = W_G1S;  }
    else if (i < W_G2S)  { src = g2g;  base = W_G2G;  ilv = 1; }
    else if (i < W_Q)    { src = g2s;  base = W_G2S;  }
    else if (i < W_KV)   { src = wq;   base = W_Q;    }
    else if (i < W_O2)   { src = wkv;  base = W_KV;   }
    else                 { src = wo2;  base = W_O2;   }
    local = i - base;
    float4 v = ((const float4*)src)[local];
    uint32_t dlocal = local;
    if (ilv == 1) {
        uint32_t r  = local >> 8;          // DIM/4 = 256 float4 per row
        uint32_t c4 = local & 255u;
        uint32_t rp = (r < GH) ? (2u*r) : (2u*(r - GH) + 1u);
        dlocal = rp*256u + c4;
    } else if (ilv == 2) {
        uint32_t r  = local / 384u;        // HID/4 = 384 float4 per row
        uint32_t c4 = local % 384u;
        uint32_t rp = (r < HID) ? (2u*r) : (2u*(r - HID) + 1u);
        dlocal = rp*384u + c4;
    }
    conv_store(hi, lo, base + dlocal, v);
}

// ---------------------------------------------------------------------------
// m8sp table: m8sp[c] = -8 * softplus(fb[c])
// ---------------------------------------------------------------------------
__global__ void m8sp_kernel(const float* __restrict__ fb, float* __restrict__ out) {
    int c = blockIdx.x * blockDim.x + threadIdx.x;
    if (c < HID) out[c] = -8.0f * log1pf(expf(fb[c]));
}

// ---------------------------------------------------------------------------
// RMSNorm -> bf16 hi/lo
// ---------------------------------------------------------------------------
__global__ void rmsnorm_bf16_kernel(const float* __restrict__ x,
                                    const float* __restrict__ gamma,
                                    __nv_bfloat16* __restrict__ hi,
                                    __nv_bfloat16* __restrict__ lo) {
    int row = blockIdx.x;
    int tid = threadIdx.x;
    float4 v = ((const float4*)(x + (size_t)row * DIM))[tid];
    float ss = v.x*v.x + v.y*v.y + v.z*v.z + v.w*v.w;
    #pragma unroll
    for (int o = 16; o; o >>= 1) ss += __shfl_xor_sync(0xffffffffu, ss, o);
    __shared__ float red[8];
    __shared__ float stot;
    if ((tid & 31) == 0) red[tid >> 5] = ss;
    __syncthreads();
    if (tid == 0) {
        float s = 0.f;
        #pragma unroll
        for (int i = 0; i < 8; i++) s += red[i];
        stot = s;
    }
    __syncthreads();
    float scale = 32.0f * rsqrtf(stot);
    float4 g = ((const float4*)gamma)[tid];
    float o0 = v.x*scale*g.x, o1 = v.y*scale*g.y, o2 = v.z*scale*g.z, o3 = v.w*scale*g.w;
    __nv_bfloat16 h0,h1,h2,h3,l0,l1,l2,l3;
    split_bf16(o0,h0,l0); split_bf16(o1,h1,l1); split_bf16(o2,h2,l2); split_bf16(o3,h3,l3);
    __nv_bfloat162* hp = (__nv_bfloat162*)(hi + (size_t)row * DIM);
    __nv_bfloat162* lp = (__nv_bfloat162*)(lo + (size_t)row * DIM);
    hp[2*tid]   = __nv_bfloat162(h0,h1);
    hp[2*tid+1] = __nv_bfloat162(h2,h3);
    lp[2*tid]   = __nv_bfloat162(l0,l1);
    lp[2*tid+1] = __nv_bfloat162(l2,l3);
}

// ---------------------------------------------------------------------------
// hawk depthwise causal conv (K=4), sliding-window; bf16 hi/lo output
// ---------------------------------------------------------------------------
#define TCH 32
__global__ void __launch_bounds__(384)
conv_kernel(const float* __restrict__ gh,
            const float* __restrict__ cw,
            const float* __restrict__ cb,
            __nv_bfloat16* __restrict__ hi,
            __nv_bfloat16* __restrict__ lo) {
    __shared__ float scw[HID*KCONV];
    const int tb = blockIdx.x;
    const int b  = blockIdx.y;
    const int c4 = threadIdx.x;
    const int c  = c4 * 4;
    for (int i = threadIdx.x; i < (HID*KCONV)/4; i += 384)
        ((float4*)scw)[i] = ((const float4*)cw)[i];
    __syncthreads();
    float w[4][4];
    #pragma unroll
    for (int i = 0; i < 4; i++)
        #pragma unroll
        for (int k = 0; k < 4; k++) w[i][k] = scw[(c+i)*KCONV + k];
    const float4 bias = ((const float4*)cb)[c4];
    const int t0 = tb * TCH;
    float4 win[4];
    #pragma unroll
    for (int k = 0; k < 3; k++) {
        int tt = t0 - 3 + k;
        win[k] = make_float4(0.f, 0.f, 0.f, 0.f);
        if (tt >= 0)
            win[k] = *(const float4*)(gh + (size_t)(b*Tdim + tt)*(2*HID) + HID + c);
    }
    for (int dt = 0; dt < TCH; dt++) {
        const int t = t0 + dt;
        win[3] = *(const float4*)(gh + (size_t)(b*Tdim + t)*(2*HID) + HID + c);
        float4 acc = bias;
        #pragma unroll
        for (int k = 0; k < 4; k++) {
            acc.x = fmaf(w[0][k], win[k].x, acc.x);
            acc.y = fmaf(w[1][k], win[k].y, acc.y);
            acc.z = fmaf(w[2][k], win[k].z, acc.z);
            acc.w = fmaf(w[3][k], win[k].w, acc.w);
        }
        const size_t bt = (size_t)(b*Tdim + t);
        __nv_bfloat16 h0,h1,h2,h3,l0,l1,l2,l3;
        split_bf16(acc.x,h0,l0); split_bf16(acc.y,h1,l1);
        split_bf16(acc.z,h2,l2); split_bf16(acc.w,h3,l3);
        __nv_bfloat162* hp = (__nv_bfloat162*)(hi + bt * HID + c);
        __nv_bfloat162* lp = (__nv_bfloat162*)(lo + bt * HID + c);
        hp[0] = __nv_bfloat162(h0,h1);
        hp[1] = __nv_bfloat162(h2,h3);
        lp[0] = __nv_bfloat162(l0,l1);
        lp[1] = __nv_bfloat162(l2,l3);
        win[0] = win[1]; win[1] = win[2]; win[2] = win[3];
    }
}

// ---------------------------------------------------------------------------
// chunked parallel scan over {alpha, xs} float2 pairs (gi interleaved layout)
// ---------------------------------------------------------------------------
#define SCH 128
#define NCH 16
__global__ void scanA_kernel(const float* __restrict__ gi,
                             float* __restrict__ chA, float* __restrict__ chS) {
    int idx = blockIdx.x * blockDim.x + threadIdx.x;
    if (idx >= Bdim * NCH * HID) return;
    int c = idx % HID;
    int r = idx / HID;
    int ch = r & (NCH - 1);
    int b  = r >> 4;
    size_t base = ((size_t)b * Tdim + ch * SCH) * (2*HID) + 2*c;
    float ap = 1.f, s = 0.f;
    for (int t = 0; t < SCH; t++) {
        float2 axs = *(const float2*)(gi + base + (size_t)t * (2*HID));
        s = fmaf(axs.x, s, axs.y);
        ap *= axs.x;
    }
    chA[idx] = ap;
    chS[idx] = s;
}
__global__ void scanB_kernel(const float* __restrict__ chA, const float* __restrict__ chS,
                             float* __restrict__ sIn) {
    int idx = blockIdx.x * blockDim.x + threadIdx.x;
    if (idx >= Bdim * HID) return;
    int c = idx % HID;
    int b = idx / HID;
    float s = 0.f;
    #pragma unroll
    for (int ch = 0; ch < NCH; ch++) {
        size_t o = ((size_t)(b * NCH + ch)) * HID + c;
        sIn[o] = s;
        s = fmaf(chA[o], s, chS[o]);
    }
}
__global__ void scanC_kernel(const float* __restrict__ gi, const float* __restrict__ gh,
                             const float* __restrict__ sIn,
                             __nv_bfloat16* __restrict__ hi, __nv_bfloat16* __restrict__ lo) {
    int idx = blockIdx.x * blockDim.x + threadIdx.x;
    if (idx >= Bdim * NCH * HID) return;
    int c = idx % HID;
    int r = idx / HID;
    int ch = r & (NCH - 1);
    int b  = r >> 4;
    float st = sIn[idx];
    size_t gbase = ((size_t)b * Tdim + ch * SCH) * (2*HID);
    size_t ob    = ((size_t)b * Tdim + ch * SCH) * HID + c;
    for (int t = 0; t < SCH; t++) {
        size_t o = gbase + (size_t)t * (2*HID);
        float2 axs = *(const float2*)(gi + o + 2*c);
        float g = gh[o + c];
        st = fmaf(axs.x, st, axs.y);
        float y = gelu_exact(g) * st;
        __nv_bfloat16 h, l; split_bf16(y, h, l);
        hi[ob + (size_t)t * HID] = h;
        lo[ob + (size_t)t * HID] = l;
    }
}

// ---------------------------------------------------------------------------
// HMMA flash attention (unchanged from R12): bf16x3 QK^T, PV hi-only P
// ---------------------------------------------------------------------------
#define AQ 128
#define AQH_OFF 0u
#define AQL_OFF 34816u
#define AST_OFF 69632u
#define AKH 0u
#define AKL 17408u
#define AVH 34816u
#define AVL 53248u
#define ASTAGE 71680u
#define ATT_SMEM (69632u + 2u*71680u)   // 212992

__global__ void __launch_bounds__(256, 1)
attn_hmma_kernel(const __nv_bfloat16* __restrict__ qhi, const __nv_bfloat16* __restrict__ qlo,
                 const __nv_bfloat16* __restrict__ khi, const __nv_bfloat16* __restrict__ klo,
                 const __nv_bfloat16* __restrict__ vthi, const __nv_bfloat16* __restrict__ vtlo,
                 __nv_bfloat16* __restrict__ ohi, __nv_bfloat16* __restrict__ olo) {
    extern __shared__ char smc[];
    const uint32_t sb = smem_u32(smc);
    const int tid  = threadIdx.x;
    const int lane = tid & 31;
    const int w    = tid >> 5;
    const int b  = blockIdx.z;
    const int h  = blockIdx.y;
    const int q0 = blockIdx.x * AQ;

    {
        const __nv_bfloat16* qh_ = qhi + ((size_t)(b*QH + h) * Tdim + q0) * HD;
        const __nv_bfloat16* ql_ = qlo + ((size_t)(b*QH + h) * Tdim + q0) * HD;
        #pragma unroll
        for (int it = 0; it < 8; it++) {
            int u = tid + it*256;
            int r = u >> 4, c = u & 15;
            uint32_t d = sb + AQH_OFF + (uint32_t)r*272u + (uint32_t)c*16u;
            cp16(d,           qh_ + (size_t)r*HD + c*8);
            cp16(d + AQL_OFF, ql_ + (size_t)r*HD + c*8);
        }
        asm volatile("cp.async.commit_group;");
    }

    const int ks0 = (q0 >= WINSZ) ? (q0 - WINSZ) : 0;
    const int nt  = (q0 + AQ - ks0) >> 6;

    #define LOAD_KV(stg, ks) do { \
        uint32_t sbase_ = sb + AST_OFF + (uint32_t)(stg)*ASTAGE; \
        const __nv_bfloat16* kh_ = khi + ((size_t)b*Tdim + (ks))*HD; \
        const __nv_bfloat16* kl_ = klo + ((size_t)b*Tdim + (ks))*HD; \
        const __nv_bfloat16* vh_ = vthi + (size_t)b*HD*Tdim + (ks); \
        const __nv_bfloat16* vl_ = vtlo + (size_t)b*HD*Tdim + (ks); \
        _Pragma("unroll") \
        for (int it_ = 0; it_ < 4; it_++) { \
            int u_ = tid + it_*256; \
            int r_ = u_ >> 4, c_ = u_ & 15; \
            uint32_t d_ = sbase_ + AKH + (uint32_t)r_*272u + (uint32_t)c_*16u; \
            cp16(d_,             kh_ + (size_t)r_*HD + c_*8); \
            cp16(d_ + (AKL-AKH), kl_ + (size_t)r_*HD + c_*8); \
            int r2_ = u_ >> 3, c2_ = u_ & 7; \
            uint32_t d2_ = sbase_ + AVH + (uint32_t)r2_*144u + (uint32_t)c2_*16u; \
            cp16(d2_,            vh_ + (size_t)r2_*Tdim + c2_*8); \
            cp16(d2_ + (AVL-AVH), vl_ + (size_t)r2_*Tdim + c2_*8); \
        } \
        asm volatile("cp.async.commit_group;"); \
    } while (0)

    LOAD_KV(0, ks0);
    asm volatile("cp.async.wait_group 1;");
    __syncthreads();

    uint32_t qfh[8][4], qfl[8][4];
    {
        const int arow = w*16 + (lane & 15);
        const int acol = (lane >> 4) * 8;
        uint32_t abase = sb + AQH_OFF + (uint32_t)(arow*136 + acol)*2u;
        #pragma unroll
        for (int k = 0; k < 8; k++) {
            LDSM4(qfh[k][0],qfh[k][1],qfh[k][2],qfh[k][3], abase + (uint32_t)k*32u);
            LDSM4(qfl[k][0],qfl[k][1],qfl[k][2],qfl[k][3], abase + AQL_OFF + (uint32_t)k*32u);
        }
    }

    float o_[16][4];
    #pragma unroll
    for (int j = 0; j < 16; j++)
        #pragma unroll
        for (int v = 0; v < 4; v++) o_[j][v] = 0.f;
    float m0 = -1e30f, m1 = -1e30f, l0 = 0.f, l1 = 0.f;

    const int t0 = q0 + w*16 + (lane >> 2);
    const int t1 = t0 + 8;
    const int cb2 = (lane & 3)*2;
    const int gB  = lane >> 3;
    const int rrB = lane & 7;
    const int browB = rrB + ((gB >> 1) << 3);
    const int bcolB = (gB & 1) * 8;

    for (int i = 0; i < nt; i++) {
        const int stg = i & 1;
        if (i + 1 < nt) {
            LOAD_KV(stg ^ 1, ks0 + (i+1)*64);
            asm volatile("cp.async.wait_group 1;");
        } else {
            asm volatile("cp.async.wait_group 0;");
        }
        __syncthreads();
        const uint32_t kb_ = sb + AST_OFF + (uint32_t)stg*ASTAGE;
        const int ks = ks0 + i*64;

        float s_[8][4];
        #pragma unroll
        for (int j = 0; j < 8; j++)
            #pragma unroll
            for (int v = 0; v < 4; v++) s_[j][v] = 0.f;
        #pragma unroll
        for (int jp = 0; jp < 4; jp++) {
            #pragma unroll
            for (int k = 0; k < 8; k++) {
                uint32_t ad = kb_ + AKH + (uint32_t)((browB + jp*16)*136 + bcolB + k*16)*2u;
                uint32_t bh0,bh1,bh2,bh3, bl0,bl1,bl2,bl3;
                LDSM4(bh0,bh1,bh2,bh3, ad);
                LDSM4(bl0,bl1,bl2,bl3, ad + (AKL-AKH));
                uint32_t ba[2] = {bh0,bh1}, bb[2] = {bh2,bh3};
                uint32_t la[2] = {bl0,bl1}, lb[2] = {bl2,bl3};
                MMA_BF16(s_[2*jp],   qfh[k], ba);
                MMA_BF16(s_[2*jp],   qfl[k], ba);
                MMA_BF16(s_[2*jp],   qfh[k], la);
                MMA_BF16(s_[2*jp+1], qfh[k], bb);
                MMA_BF16(s_[2*jp+1], qfl[k], bb);
                MMA_BF16(s_[2*jp+1], qfh[k], lb);
            }
        }

        float mx0 = -1e30f, mx1 = -1e30f;
        #pragma unroll
        for (int jf = 0; jf < 8; jf++) {
            #pragma unroll
            for (int cc = 0; cc < 2; cc++) {
                int g = ks + jf*8 + cb2 + cc;
                if (!(g <= t0 && g >= t0 - WINSZ)) s_[jf][cc]   = -1e30f;
                if (!(g <= t1 && g >= t1 - WINSZ)) s_[jf][2+cc] = -1e30f;
            }
            mx0 = fmaxf(mx0, fmaxf(s_[jf][0], s_[jf][1]));
            mx1 = fmaxf(mx1, fmaxf(s_[jf][2], s_[jf][3]));
        }
        mx0 = fmaxf(mx0, __shfl_xor_sync(0xffffffffu, mx0, 1));
        mx0 = fmaxf(mx0, __shfl_xor_sync(0xffffffffu, mx0, 2));
        mx1 = fmaxf(mx1, __shfl_xor_sync(0xffffffffu, mx1, 1));
        mx1 = fmaxf(mx1, __shfl_xor_sync(0xffffffffu, mx1, 2));
        float m0n = fmaxf(m0, mx0), m1n = fmaxf(m1, mx1);
        float c0 = exp2f((m0 - m0n)*LOG2E), c1 = exp2f((m1 - m1n)*LOG2E);

        float rs0 = 0.f, rs1 = 0.f;
        uint32_t pfh[4][4];
        #pragma unroll
        for (int kf = 0; kf < 4; kf++) {
            #pragma unroll
            for (int jj = 0; jj < 2; jj++) {
                const int jf = 2*kf + jj;
                float p0 = (s_[jf][0] > -1e29f) ? exp2f((s_[jf][0] - m0n)*LOG2E) : 0.f;
                float p1 = (s_[jf][1] > -1e29f) ? exp2f((s_[jf][1] - m0n)*LOG2E) : 0.f;
                float p2 = (s_[jf][2] > -1e29f) ? exp2f((s_[jf][2] - m1n)*LOG2E) : 0.f;
                float p3 = (s_[jf][3] > -1e29f) ? exp2f((s_[jf][3] - m1n)*LOG2E) : 0.f;
                rs0 += p0 + p1;
                rs1 += p2 + p3;
                __nv_bfloat162 hA(__float2bfloat16(p0), __float2bfloat16(p1));
                __nv_bfloat162 hB(__float2bfloat16(p2), __float2bfloat16(p3));
                pfh[kf][0 + 2*jj] = *(uint32_t*)&hA;
                pfh[kf][1 + 2*jj] = *(uint32_t*)&hB;
            }
        }
        rs0 += __shfl_xor_sync(0xffffffffu, rs0, 1);
        rs0 += __shfl_xor_sync(0xffffffffu, rs0, 2);
        rs1 += __shfl_xor_sync(0xffffffffu, rs1, 1);
        rs1 += __shfl_xor_sync(0xffffffffu, rs1, 2);
        l0 = l0*c0 + rs0;
        l1 = l1*c1 + rs1;
        m0 = m0n; m1 = m1n;
        #pragma unroll
        for (int j = 0; j < 16; j++) {
            o_[j][0] *= c0; o_[j][1] *= c0;
            o_[j][2] *= c1; o_[j][3] *= c1;
        }

        // O += P V  (P bf16, V split hi+lo)
        #pragma unroll
        for (int jp = 0; jp < 8; jp++) {
            #pragma unroll
            for (int kf = 0; kf < 4; kf++) {
                uint32_t ad = kb_ + AVH + (uint32_t)((browB + jp*16)*72 + bcolB + kf*16)*2u;
                uint32_t vh0,vh1,vh2,vh3, vl0,vl1,vl2,vl3;
                LDSM4(vh0,vh1,vh2,vh3, ad);
                LDSM4(vl0,vl1,vl2,vl3, ad + (AVL-AVH));
                uint32_t va[2] = {vh0,vh1}, vb[2] = {vh2,vh3};
                uint32_t wa[2] = {vl0,vl1}, wb[2] = {vl2,vl3};
                MMA_BF16(o_[2*jp],   pfh[kf], va);
                MMA_BF16(o_[2*jp],   pfh[kf], wa);
                MMA_BF16(o_[2*jp+1], pfh[kf], vb);
                MMA_BF16(o_[2*jp+1], pfh[kf], wb);
            }
        }
        __syncthreads();
    }
    #undef LOAD_KV

    const float inv0 = 1.0f / l0;
    const float inv1 = 1.0f / l1;
    const size_t ob0 = ((size_t)(b*Tdim) + t0) * (QH*HD) + h*HD;
    const size_t ob1 = ((size_t)(b*Tdim) + t1) * (QH*HD) + h*HD;
    #pragma unroll
    for (int jn = 0; jn < 16; jn++) {
        int d = jn*8 + cb2;
        float y0 = o_[jn][0]*inv0, y1 = o_[jn][1]*inv0;
        float y2 = o_[jn][2]*inv1, y3 = o_[jn][3]*inv1;
        __nv_bfloat16 h0,lo0,h1,lo1,h2,lo2,h3,lo3;
        split_bf16(y0,h0,lo0); split_bf16(y1,h1,lo1);
        split_bf16(y2,h2,lo2); split_bf16(y3,h3,lo3);
        *(__nv_bfloat162*)(ohi + ob0 + d) = __nv_bfloat162(h0,h1);
        *(__nv_bfloat162*)(olo + ob0 + d) = __nv_bfloat162(lo0,lo1);
        *(__nv_bfloat162*)(ohi + ob1 + d) = __nv_bfloat162(h2,h3);
        *(__nv_bfloat162*)(olo + ob1 + d) = __nv_bfloat162(lo2,lo3);
    }
}

// ---------------------------------------------------------------------------
// launch helper (grid passed explicitly)
// ---------------------------------------------------------------------------
#define LAUNCH_G(g, EPI, BIAS, RES, ...) \
    bgemm_kernel<EPI, BIAS, RES><<<(g), 256, GEMM_SMEM_BYTES>>>(__VA_ARGS__)

extern "C" void kernel_launch(void* const* d_in, const int* in_sizes, int n_in,
                              void* d_out, int out_size) {
    const float* x         = (const float*)d_in[0];
    const float* gn_hawk   = (const float*)d_in[1];
    const float* gn_hgmlp  = (const float*)d_in[2];
    const float* gn_smqa   = (const float*)d_in[3];
    const float* gn_sgmlp  = (const float*)d_in[4];
    const float* hawk_Win  = (const float*)d_in[5];
    const float* hawk_cw   = (const float*)d_in[6];
    const float* hawk_cb   = (const float*)d_in[7];
    const float* hawk_Wg   = (const float*)d_in[8];
    const float* hawk_bg   = (const float*)d_in[9];
    const float* hawk_fb   = (const float*)d_in[10];
    const float* hawk_Wout = (const float*)d_in[11];
    const float* g1_Wgrow  = (const float*)d_in[12];
    const float* g1_Wshr   = (const float*)d_in[13];
    const float* g2_Wgrow  = (const float*)d_in[14];
    const float* g2_Wshr   = (const float*)d_in[15];
    const float* smqa_Wq   = (const float*)d_in[16];
    const float* smqa_Wkv  = (const float*)d_in[17];
    const float* smqa_Wout = (const float*)d_in[18];
    float* out = (float*)d_out;

    float *big, *mid, *small, *chA, *chS, *sIn;
    __nv_bfloat16 *Ahi, *Alo, *Whi, *Wlo;
    cudaGetSymbolAddress((void**)&big,   g_big);
    cudaGetSymbolAddress((void**)&mid,   g_mid);
    cudaGetSymbolAddress((void**)&small, g_small);
    cudaGetSymbolAddress((void**)&Ahi,   g_Ahi);
    cudaGetSymbolAddress((void**)&Alo,   g_Alo);
    cudaGetSymbolAddress((void**)&Whi,   g_Whi);
    cudaGetSymbolAddress((void**)&Wlo,   g_Wlo);
    cudaGetSymbolAddress((void**)&chA,   g_chA);
    cudaGetSymbolAddress((void**)&chS,   g_chS);
    cudaGetSymbolAddress((void**)&sIn,   g_sIn);

    cudaFuncSetAttribute((const void*)attn_hmma_kernel,
                         cudaFuncAttributeMaxDynamicSharedMemorySize, (int)ATT_SMEM);
    cudaFuncSetAttribute((const void*)bgemm_kernel<0,false,false>,
                         cudaFuncAttributeMaxDynamicSharedMemorySize, GEMM_SMEM_BYTES);
    cudaFuncSetAttribute((const void*)bgemm_kernel<0,false,true>,
                         cudaFuncAttributeMaxDynamicSharedMemorySize, GEMM_SMEM_BYTES);
    cudaFuncSetAttribute((const void*)bgemm_kernel<1,false,false>,
                         cudaFuncAttributeMaxDynamicSharedMemorySize, GEMM_SMEM_BYTES);
    cudaFuncSetAttribute((const void*)bgemm_kernel<2,false,false>,
                         cudaFuncAttributeMaxDynamicSharedMemorySize, GEMM_SMEM_BYTES);
    cudaFuncSetAttribute((const void*)bgemm_kernel<3,false,false>,
                         cudaFuncAttributeMaxDynamicSharedMemorySize, GEMM_SMEM_BYTES);
    cudaFuncSetAttribute((const void*)bgemm_kernel<5,false,false>,
                         cudaFuncAttributeMaxDynamicSharedMemorySize, GEMM_SMEM_BYTES);

    const int EW = 256;
    __nv_bfloat16* nb = nullptr;
    float* m8sp = small;   // HID floats

    // weight slices
    __nv_bfloat16* WinH  = Whi + (size_t)W_WIN*4;   __nv_bfloat16* WinL  = Wlo + (size_t)W_WIN*4;
    __nv_bfloat16* WgH   = Whi + (size_t)W_WG*4;    __nv_bfloat16* WgL   = Wlo + (size_t)W_WG*4;
    __nv_bfloat16* WoutH = Whi + (size_t)W_WOUT*4;  __nv_bfloat16* WoutL = Wlo + (size_t)W_WOUT*4;
    __nv_bfloat16* G1gH  = Whi + (size_t)W_G1G*4;   __nv_bfloat16* G1gL  = Wlo + (size_t)W_G1G*4;
    __nv_bfloat16* G1sH  = Whi + (size_t)W_G1S*4;   __nv_bfloat16* G1sL  = Wlo + (size_t)W_G1S*4;
    __nv_bfloat16* G2gH  = Whi + (size_t)W_G2G*4;   __nv_bfloat16* G2gL  = Wlo + (size_t)W_G2G*4;
    __nv_bfloat16* G2sH  = Whi + (size_t)W_G2S*4;   __nv_bfloat16* G2sL  = Wlo + (size_t)W_G2S*4;
    __nv_bfloat16* WqH   = Whi + (size_t)W_Q*4;     __nv_bfloat16* WqL   = Wlo + (size_t)W_Q*4;
    __nv_bfloat16* WkvH  = Whi + (size_t)W_KV*4;    __nv_bfloat16* WkvL  = Wlo + (size_t)W_KV*4;
    __nv_bfloat16* Wo2H  = Whi + (size_t)W_O2*4;    __nv_bfloat16* Wo2L  = Wlo + (size_t)W_O2*4;

    // grids (CTN=128, R12 config)
    const dim3 gridWin((2*HID)/CTN, MROWS/CTM);   // 24 x 64
    const dim3 gridDim_(DIM/CTN, MROWS/CTM);      // 8 x 64
    const dim3 gridGrow((2*GH)/CTN, MROWS/CTM);   // 32 x 64
    const dim3 gridQ((QH*HD)/CTN, MROWS/CTM);     // 8 x 64
    const dim3 gridKV((2*HD)/CTN, MROWS/CTM);     // 2 x 64

    // attn bf16 buffers inside g_mid
    __nv_bfloat16* qhi  = (__nv_bfloat16*)mid;
    __nv_bfloat16* qlo  = (__nv_bfloat16*)(mid + 4194304);
    __nv_bfloat16* khi  = (__nv_bfloat16*)(mid + 8388608);
    __nv_bfloat16* klo  = (__nv_bfloat16*)(mid + 8912896);
    __nv_bfloat16* vthi = (__nv_bfloat16*)(mid + 9437184);
    __nv_bfloat16* vtlo = (__nv_bfloat16*)(mid + 9961472);
    __nv_bfloat16* acth = (__nv_bfloat16*)mid;
    __nv_bfloat16* actl = (__nv_bfloat16*)(mid + 8388608);

    // ---------------- one-shot: convert all weights + m8sp table ----------------
    convw_all_kernel<<<(W_TOT + EW - 1)/EW, EW>>>(
        hawk_Win, hawk_Wg, hawk_Wout, g1_Wgrow, g1_Wshr,
        g2_Wgrow, g2_Wshr, smqa_Wq, smqa_Wkv, smqa_Wout, Whi, Wlo);
    m8sp_kernel<<<(HID + EW - 1)/EW, EW>>>(hawk_fb, m8sp);

    // ---------------- stage 1: hawk ----------------
    rmsnorm_bf16_kernel<<<MROWS, 256>>>(x, gn_hawk, Ahi, Alo);
    LAUNCH_G(gridWin, 0,false,false, Ahi,Alo,WinH,WinL, nullptr,nullptr, big, 2*HID, DIM, nb,nb,nb,nb);
    conv_kernel<<<dim3(Tdim/TCH, Bdim), 384>>>(big, hawk_cw, hawk_cb, Ahi, Alo);
    // Wg GEMM with fused gates: reads hconv (Ahi/Alo) in epilogue, writes {alpha,xs}
    LAUNCH_G(gridWin, 5,false,false, Ahi,Alo,WgH,WgL, hawk_bg, m8sp, mid, 2*HID, HID,
             Ahi, Alo, nb, nb);
    scanA_kernel<<<(Bdim*NCH*HID + EW - 1)/EW, EW>>>(mid, chA, chS);
    scanB_kernel<<<(Bdim*HID + EW - 1)/EW, EW>>>(chA, chS, sIn);
    scanC_kernel<<<(Bdim*NCH*HID + EW - 1)/EW, EW>>>(mid, big, sIn, Ahi, Alo);
    LAUNCH_G(gridDim_, 0,false,true, Ahi,Alo,WoutH,WoutL, nullptr,x, out, DIM, HID, nb,nb,nb,nb);

    // ---------------- stage 2: gated MLP 1 ----------------
    rmsnorm_bf16_kernel<<<MROWS, 256>>>(out, gn_hgmlp, Ahi, Alo);
    LAUNCH_G(gridGrow, 1,false,false, Ahi,Alo,G1gH,G1gL, nullptr,nullptr, nullptr, 2*GH, DIM,
             acth, actl, nb, nb);
    LAUNCH_G(gridDim_, 0,false,true, acth,actl,G1sH,G1sL, nullptr,out, out, DIM, GH, nb,nb,nb,nb);

    // ---------------- stage 3: sliding-window MQA ----------------
    rmsnorm_bf16_kernel<<<MROWS, 256>>>(out, gn_smqa, Ahi, Alo);
    LAUNCH_G(gridQ, 2,false,false, Ahi,Alo,WqH,WqL, nullptr,nullptr, nullptr, QH*HD, DIM,
             qhi, qlo, nb, nb);
    LAUNCH_G(gridKV, 3,false,false, Ahi,Alo,WkvH,WkvL, nullptr,nullptr, nullptr, 2*HD, DIM,
             khi, klo, vthi, vtlo);
    attn_hmma_kernel<<<dim3(Tdim/AQ, QH, Bdim), 256, ATT_SMEM>>>(
        qhi, qlo, khi, klo, vthi, vtlo, Ahi, Alo);
    LAUNCH_G(gridDim_, 0,false,true, Ahi,Alo,Wo2H,Wo2L, nullptr,out, out, DIM, DIM, nb,nb,nb,nb);

    // ---------------- stage 4: gated MLP 2 ----------------
    rmsnorm_bf16_kernel<<<MROWS, 256>>>(out, gn_sgmlp, Ahi, Alo);
    LAUNCH_G(gridGrow, 1,false,false, Ahi,Alo,G2gH,G2gL, nullptr,nullptr, nullptr, 2*GH, DIM,
             acth, actl, nb, nb);
    LAUNCH_G(gridDim_, 0,false,true, acth,actl,G2sH,G2sL, nullptr,out, out, DIM, GH, nb,nb,nb,nb);
}

// round 17
// speedup vs baseline: 1.1088x; 1.0014x over previous
#include <cuda_runtime.h>
#include <cuda_bf16.h>
#include <math.h>
#include <stdint.h>

// ---------------------------------------------------------------------------
// GriffinBlock: HMMA bf16x3 GEMMs (R12 config) + HMMA flash attn
// R17: gelu(gate) fused into Win GEMM epilogue (EPI=6); scanC just multiplies
// B=4, T=2048, DIM=1024, HID=1536, GH=2048, K=4, HD=128, QH=8, W=1024
// ---------------------------------------------------------------------------

#define Bdim 4
#define Tdim 2048
#define DIM 1024
#define HID 1536
#define GH  2048
#define KCONV 4
#define HD  128
#define QH  8
#define WINSZ 1024
#define MROWS (Bdim*Tdim)   // 8192
#define LOG2E 1.4426950408889634f
#define QSCALE 0.088388347648318447f
#define ROT_C (9.210340371976184f / 128.0f)

// ---------------- static scratch ----------------
__device__ float g_big[33554432];      // 8192*4096
__device__ float g_mid[25165824];      // 8192*3072 (hawk gi; act/attn bf16 scratch)
__device__ float g_small[12582912];    // m8sp table lives at [0..HID)
__device__ __nv_bfloat16 g_Ahi[16777216];  // 8192*2048 max
__device__ __nv_bfloat16 g_Alo[16777216];
__device__ __nv_bfloat16 g_Whi[24379392];  // all weights, bf16 hi
__device__ __nv_bfloat16 g_Wlo[24379392];  // all weights, bf16 lo
__device__ float g_chA[98304];
__device__ float g_chS[98304];
__device__ float g_sIn[98304];

// weight slice offsets in float4 units (x4 for elements)
#define W_WIN  0u
#define W_WG   786432u
#define W_WOUT 1966080u
#define W_G1G  2359296u
#define W_G1S  3407872u
#define W_G2G  3932160u
#define W_G2S  4980736u
#define W_Q    5505024u
#define W_KV   5767168u
#define W_O2   5832704u
#define W_TOT  6094848u

__device__ __forceinline__ float gelu_exact(float x) {
    return 0.5f * x * (1.0f + erff(x * 0.70710678118654752f));
}
__device__ __forceinline__ float sigmoidf_(float x) {
    return 1.0f / (1.0f + expf(-x));
}
__device__ __forceinline__ void split_bf16(float v, __nv_bfloat16& h, __nv_bfloat16& l) {
    h = __float2bfloat16(v);
    l = __float2bfloat16(v - __bfloat162float(h));
}

__device__ __forceinline__ uint32_t smem_u32(const void* p) {
    uint32_t a;
    asm("{ .reg .u64 t; cvta.to.shared.u64 t, %1; cvt.u32.u64 %0, t; }" : "=r"(a) : "l"(p));
    return a;
}
__device__ __forceinline__ void cp16(uint32_t dst, const void* src) {
    asm volatile("cp.async.ca.shared.global [%0], [%1], 16;" :: "r"(dst), "l"(src));
}

#define LDSM4(r0, r1, r2, r3, addr) \
    asm volatile("ldmatrix.sync.aligned.m8n8.x4.shared.b16 {%0,%1,%2,%3}, [%4];" \
        : "=r"(r0), "=r"(r1), "=r"(r2), "=r"(r3) : "r"(addr))

#define MMA_BF16(d, a, b) \
    asm volatile("mma.sync.aligned.m16n8k16.row.col.f32.bf16.bf16.f32 " \
        "{%0,%1,%2,%3}, {%4,%5,%6,%7}, {%8,%9}, {%0,%1,%2,%3};" \
        : "+f"((d)[0]), "+f"((d)[1]), "+f"((d)[2]), "+f"((d)[3]) \
        : "r"((a)[0]), "r"((a)[1]), "r"((a)[2]), "r"((a)[3]), \
          "r"((b)[0]), "r"((b)[1]))

// ---------------------------------------------------------------------------
// bf16x3 HMMA GEMM (R12 config): CTA 128x128, warp 32x64, CTK=64, 2-stage.
// EPI: 0 = plain fp32 C (+bias/res), 1 = gelu-gate pair -> bf16 hi/lo,
//      2 = q rotary+scale -> bf16, 3 = kv rotary / v-transpose -> bf16,
//      5 = hawk gates (interleaved Wg): {alpha, xs} float2 -> C,
//      6 = Win: cols<HID -> gelu(v) fp32, cols>=HID -> plain fp32
// ---------------------------------------------------------------------------
#define CTM 128
#define CTN 128
#define CTK 64
#define APITCH 72
#define OFF_SALO_B 18432u
#define OFF_SBHI_B 36864u
#define OFF_SBLO_B 55296u
#define STAGE_BYTES 73728u
#define GEMM_SMEM_BYTES (2u*STAGE_BYTES)  // 147456

template<int EPI, bool HAS_BIAS, bool HAS_RES>
__global__ void __launch_bounds__(256, 1)
bgemm_kernel(const __nv_bfloat16* __restrict__ Ahi, const __nv_bfloat16* __restrict__ Alo,
             const __nv_bfloat16* __restrict__ Whi, const __nv_bfloat16* __restrict__ Wlo,
             const float* __restrict__ bias, const float* __restrict__ res,
             float* __restrict__ C, int N, int K,
             __nv_bfloat16* __restrict__ e0, __nv_bfloat16* __restrict__ e1,
             __nv_bfloat16* __restrict__ e2, __nv_bfloat16* __restrict__ e3) {
    extern __shared__ char smc[];
    const uint32_t sb = smem_u32(smc);
    const int tid = threadIdx.x;
    const int lane = tid & 31;
    const int wid = tid >> 5;
    const int wy = wid & 3;
    const int wx = wid >> 2;
    const int m0 = blockIdx.y * CTM;
    const int n0 = blockIdx.x * CTN;

    const int arow = wy*32 + (lane & 15);
    const int acol = (lane >> 4) * 8;
    const uint32_t aoff = (uint32_t)(arow*APITCH + acol) * 2u;
    const int g  = lane >> 3;
    const int rr = lane & 7;
    const int brow = wx*64 + rr + ((g >> 1) << 3);
    const int bcol = (g & 1) * 8;
    const uint32_t boff = (uint32_t)(brow*APITCH + bcol) * 2u;

    float acc[2][8][4];
    #pragma unroll
    for (int i = 0; i < 2; i++)
        #pragma unroll
        for (int j = 0; j < 8; j++)
            #pragma unroll
            for (int v = 0; v < 4; v++) acc[i][j][v] = 0.f;

    const int NC = K / CTK;

    #define LOAD_STAGE(stg, kb) do { \
        uint32_t sbase_ = sb + (stg)*STAGE_BYTES; \
        _Pragma("unroll") \
        for (int it_ = 0; it_ < 4; it_++) { \
            int u_ = tid + it_*256; \
            int r_ = u_ >> 3; \
            int c_ = u_ & 7; \
            uint32_t d_ = sbase_ + (uint32_t)r_*144u + (uint32_t)c_*16u; \
            size_t ga_ = (size_t)(m0 + r_) * K + (kb) + c_*8; \
            size_t gb_ = (size_t)(n0 + r_) * K + (kb) + c_*8; \
            cp16(d_,              Ahi + ga_); \
            cp16(d_ + OFF_SALO_B, Alo + ga_); \
            cp16(d_ + OFF_SBHI_B, Whi + gb_); \
            cp16(d_ + OFF_SBLO_B, Wlo + gb_); \
        } \
        asm volatile("cp.async.commit_group;"); \
    } while (0)

    LOAD_STAGE(0, 0);

    for (int ch = 0; ch < NC; ch++) {
        const int stg = ch & 1;
        if (ch + 1 < NC) {
            LOAD_STAGE(stg ^ 1, (ch + 1) * CTK);
            asm volatile("cp.async.wait_group 1;");
        } else {
            asm volatile("cp.async.wait_group 0;");
        }
        __syncthreads();

        const uint32_t sbase = sb + stg * STAGE_BYTES;
        #pragma unroll
        for (int k16 = 0; k16 < 4; k16++) {
            uint32_t ah[2][4], al[2][4], bh[8][2], bl[8][2];
            #pragma unroll
            for (int mt = 0; mt < 2; mt++) {
                uint32_t ad = sbase + aoff + (uint32_t)mt*(16*APITCH*2) + (uint32_t)k16*32u;
                LDSM4(ah[mt][0], ah[mt][1], ah[mt][2], ah[mt][3], ad);
                LDSM4(al[mt][0], al[mt][1], al[mt][2], al[mt][3], ad + OFF_SALO_B);
            }
            #pragma unroll
            for (int jp = 0; jp < 4; jp++) {
                uint32_t bd = sbase + boff + (uint32_t)jp*(16*APITCH*2) + (uint32_t)k16*32u;
                LDSM4(bh[2*jp][0], bh[2*jp][1], bh[2*jp+1][0], bh[2*jp+1][1], bd + OFF_SBHI_B);
                LDSM4(bl[2*jp][0], bl[2*jp][1], bl[2*jp+1][0], bl[2*jp+1][1], bd + OFF_SBLO_B);
            }
            #pragma unroll
            for (int mt = 0; mt < 2; mt++)
                #pragma unroll
                for (int j = 0; j < 8; j++) {
                    MMA_BF16(acc[mt][j], ah[mt], bh[j]);
                    MMA_BF16(acc[mt][j], ah[mt], bl[j]);
                    MMA_BF16(acc[mt][j], al[mt], bh[j]);
                }
        }
        __syncthreads();
    }
    #undef LOAD_STAGE

    // ---- epilogues ----
    const int rbase = m0 + wy*32 + (lane >> 2);
    const int cbase = wx*64 + (lane & 3)*2;   // tile-local, even
    #pragma unroll
    for (int mt = 0; mt < 2; mt++) {
        #pragma unroll
        for (int half = 0; half < 2; half++) {
            const int row = rbase + mt*16 + half*8;
            #pragma unroll
            for (int j = 0; j < 8; j++) {
                const int coll = cbase + j*8;     // local col (even)
                const int col  = n0 + coll;       // global col
                float v0 = acc[mt][j][half*2 + 0];
                float v1 = acc[mt][j][half*2 + 1];
                if (EPI == 0) {
                    if (HAS_BIAS) { v0 += bias[col]; v1 += bias[col + 1]; }
                    if (HAS_RES) {
                        const float2 rv = *(const float2*)(res + (size_t)row * N + col);
                        v0 += rv.x; v1 += rv.y;
                    }
                    float2 o; o.x = v0; o.y = v1;
                    *(float2*)(C + (size_t)row * N + col) = o;
                } else if (EPI == 1) {
                    float y = gelu_exact(v0) * v1;
                    __nv_bfloat16 hh, ll; split_bf16(y, hh, ll);
                    size_t o = (size_t)row * GH + (col >> 1);
                    e0[o] = hh; e1[o] = ll;
                } else if (EPI == 2) {
                    int d = col & (HD - 1);
                    int hh_ = col >> 7;
                    int t = row & (Tdim - 1);
                    int b = row >> 11;
                    float inv = expf(-(float)d * ROT_C);
                    float sn, cs; sincosf((float)t * inv, &sn, &cs);
                    float y0 = (v0*cs - v1*sn) * QSCALE;
                    float y1 = (v1*cs + v0*sn) * QSCALE;
                    __nv_bfloat16 h0,l0,h1,l1;
                    split_bf16(y0,h0,l0); split_bf16(y1,h1,l1);
                    size_t o = (((size_t)(b*QH + hh_)) * Tdim + t) * HD + d;
                    *(__nv_bfloat162*)(e0 + o) = __nv_bfloat162(h0,h1);
                    *(__nv_bfloat162*)(e1 + o) = __nv_bfloat162(l0,l1);
                } else if (EPI == 3) {
                    int t = row & (Tdim - 1);
                    int b = row >> 11;
                    if (col < HD) {
                        int d = col;
                        float inv = expf(-(float)d * ROT_C);
                        float sn, cs; sincosf((float)t * inv, &sn, &cs);
                        float y0 = v0*cs - v1*sn;
                        float y1 = v1*cs + v0*sn;
                        __nv_bfloat16 h0,l0,h1,l1;
                        split_bf16(y0,h0,l0); split_bf16(y1,h1,l1);
                        size_t o = (size_t)row * HD + d;
                        *(__nv_bfloat162*)(e0 + o) = __nv_bfloat162(h0,h1);
                        *(__nv_bfloat162*)(e1 + o) = __nv_bfloat162(l0,l1);
                    } else {
                        int d = col - HD;
                        __nv_bfloat16 h0,l0,h1,l1;
                        split_bf16(v0,h0,l0); split_bf16(v1,h1,l1);
                        size_t o0 = ((size_t)(b*HD + d)) * Tdim + t;
                        size_t o1 = ((size_t)(b*HD + d + 1)) * Tdim + t;
                        e2[o0] = h0; e3[o0] = l0;
                        e2[o1] = h1; e3[o1] = l1;
                    }
                } else if (EPI == 5) {
                    // hawk gates. col even pair = channel c.
                    int c = col >> 1;
                    float f  = v0 + bias[c];
                    float ip = v1 + bias[HID + c];
                    size_t ho = (size_t)row * HID + c;
                    float h = __bfloat162float(e0[ho]) + __bfloat162float(e1[ho]);
                    float alpha = expf(res[c] * sigmoidf_(f));
                    float beta  = sqrtf(1.0f - alpha*alpha + 1e-6f);
                    float xs = beta * sigmoidf_(ip) * h;
                    float2 o; o.x = alpha; o.y = xs;
                    *(float2*)(C + (size_t)row * N + col) = o;
                } else {
                    // EPI == 6: Win. gate cols (<HID) -> gelu, h cols plain.
                    if (col < HID) { v0 = gelu_exact(v0); v1 = gelu_exact(v1); }
                    float2 o; o.x = v0; o.y = v1;
                    *(float2*)(C + (size_t)row * N + col) = o;
                }
            }
        }
    }
}

// ---------------------------------------------------------------------------
// ONE-SHOT weight conversion. grow weights: gate/h row-interleaved (DIM cols).
// Wg weights: forget/inp row-interleaved (HID cols).
// ---------------------------------------------------------------------------
__device__ __forceinline__ void conv_store(__nv_bfloat16* hi, __nv_bfloat16* lo,
                                           uint32_t dst4, float4 v) {
    __nv_bfloat16 h0, h1, h2, h3, l0, l1, l2, l3;
    split_bf16(v.x, h0, l0); split_bf16(v.y, h1, l1);
    split_bf16(v.z, h2, l2); split_bf16(v.w, h3, l3);
    __nv_bfloat162* hp = (__nv_bfloat162*)hi;
    __nv_bfloat162* lp = (__nv_bfloat162*)lo;
    hp[2*(size_t)dst4]   = __nv_bfloat162(h0, h1);
    hp[2*(size_t)dst4+1] = __nv_bfloat162(h2, h3);
    lp[2*(size_t)dst4]   = __nv_bfloat162(l0, l1);
    lp[2*(size_t)dst4+1] = __nv_bfloat162(l2, l3);
}

__global__ void convw_all_kernel(
    const float* __restrict__ win, const float* __restrict__ wg,
    const float* __restrict__ wout, const float* __restrict__ g1g,
    const float* __restrict__ g1s, const float* __restrict__ g2g,
    const float* __restrict__ g2s, const float* __restrict__ wq,
    const float* __restrict__ wkv, const float* __restrict__ wo2,
    __nv_bfloat16* __restrict__ hi, __nv_bfloat16* __restrict__ lo) {
    uint32_t i = blockIdx.x * blockDim.x + threadIdx.x;
    if (i >= W_TOT) return;
    const float* src;
    uint32_t base, local;
    int ilv = 0;   // 0 none, 1 = grow (DIM cols, GH half), 2 = Wg (HID cols, HID half)
    if      (i < W_WG)   { src = win;  base = W_WIN;  }
    else if (i < W_WOUT) { src = wg;   base = W_WG;   ilv = 2; }
    else if (i < W_G1G)  { src = wout; base = W_WOUT; }
    else if (i < W_G1S)  { src = g1g;  base = W_G1G;  ilv = 1; }
    else if (i < W_G2G)  { src = g1s;  base = W_G1S;  }
    else if (i < W_G2S)  { src = g2g;  base = W_G2G;  ilv = 1; }
    else if (i < W_Q)    { src = g2s;  base = W_G2S;  }
    else if (i < W_KV)   { src = wq;   base = W_Q;    }
    else if (i < W_O2)   { src = wkv;  base = W_KV;   }
    else                 { src = wo2;  base = W_O2;   }
    local = i - base;
    float4 v = ((const float4*)src)[local];
    uint32_t dlocal = local;
    if (ilv == 1) {
        uint32_t r  = local >> 8;          // DIM/4 = 256 float4 per row
        uint32_t c4 = local & 255u;
        uint32_t rp = (r < GH) ? (2u*r) : (2u*(r - GH) + 1u);
        dlocal = rp*256u + c4;
    } else if (ilv == 2) {
        uint32_t r  = local / 384u;        // HID/4 = 384 float4 per row
        uint32_t c4 = local % 384u;
        uint32_t rp = (r < HID) ? (2u*r) : (2u*(r - HID) + 1u);
        dlocal = rp*384u + c4;
    }
    conv_store(hi, lo, base + dlocal, v);
}

// ---------------------------------------------------------------------------
// m8sp table: m8sp[c] = -8 * softplus(fb[c])
// ---------------------------------------------------------------------------
__global__ void m8sp_kernel(const float* __restrict__ fb, float* __restrict__ out) {
    int c = blockIdx.x * blockDim.x + threadIdx.x;
    if (c < HID) out[c] = -8.0f * log1pf(expf(fb[c]));
}

// ---------------------------------------------------------------------------
// RMSNorm -> bf16 hi/lo
// ---------------------------------------------------------------------------
__global__ void rmsnorm_bf16_kernel(const float* __restrict__ x,
                                    const float* __restrict__ gamma,
                                    __nv_bfloat16* __restrict__ hi,
                                    __nv_bfloat16* __restrict__ lo) {
    int row = blockIdx.x;
    int tid = threadIdx.x;
    float4 v = ((const float4*)(x + (size_t)row * DIM))[tid];
    float ss = v.x*v.x + v.y*v.y + v.z*v.z + v.w*v.w;
    #pragma unroll
    for (int o = 16; o; o >>= 1) ss += __shfl_xor_sync(0xffffffffu, ss, o);
    __shared__ float red[8];
    __shared__ float stot;
    if ((tid & 31) == 0) red[tid >> 5] = ss;
    __syncthreads();
    if (tid == 0) {
        float s = 0.f;
        #pragma unroll
        for (int i = 0; i < 8; i++) s += red[i];
        stot = s;
    }
    __syncthreads();
    float scale = 32.0f * rsqrtf(stot);
    float4 g = ((const float4*)gamma)[tid];
    float o0 = v.x*scale*g.x, o1 = v.y*scale*g.y, o2 = v.z*scale*g.z, o3 = v.w*scale*g.w;
    __nv_bfloat16 h0,h1,h2,h3,l0,l1,l2,l3;
    split_bf16(o0,h0,l0); split_bf16(o1,h1,l1); split_bf16(o2,h2,l2); split_bf16(o3,h3,l3);
    __nv_bfloat162* hp = (__nv_bfloat162*)(hi + (size_t)row * DIM);
    __nv_bfloat162* lp = (__nv_bfloat162*)(lo + (size_t)row * DIM);
    hp[2*tid]   = __nv_bfloat162(h0,h1);
    hp[2*tid+1] = __nv_bfloat162(h2,h3);
    lp[2*tid]   = __nv_bfloat162(l0,l1);
    lp[2*tid+1] = __nv_bfloat162(l2,l3);
}

// ---------------------------------------------------------------------------
// hawk depthwise causal conv (K=4), sliding-window; bf16 hi/lo output
// NOTE: gh h-columns are NOT gelu'd by EPI=6 (cols >= HID pass through).
// ---------------------------------------------------------------------------
#define TCH 32
__global__ void __launch_bounds__(384)
conv_kernel(const float* __restrict__ gh,
            const float* __restrict__ cw,
            const float* __restrict__ cb,
            __nv_bfloat16* __restrict__ hi,
            __nv_bfloat16* __restrict__ lo) {
    __shared__ float scw[HID*KCONV];
    const int tb = blockIdx.x;
    const int b  = blockIdx.y;
    const int c4 = threadIdx.x;
    const int c  = c4 * 4;
    for (int i = threadIdx.x; i < (HID*KCONV)/4; i += 384)
        ((float4*)scw)[i] = ((const float4*)cw)[i];
    __syncthreads();
    float w[4][4];
    #pragma unroll
    for (int i = 0; i < 4; i++)
        #pragma unroll
        for (int k = 0; k < 4; k++) w[i][k] = scw[(c+i)*KCONV + k];
    const float4 bias = ((const float4*)cb)[c4];
    const int t0 = tb * TCH;
    float4 win[4];
    #pragma unroll
    for (int k = 0; k < 3; k++) {
        int tt = t0 - 3 + k;
        win[k] = make_float4(0.f, 0.f, 0.f, 0.f);
        if (tt >= 0)
            win[k] = *(const float4*)(gh + (size_t)(b*Tdim + tt)*(2*HID) + HID + c);
    }
    for (int dt = 0; dt < TCH; dt++) {
        const int t = t0 + dt;
        win[3] = *(const float4*)(gh + (size_t)(b*Tdim + t)*(2*HID) + HID + c);
        float4 acc = bias;
        #pragma unroll
        for (int k = 0; k < 4; k++) {
            acc.x = fmaf(w[0][k], win[k].x, acc.x);
            acc.y = fmaf(w[1][k], win[k].y, acc.y);
            acc.z = fmaf(w[2][k], win[k].z, acc.z);
            acc.w = fmaf(w[3][k], win[k].w, acc.w);
        }
        const size_t bt = (size_t)(b*Tdim + t);
        __nv_bfloat16 h0,h1,h2,h3,l0,l1,l2,l3;
        split_bf16(acc.x,h0,l0); split_bf16(acc.y,h1,l1);
        split_bf16(acc.z,h2,l2); split_bf16(acc.w,h3,l3);
        __nv_bfloat162* hp = (__nv_bfloat162*)(hi + bt * HID + c);
        __nv_bfloat162* lp = (__nv_bfloat162*)(lo + bt * HID + c);
        hp[0] = __nv_bfloat162(h0,h1);
        hp[1] = __nv_bfloat162(h2,h3);
        lp[0] = __nv_bfloat162(l0,l1);
        lp[1] = __nv_bfloat162(l2,l3);
        win[0] = win[1]; win[1] = win[2]; win[2] = win[3];
    }
}

// ---------------------------------------------------------------------------
// chunked parallel scan over {alpha, xs} float2 pairs (gi interleaved layout)
// scanC reads PRE-GELU'd gate values from gh (EPI=6 applied gelu already).
// ---------------------------------------------------------------------------
#define SCH 128
#define NCH 16
__global__ void scanA_kernel(const float* __restrict__ gi,
                             float* __restrict__ chA, float* __restrict__ chS) {
    int idx = blockIdx.x * blockDim.x + threadIdx.x;
    if (idx >= Bdim * NCH * HID) return;
    int c = idx % HID;
    int r = idx / HID;
    int ch = r & (NCH - 1);
    int b  = r >> 4;
    size_t base = ((size_t)b * Tdim + ch * SCH) * (2*HID) + 2*c;
    float ap = 1.f, s = 0.f;
    for (int t = 0; t < SCH; t++) {
        float2 axs = *(const float2*)(gi + base + (size_t)t * (2*HID));
        s = fmaf(axs.x, s, axs.y);
        ap *= axs.x;
    }
    chA[idx] = ap;
    chS[idx] = s;
}
__global__ void scanB_kernel(const float* __restrict__ chA, const float* __restrict__ chS,
                             float* __restrict__ sIn) {
    int idx = blockIdx.x * blockDim.x + threadIdx.x;
    if (idx >= Bdim * HID) return;
    int c = idx % HID;
    int b = idx / HID;
    float s = 0.f;
    #pragma unroll
    for (int ch = 0; ch < NCH; ch++) {
        size_t o = ((size_t)(b * NCH + ch)) * HID + c;
        sIn[o] = s;
        s = fmaf(chA[o], s, chS[o]);
    }
}
__global__ void scanC_kernel(const float* __restrict__ gi, const float* __restrict__ gh,
                             const float* __restrict__ sIn,
                             __nv_bfloat16* __restrict__ hi, __nv_bfloat16* __restrict__ lo) {
    int idx = blockIdx.x * blockDim.x + threadIdx.x;
    if (idx >= Bdim * NCH * HID) return;
    int c = idx % HID;
    int r = idx / HID;
    int ch = r & (NCH - 1);
    int b  = r >> 4;
    float st = sIn[idx];
    size_t gbase = ((size_t)b * Tdim + ch * SCH) * (2*HID);
    size_t ob    = ((size_t)b * Tdim + ch * SCH) * HID + c;
    for (int t = 0; t < SCH; t++) {
        size_t o = gbase + (size_t)t * (2*HID);
        float2 axs = *(const float2*)(gi + o + 2*c);
        float g = gh[o + c];            // already gelu'd by EPI=6
        st = fmaf(axs.x, st, axs.y);
        float y = g * st;
        __nv_bfloat16 h, l; split_bf16(y, h, l);
        hi[ob + (size_t)t * HID] = h;
        lo[ob + (size_t)t * HID] = l;
    }
}

// ---------------------------------------------------------------------------
// HMMA flash attention (unchanged from R12): bf16x3 QK^T, PV hi-only P
// ---------------------------------------------------------------------------
#define AQ 128
#define AQH_OFF 0u
#define AQL_OFF 34816u
#define AST_OFF 69632u
#define AKH 0u
#define AKL 17408u
#define AVH 34816u
#define AVL 53248u
#define ASTAGE 71680u
#define ATT_SMEM (69632u + 2u*71680u)   // 212992

__global__ void __launch_bounds__(256, 1)
attn_hmma_kernel(const __nv_bfloat16* __restrict__ qhi, const __nv_bfloat16* __restrict__ qlo,
                 const __nv_bfloat16* __restrict__ khi, const __nv_bfloat16* __restrict__ klo,
                 const __nv_bfloat16* __restrict__ vthi, const __nv_bfloat16* __restrict__ vtlo,
                 __nv_bfloat16* __restrict__ ohi, __nv_bfloat16* __restrict__ olo) {
    extern __shared__ char smc[];
    const uint32_t sb = smem_u32(smc);
    const int tid  = threadIdx.x;
    const int lane = tid & 31;
    const int w    = tid >> 5;
    const int b  = blockIdx.z;
    const int h  = blockIdx.y;
    const int q0 = blockIdx.x * AQ;

    {
        const __nv_bfloat16* qh_ = qhi + ((size_t)(b*QH + h) * Tdim + q0) * HD;
        const __nv_bfloat16* ql_ = qlo + ((size_t)(b*QH + h) * Tdim + q0) * HD;
        #pragma unroll
        for (int it = 0; it < 8; it++) {
            int u = tid + it*256;
            int r = u >> 4, c = u & 15;
            uint32_t d = sb + AQH_OFF + (uint32_t)r*272u + (uint32_t)c*16u;
            cp16(d,           qh_ + (size_t)r*HD + c*8);
            cp16(d + AQL_OFF, ql_ + (size_t)r*HD + c*8);
        }
        asm volatile("cp.async.commit_group;");
    }

    const int ks0 = (q0 >= WINSZ) ? (q0 - WINSZ) : 0;
    const int nt  = (q0 + AQ - ks0) >> 6;

    #define LOAD_KV(stg, ks) do { \
        uint32_t sbase_ = sb + AST_OFF + (uint32_t)(stg)*ASTAGE; \
        const __nv_bfloat16* kh_ = khi + ((size_t)b*Tdim + (ks))*HD; \
        const __nv_bfloat16* kl_ = klo + ((size_t)b*Tdim + (ks))*HD; \
        const __nv_bfloat16* vh_ = vthi + (size_t)b*HD*Tdim + (ks); \
        const __nv_bfloat16* vl_ = vtlo + (size_t)b*HD*Tdim + (ks); \
        _Pragma("unroll") \
        for (int it_ = 0; it_ < 4; it_++) { \
            int u_ = tid + it_*256; \
            int r_ = u_ >> 4, c_ = u_ & 15; \
            uint32_t d_ = sbase_ + AKH + (uint32_t)r_*272u + (uint32_t)c_*16u; \
            cp16(d_,             kh_ + (size_t)r_*HD + c_*8); \
            cp16(d_ + (AKL-AKH), kl_ + (size_t)r_*HD + c_*8); \
            int r2_ = u_ >> 3, c2_ = u_ & 7; \
            uint32_t d2_ = sbase_ + AVH + (uint32_t)r2_*144u + (uint32_t)c2_*16u; \
            cp16(d2_,            vh_ + (size_t)r2_*Tdim + c2_*8); \
            cp16(d2_ + (AVL-AVH), vl_ + (size_t)r2_*Tdim + c2_*8); \
        } \
        asm volatile("cp.async.commit_group;"); \
    } while (0)

    LOAD_KV(0, ks0);
    asm volatile("cp.async.wait_group 1;");
    __syncthreads();

    uint32_t qfh[8][4], qfl[8][4];
    {
        const int arow = w*16 + (lane & 15);
        const int acol = (lane >> 4) * 8;
        uint32_t abase = sb + AQH_OFF + (uint32_t)(arow*136 + acol)*2u;
        #pragma unroll
        for (int k = 0; k < 8; k++) {
            LDSM4(qfh[k][0],qfh[k][1],qfh[k][2],qfh[k][3], abase + (uint32_t)k*32u);
            LDSM4(qfl[k][0],qfl[k][1],qfl[k][2],qfl[k][3], abase + AQL_OFF + (uint32_t)k*32u);
        }
    }

    float o_[16][4];
    #pragma unroll
    for (int j = 0; j < 16; j++)
        #pragma unroll
        for (int v = 0; v < 4; v++) o_[j][v] = 0.f;
    float m0 = -1e30f, m1 = -1e30f, l0 = 0.f, l1 = 0.f;

    const int t0 = q0 + w*16 + (lane >> 2);
    const int t1 = t0 + 8;
    const int cb2 = (lane & 3)*2;
    const int gB  = lane >> 3;
    const int rrB = lane & 7;
    const int browB = rrB + ((gB >> 1) << 3);
    const int bcolB = (gB & 1) * 8;

    for (int i = 0; i < nt; i++) {
        const int stg = i & 1;
        if (i + 1 < nt) {
            LOAD_KV(stg ^ 1, ks0 + (i+1)*64);
            asm volatile("cp.async.wait_group 1;");
        } else {
            asm volatile("cp.async.wait_group 0;");
        }
        __syncthreads();
        const uint32_t kb_ = sb + AST_OFF + (uint32_t)stg*ASTAGE;
        const int ks = ks0 + i*64;

        float s_[8][4];
        #pragma unroll
        for (int j = 0; j < 8; j++)
            #pragma unroll
            for (int v = 0; v < 4; v++) s_[j][v] = 0.f;
        #pragma unroll
        for (int jp = 0; jp < 4; jp++) {
            #pragma unroll
            for (int k = 0; k < 8; k++) {
                uint32_t ad = kb_ + AKH + (uint32_t)((browB + jp*16)*136 + bcolB + k*16)*2u;
                uint32_t bh0,bh1,bh2,bh3, bl0,bl1,bl2,bl3;
                LDSM4(bh0,bh1,bh2,bh3, ad);
                LDSM4(bl0,bl1,bl2,bl3, ad + (AKL-AKH));
                uint32_t ba[2] = {bh0,bh1}, bb[2] = {bh2,bh3};
                uint32_t la[2] = {bl0,bl1}, lb[2] = {bl2,bl3};
                MMA_BF16(s_[2*jp],   qfh[k], ba);
                MMA_BF16(s_[2*jp],   qfl[k], ba);
                MMA_BF16(s_[2*jp],   qfh[k], la);
                MMA_BF16(s_[2*jp+1], qfh[k], bb);
                MMA_BF16(s_[2*jp+1], qfl[k], bb);
                MMA_BF16(s_[2*jp+1], qfh[k], lb);
            }
        }

        float mx0 = -1e30f, mx1 = -1e30f;
        #pragma unroll
        for (int jf = 0; jf < 8; jf++) {
            #pragma unroll
            for (int cc = 0; cc < 2; cc++) {
                int g = ks + jf*8 + cb2 + cc;
                if (!(g <= t0 && g >= t0 - WINSZ)) s_[jf][cc]   = -1e30f;
                if (!(g <= t1 && g >= t1 - WINSZ)) s_[jf][2+cc] = -1e30f;
            }
            mx0 = fmaxf(mx0, fmaxf(s_[jf][0], s_[jf][1]));
            mx1 = fmaxf(mx1, fmaxf(s_[jf][2], s_[jf][3]));
        }
        mx0 = fmaxf(mx0, __shfl_xor_sync(0xffffffffu, mx0, 1));
        mx0 = fmaxf(mx0, __shfl_xor_sync(0xffffffffu, mx0, 2));
        mx1 = fmaxf(mx1, __shfl_xor_sync(0xffffffffu, mx1, 1));
        mx1 = fmaxf(mx1, __shfl_xor_sync(0xffffffffu, mx1, 2));
        float m0n = fmaxf(m0, mx0), m1n = fmaxf(m1, mx1);
        float c0 = exp2f((m0 - m0n)*LOG2E), c1 = exp2f((m1 - m1n)*LOG2E);

        float rs0 = 0.f, rs1 = 0.f;
        uint32_t pfh[4][4];
        #pragma unroll
        for (int kf = 0; kf < 4; kf++) {
            #pragma unroll
            for (int jj = 0; jj < 2; jj++) {
                const int jf = 2*kf + jj;
                float p0 = (s_[jf][0] > -1e29f) ? exp2f((s_[jf][0] - m0n)*LOG2E) : 0.f;
                float p1 = (s_[jf][1] > -1e29f) ? exp2f((s_[jf][1] - m0n)*LOG2E) : 0.f;
                float p2 = (s_[jf][2] > -1e29f) ? exp2f((s_[jf][2] - m1n)*LOG2E) : 0.f;
                float p3 = (s_[jf][3] > -1e29f) ? exp2f((s_[jf][3] - m1n)*LOG2E) : 0.f;
                rs0 += p0 + p1;
                rs1 += p2 + p3;
                __nv_bfloat162 hA(__float2bfloat16(p0), __float2bfloat16(p1));
                __nv_bfloat162 hB(__float2bfloat16(p2), __float2bfloat16(p3));
                pfh[kf][0 + 2*jj] = *(uint32_t*)&hA;
                pfh[kf][1 + 2*jj] = *(uint32_t*)&hB;
            }
        }
        rs0 += __shfl_xor_sync(0xffffffffu, rs0, 1);
        rs0 += __shfl_xor_sync(0xffffffffu, rs0, 2);
        rs1 += __shfl_xor_sync(0xffffffffu, rs1, 1);
        rs1 += __shfl_xor_sync(0xffffffffu, rs1, 2);
        l0 = l0*c0 + rs0;
        l1 = l1*c1 + rs1;
        m0 = m0n; m1 = m1n;
        #pragma unroll
        for (int j = 0; j < 16; j++) {
            o_[j][0] *= c0; o_[j][1] *= c0;
            o_[j][2] *= c1; o_[j][3] *= c1;
        }

        // O += P V  (P bf16, V split hi+lo)
        #pragma unroll
        for (int jp = 0; jp < 8; jp++) {
            #pragma unroll
            for (int kf = 0; kf < 4; kf++) {
                uint32_t ad = kb_ + AVH + (uint32_t)((browB + jp*16)*72 + bcolB + kf*16)*2u;
                uint32_t vh0,vh1,vh2,vh3, vl0,vl1,vl2,vl3;
                LDSM4(vh0,vh1,vh2,vh3, ad);
                LDSM4(vl0,vl1,vl2,vl3, ad + (AVL-AVH));
                uint32_t va[2] = {vh0,vh1}, vb[2] = {vh2,vh3};
                uint32_t wa[2] = {vl0,vl1}, wb[2] = {vl2,vl3};
                MMA_BF16(o_[2*jp],   pfh[kf], va);
                MMA_BF16(o_[2*jp],   pfh[kf], wa);
                MMA_BF16(o_[2*jp+1], pfh[kf], vb);
                MMA_BF16(o_[2*jp+1], pfh[kf], wb);
            }
        }
        __syncthreads();
    }
    #undef LOAD_KV

    const float inv0 = 1.0f / l0;
    const float inv1 = 1.0f / l1;
    const size_t ob0 = ((size_t)(b*Tdim) + t0) * (QH*HD) + h*HD;
    const size_t ob1 = ((size_t)(b*Tdim) + t1) * (QH*HD) + h*HD;
    #pragma unroll
    for (int jn = 0; jn < 16; jn++) {
        int d = jn*8 + cb2;
        float y0 = o_[jn][0]*inv0, y1 = o_[jn][1]*inv0;
        float y2 = o_[jn][2]*inv1, y3 = o_[jn][3]*inv1;
        __nv_bfloat16 h0,lo0,h1,lo1,h2,lo2,h3,lo3;
        split_bf16(y0,h0,lo0); split_bf16(y1,h1,lo1);
        split_bf16(y2,h2,lo2); split_bf16(y3,h3,lo3);
        *(__nv_bfloat162*)(ohi + ob0 + d) = __nv_bfloat162(h0,h1);
        *(__nv_bfloat162*)(olo + ob0 + d) = __nv_bfloat162(lo0,lo1);
        *(__nv_bfloat162*)(ohi + ob1 + d) = __nv_bfloat162(h2,h3);
        *(__nv_bfloat162*)(olo + ob1 + d) = __nv_bfloat162(lo2,lo3);
    }
}

// ---------------------------------------------------------------------------
// launch helper (grid passed explicitly)
// ---------------------------------------------------------------------------
#define LAUNCH_G(g, EPI, BIAS, RES, ...) \
    bgemm_kernel<EPI, BIAS, RES><<<(g), 256, GEMM_SMEM_BYTES>>>(__VA_ARGS__)

extern "C" void kernel_launch(void* const* d_in, const int* in_sizes, int n_in,
                              void* d_out, int out_size) {
    const float* x         = (const float*)d_in[0];
    const float* gn_hawk   = (const float*)d_in[1];
    const float* gn_hgmlp  = (const float*)d_in[2];
    const float* gn_smqa   = (const float*)d_in[3];
    const float* gn_sgmlp  = (const float*)d_in[4];
    const float* hawk_Win  = (const float*)d_in[5];
    const float* hawk_cw   = (const float*)d_in[6];
    const float* hawk_cb   = (const float*)d_in[7];
    const float* hawk_Wg   = (const float*)d_in[8];
    const float* hawk_bg   = (const float*)d_in[9];
    const float* hawk_fb   = (const float*)d_in[10];
    const float* hawk_Wout = (const float*)d_in[11];
    const float* g1_Wgrow  = (const float*)d_in[12];
    const float* g1_Wshr   = (const float*)d_in[13];
    const float* g2_Wgrow  = (const float*)d_in[14];
    const float* g2_Wshr   = (const float*)d_in[15];
    const float* smqa_Wq   = (const float*)d_in[16];
    const float* smqa_Wkv  = (const float*)d_in[17];
    const float* smqa_Wout = (const float*)d_in[18];
    float* out = (float*)d_out;

    float *big, *mid, *small, *chA, *chS, *sIn;
    __nv_bfloat16 *Ahi, *Alo, *Whi, *Wlo;
    cudaGetSymbolAddress((void**)&big,   g_big);
    cudaGetSymbolAddress((void**)&mid,   g_mid);
    cudaGetSymbolAddress((void**)&small, g_small);
    cudaGetSymbolAddress((void**)&Ahi,   g_Ahi);
    cudaGetSymbolAddress((void**)&Alo,   g_Alo);
    cudaGetSymbolAddress((void**)&Whi,   g_Whi);
    cudaGetSymbolAddress((void**)&Wlo,   g_Wlo);
    cudaGetSymbolAddress((void**)&chA,   g_chA);
    cudaGetSymbolAddress((void**)&chS,   g_chS);
    cudaGetSymbolAddress((void**)&sIn,   g_sIn);

    cudaFuncSetAttribute((const void*)attn_hmma_kernel,
                         cudaFuncAttributeMaxDynamicSharedMemorySize, (int)ATT_SMEM);
    cudaFuncSetAttribute((const void*)bgemm_kernel<0,false,false>,
                         cudaFuncAttributeMaxDynamicSharedMemorySize, GEMM_SMEM_BYTES);
    cudaFuncSetAttribute((const void*)bgemm_kernel<0,false,true>,
                         cudaFuncAttributeMaxDynamicSharedMemorySize, GEMM_SMEM_BYTES);
    cudaFuncSetAttribute((const void*)bgemm_kernel<1,false,false>,
                         cudaFuncAttributeMaxDynamicSharedMemorySize, GEMM_SMEM_BYTES);
    cudaFuncSetAttribute((const void*)bgemm_kernel<2,false,false>,
                         cudaFuncAttributeMaxDynamicSharedMemorySize, GEMM_SMEM_BYTES);
    cudaFuncSetAttribute((const void*)bgemm_kernel<3,false,false>,
                         cudaFuncAttributeMaxDynamicSharedMemorySize, GEMM_SMEM_BYTES);
    cudaFuncSetAttribute((const void*)bgemm_kernel<5,false,false>,
                         cudaFuncAttributeMaxDynamicSharedMemorySize, GEMM_SMEM_BYTES);
    cudaFuncSetAttribute((const void*)bgemm_kernel<6,false,false>,
                         cudaFuncAttributeMaxDynamicSharedMemorySize, GEMM_SMEM_BYTES);

    const int EW = 256;
    __nv_bfloat16* nb = nullptr;
    float* m8sp = small;   // HID floats

    // weight slices
    __nv_bfloat16* WinH  = Whi + (size_t)W_WIN*4;   __nv_bfloat16* WinL  = Wlo + (size_t)W_WIN*4;
    __nv_bfloat16* WgH   = Whi + (size_t)W_WG*4;    __nv_bfloat16* WgL   = Wlo + (size_t)W_WG*4;
    __nv_bfloat16* WoutH = Whi + (size_t)W_WOUT*4;  __nv_bfloat16* WoutL = Wlo + (size_t)W_WOUT*4;
    __nv_bfloat16* G1gH  = Whi + (size_t)W_G1G*4;   __nv_bfloat16* G1gL  = Wlo + (size_t)W_G1G*4;
    __nv_bfloat16* G1sH  = Whi + (size_t)W_G1S*4;   __nv_bfloat16* G1sL  = Wlo + (size_t)W_G1S*4;
    __nv_bfloat16* G2gH  = Whi + (size_t)W_G2G*4;   __nv_bfloat16* G2gL  = Wlo + (size_t)W_G2G*4;
    __nv_bfloat16* G2sH  = Whi + (size_t)W_G2S*4;   __nv_bfloat16* G2sL  = Wlo + (size_t)W_G2S*4;
    __nv_bfloat16* WqH   = Whi + (size_t)W_Q*4;     __nv_bfloat16* WqL   = Wlo + (size_t)W_Q*4;
    __nv_bfloat16* WkvH  = Whi + (size_t)W_KV*4;    __nv_bfloat16* WkvL  = Wlo + (size_t)W_KV*4;
    __nv_bfloat16* Wo2H  = Whi + (size_t)W_O2*4;    __nv_bfloat16* Wo2L  = Wlo + (size_t)W_O2*4;

    // grids (CTN=128, R12 config)
    const dim3 gridWin((2*HID)/CTN, MROWS/CTM);   // 24 x 64
    const dim3 gridDim_(DIM/CTN, MROWS/CTM);      // 8 x 64
    const dim3 gridGrow((2*GH)/CTN, MROWS/CTM);   // 32 x 64
    const dim3 gridQ((QH*HD)/CTN, MROWS/CTM);     // 8 x 64
    const dim3 gridKV((2*HD)/CTN, MROWS/CTM);     // 2 x 64

    // attn bf16 buffers inside g_mid
    __nv_bfloat16* qhi  = (__nv_bfloat16*)mid;
    __nv_bfloat16* qlo  = (__nv_bfloat16*)(mid + 4194304);
    __nv_bfloat16* khi  = (__nv_bfloat16*)(mid + 8388608);
    __nv_bfloat16* klo  = (__nv_bfloat16*)(mid + 8912896);
    __nv_bfloat16* vthi = (__nv_bfloat16*)(mid + 9437184);
    __nv_bfloat16* vtlo = (__nv_bfloat16*)(mid + 9961472);
    __nv_bfloat16* acth = (__nv_bfloat16*)mid;
    __nv_bfloat16* actl = (__nv_bfloat16*)(mid + 8388608);

    // ---------------- one-shot: convert all weights + m8sp table ----------------
    convw_all_kernel<<<(W_TOT + EW - 1)/EW, EW>>>(
        hawk_Win, hawk_Wg, hawk_Wout, g1_Wgrow, g1_Wshr,
        g2_Wgrow, g2_Wshr, smqa_Wq, smqa_Wkv, smqa_Wout, Whi, Wlo);
    m8sp_kernel<<<(HID + EW - 1)/EW, EW>>>(hawk_fb, m8sp);

    // ---------------- stage 1: hawk ----------------
    rmsnorm_bf16_kernel<<<MROWS, 256>>>(x, gn_hawk, Ahi, Alo);
    // Win GEMM with gelu'd gate columns (EPI=6)
    LAUNCH_G(gridWin, 6,false,false, Ahi,Alo,WinH,WinL, nullptr,nullptr, big, 2*HID, DIM, nb,nb,nb,nb);
    conv_kernel<<<dim3(Tdim/TCH, Bdim), 384>>>(big, hawk_cw, hawk_cb, Ahi, Alo);
    // Wg GEMM with fused gates: reads hconv (Ahi/Alo) in epilogue, writes {alpha,xs}
    LAUNCH_G(gridWin, 5,false,false, Ahi,Alo,WgH,WgL, hawk_bg, m8sp, mid, 2*HID, HID,
             Ahi, Alo, nb, nb);
    scanA_kernel<<<(Bdim*NCH*HID + EW - 1)/EW, EW>>>(mid, chA, chS);
    scanB_kernel<<<(Bdim*HID + EW - 1)/EW, EW>>>(chA, chS, sIn);
    scanC_kernel<<<(Bdim*NCH*HID + EW - 1)/EW, EW>>>(mid, big, sIn, Ahi, Alo);
    LAUNCH_G(gridDim_, 0,false,true, Ahi,Alo,WoutH,WoutL, nullptr,x, out, DIM, HID, nb,nb,nb,nb);

    // ---------------- stage 2: gated MLP 1 ----------------
    rmsnorm_bf16_kernel<<<MROWS, 256>>>(out, gn_hgmlp, Ahi, Alo);
    LAUNCH_G(gridGrow, 1,false,false, Ahi,Alo,G1gH,G1gL, nullptr,nullptr, nullptr, 2*GH, DIM,
             acth, actl, nb, nb);
    LAUNCH_G(gridDim_, 0,false,true, acth,actl,G1sH,G1sL, nullptr,out, out, DIM, GH, nb,nb,nb,nb);

    // ---------------- stage 3: sliding-window MQA ----------------
    rmsnorm_bf16_kernel<<<MROWS, 256>>>(out, gn_smqa, Ahi, Alo);
    LAUNCH_G(gridQ, 2,false,false, Ahi,Alo,WqH,WqL, nullptr,nullptr, nullptr, QH*HD, DIM,
             qhi, qlo, nb, nb);
    LAUNCH_G(gridKV, 3,false,false, Ahi,Alo,WkvH,WkvL, nullptr,nullptr, nullptr, 2*HD, DIM,
             khi, klo, vthi, vtlo);
    attn_hmma_kernel<<<dim3(Tdim/AQ, QH, Bdim), 256, ATT_SMEM>>>(
        qhi, qlo, khi, klo, vthi, vtlo, Ahi, Alo);
    LAUNCH_G(gridDim_, 0,false,true, Ahi,Alo,Wo2H,Wo2L, nullptr,out, out, DIM, DIM, nb,nb,nb,nb);

    // ---------------- stage 4: gated MLP 2 ----------------
    rmsnorm_bf16_kernel<<<MROWS, 256>>>(out, gn_sgmlp, Ahi, Alo);
    LAUNCH_G(gridGrow, 1,false,false, Ahi,Alo,G2gH,G2gL, nullptr,nullptr, nullptr, 2*GH, DIM,
             acth, actl, nb, nb);
    LAUNCH_G(gridDim_, 0,false,true, acth,actl,G2sH,G2sL, nullptr,out, out, DIM, GH, nb,nb,nb,nb);
}